// round 10
// baseline (speedup 1.0000x reference)
#include <cuda_runtime.h>
#include <cuda_bf16.h>
#include <math.h>

#define Bsz 8
#define Dd 512
#define Hh 8
#define Ee 64
#define DI 1024
#define Ss 64
#define Rr 32
#define DFF 2048
#define LL 1152
#define Mrows (Bsz*LL)   /* 9216 */

// ---------------- scratch (static __device__, no allocation) ----------------
__device__ float g_q[Mrows*Dd];
__device__ float g_k[Mrows*Dd];
__device__ float g_v[Mrows*Dd];
__device__ float g_attnO[Mrows*Dd];
__device__ float g_attn_out[Mrows*Dd];
__device__ float g_xz[Mrows*2*DI];
__device__ float g_uact[Mrows*DI];
__device__ float g_xdbc[Mrows*160];
__device__ float g_delta[Mrows*DI];
__device__ float g_y[Mrows*DI];
__device__ float g_mamba[Mrows*Dd];
__device__ float g_h[Mrows*Dd];
__device__ float g_hn[Mrows*Dd];
__device__ float g_mid[Mrows*DFF];

enum { EPI_NONE = 0, EPI_SOFTPLUS = 1, EPI_GELU = 2, EPI_ADD = 3 };

__device__ __forceinline__ unsigned f2tf32(float f)
{
    unsigned u;
    asm("cvt.rna.tf32.f32 %0, %1;" : "=r"(u) : "f"(f));
    return u;
}

__device__ __forceinline__ void mma_tf32(float* c, const unsigned* a, const unsigned* b)
{
    asm volatile(
        "mma.sync.aligned.m16n8k8.row.col.f32.tf32.tf32.f32 "
        "{%0,%1,%2,%3},{%4,%5,%6,%7},{%8,%9},{%0,%1,%2,%3};"
        : "+f"(c[0]), "+f"(c[1]), "+f"(c[2]), "+f"(c[3])
        : "r"(a[0]), "r"(a[1]), "r"(a[2]), "r"(a[3]), "r"(b[0]), "r"(b[1]));
}

__device__ __forceinline__ void mma_bf16(float* c, const unsigned* a, const unsigned* b)
{
    asm volatile(
        "mma.sync.aligned.m16n8k16.row.col.f32.bf16.bf16.f32 "
        "{%0,%1,%2,%3},{%4,%5,%6,%7},{%8,%9},{%0,%1,%2,%3};"
        : "+f"(c[0]), "+f"(c[1]), "+f"(c[2]), "+f"(c[3])
        : "r"(a[0]), "r"(a[1]), "r"(a[2]), "r"(a[3]), "r"(b[0]), "r"(b[1]));
}

__device__ __forceinline__ void ldsm4(unsigned* r, unsigned saddr)
{
    asm volatile("ldmatrix.sync.aligned.m8n8.x4.shared.b16 {%0,%1,%2,%3}, [%4];"
        : "=r"(r[0]), "=r"(r[1]), "=r"(r[2]), "=r"(r[3]) : "r"(saddr));
}

__device__ __forceinline__ uint2 pack4(float4 f)
{
    __nv_bfloat162 p0 = __floats2bfloat162_rn(f.x, f.y);
    __nv_bfloat162 p1 = __floats2bfloat162_rn(f.z, f.w);
    uint2 u;
    u.x = *(unsigned*)&p0;
    u.y = *(unsigned*)&p1;
    return u;
}

__device__ __forceinline__ float epi_apply_scalar(int EPI, float v)
{
    if (EPI == EPI_SOFTPLUS) return (v > 20.f) ? v : log1pf(expf(v));
    if (EPI == EPI_GELU)     return 0.5f*v*(1.f + erff(v*0.7071067811865475f));
    return v;
}

// ====== bf16 tensor-core GEMM, 128x128 block tile: C = A(MxK) @ W(NxK)^T =====
// Requires N % 128 == 0, K % 4 == 0 (zero-padded per 64-k-tile).
// 8 warps (2M x 4N), warp tile 64x32, BK=64, double-buffered 64KB dynamic smem.
template<int EPI>
__global__ __launch_bounds__(256) void gemm_bf16w(
    const float* __restrict__ A, int lda,
    const float* __restrict__ W,
    const float* __restrict__ bias,
    const float* __restrict__ add,
    float* __restrict__ C, int M, int N, int K)
{
    extern __shared__ __align__(16) char smw[];
    char* AsP = smw;                 // 2 x [128 rows x 128B]
    char* BsP = smw + 2*16384;       // 2 x [128 rows x 128B]
    const unsigned asU = (unsigned)__cvta_generic_to_shared(AsP);
    const unsigned bsU = (unsigned)__cvta_generic_to_shared(BsP);

    const int tid = threadIdx.x;
    const int lane = tid & 31, w = tid >> 5;
    const int warpM = w >> 2, warpN = w & 3;       // 2 x 4
    const int m0 = blockIdx.y * 128, n0 = blockIdx.x * 128;

    const int arow0 = tid >> 4;          // 0..15
    const int akq   = (tid & 15) * 4;    // 0..60
    const float* Ap = A + (size_t)(m0 + arow0) * lda + akq;
    const float* Bp = W + (size_t)(n0 + arow0) * K + akq;
    const int so0 = arow0*128 + (((akq >> 3) ^ (arow0 & 7)) << 4) + (akq & 7)*2;

    // ldmatrix lane geometry
    const int lr = (lane & 7) + ((lane >> 3) & 1) * 8;   // 0..15
    const int ko = (lane >> 4);                           // 0/1
    int rA[4], mA[4];
#pragma unroll
    for (int mi = 0; mi < 4; mi++) {
        int r = warpM*64 + mi*16 + lr;
        rA[mi] = r * 128; mA[mi] = r & 7;
    }
    int rB[2], mB[2];
#pragma unroll
    for (int nh = 0; nh < 2; nh++) {
        int r = warpN*32 + nh*16 + lr;
        rB[nh] = r * 128; mB[nh] = r & 7;
    }

    float acc[4][4][4];
#pragma unroll
    for (int mi = 0; mi < 4; mi++)
#pragma unroll
        for (int nf = 0; nf < 4; nf++)
#pragma unroll
            for (int j = 0; j < 4; j++) acc[mi][nf][j] = 0.f;

    const int nk = (K + 63) >> 6;
    float4 ar[8], br[8];

    // prologue: tile 0
    {
        const bool av = akq < K;
#pragma unroll
        for (int i = 0; i < 8; i++) {
            ar[i] = av ? *(const float4*)(Ap + (size_t)i*16*lda) : make_float4(0.f,0.f,0.f,0.f);
            br[i] = av ? *(const float4*)(Bp + (size_t)i*16*K)   : make_float4(0.f,0.f,0.f,0.f);
        }
#pragma unroll
        for (int i = 0; i < 8; i++) {
            *(uint2*)(AsP + so0 + i*2048) = pack4(ar[i]);
            *(uint2*)(BsP + so0 + i*2048) = pack4(br[i]);
        }
    }
    __syncthreads();

    for (int kt = 0; kt < nk; kt++) {
        const int cur = kt & 1;
        const bool more = (kt + 1) < nk;
        if (more) {
            const int kof = (kt + 1) << 6;
            const bool av = (akq + kof) < K;
#pragma unroll
            for (int i = 0; i < 8; i++) {
                ar[i] = av ? *(const float4*)(Ap + kof + (size_t)i*16*lda) : make_float4(0.f,0.f,0.f,0.f);
                br[i] = av ? *(const float4*)(Bp + kof + (size_t)i*16*K)   : make_float4(0.f,0.f,0.f,0.f);
            }
        }

        const unsigned aB = asU + cur*16384;
        const unsigned bB = bsU + cur*16384;
#pragma unroll
        for (int ks = 0; ks < 4; ks++) {
            const int kx = 2*ks + ko;
            unsigned afr[4][4], bfr[2][4];
#pragma unroll
            for (int mi = 0; mi < 4; mi++)
                ldsm4(afr[mi], aB + rA[mi] + ((kx ^ mA[mi]) << 4));
#pragma unroll
            for (int nh = 0; nh < 2; nh++)
                ldsm4(bfr[nh], bB + rB[nh] + ((kx ^ mB[nh]) << 4));
#pragma unroll
            for (int mi = 0; mi < 4; mi++) {
                unsigned b0[2] = {bfr[0][0], bfr[0][2]};
                unsigned b1[2] = {bfr[0][1], bfr[0][3]};
                unsigned b2[2] = {bfr[1][0], bfr[1][2]};
                unsigned b3[2] = {bfr[1][1], bfr[1][3]};
                mma_bf16(acc[mi][0], afr[mi], b0);
                mma_bf16(acc[mi][1], afr[mi], b1);
                mma_bf16(acc[mi][2], afr[mi], b2);
                mma_bf16(acc[mi][3], afr[mi], b3);
            }
        }

        if (more) {
            const int nxt = cur ^ 1;
#pragma unroll
            for (int i = 0; i < 8; i++) {
                *(uint2*)(AsP + nxt*16384 + so0 + i*2048) = pack4(ar[i]);
                *(uint2*)(BsP + nxt*16384 + so0 + i*2048) = pack4(br[i]);
            }
            __syncthreads();
        }
    }

    // epilogue
#pragma unroll
    for (int mi = 0; mi < 4; mi++) {
#pragma unroll
        for (int nf = 0; nf < 4; nf++) {
            int row = m0 + warpM*64 + mi*16 + (lane >> 2);
            int col = n0 + warpN*32 + nf*8 + (lane & 3)*2;
            float v00 = acc[mi][nf][0], v01 = acc[mi][nf][1];
            float v10 = acc[mi][nf][2], v11 = acc[mi][nf][3];
            if (bias) {
                float b0 = bias[col], b1 = bias[col+1];
                v00 += b0; v01 += b1; v10 += b0; v11 += b1;
            }
            if (EPI == EPI_ADD) {
                const float* ap0 = add + (size_t)row * N + col;
                const float* ap1 = add + (size_t)(row+8) * N + col;
                v00 += ap0[0]; v01 += ap0[1]; v10 += ap1[0]; v11 += ap1[1];
            } else {
                v00 = epi_apply_scalar(EPI, v00); v01 = epi_apply_scalar(EPI, v01);
                v10 = epi_apply_scalar(EPI, v10); v11 = epi_apply_scalar(EPI, v11);
            }
            *(float2*)&C[(size_t)row * N + col]     = make_float2(v00, v01);
            *(float2*)&C[(size_t)(row+8) * N + col] = make_float2(v10, v11);
        }
    }
}

// ================= tf32 tensor-core GEMM (scan-sensitive projections) ========
template<int EPI>
__global__ __launch_bounds__(256) void gemm_tf32(
    const float* __restrict__ A, int lda,
    const float* __restrict__ W,
    const float* __restrict__ bias,
    const float* __restrict__ add,
    float* __restrict__ C, int M, int N, int K)
{
    __shared__ __align__(16) unsigned As[2][128*32];
    __shared__ __align__(16) unsigned Bs[2][64*32];

    const int t = threadIdx.x;
    const int m0 = blockIdx.y * 128, n0 = blockIdx.x * 64;
    const int lane = t & 31, w = t >> 5;
    const int warpM = w & 3, warpN = w >> 2;
    const int s = lane >> 2, off = lane & 3;

    const float* aptr[4]; int aso[4];
#pragma unroll
    for (int i = 0; i < 4; i++) {
        int e = t + i*256;
        int m = e >> 3, g = e & 7;
        aptr[i] = A + (size_t)(m0 + m) * lda + g*4;
        aso[i]  = m*32 + ((g ^ (m & 7)) << 2);
    }
    const float* bptr[2]; int bso[2]; bool bval[2];
#pragma unroll
    for (int i = 0; i < 2; i++) {
        int e = t + i*256;
        int n = e >> 3, g = e & 7;
        bval[i] = (n0 + n) < N;
        bptr[i] = W + (size_t)(n0 + n) * K + g*4;
        bso[i]  = n*32 + ((g ^ (n & 7)) << 2);
    }

    float acc[2][4][4];
#pragma unroll
    for (int mi = 0; mi < 2; mi++)
#pragma unroll
        for (int ni = 0; ni < 4; ni++)
#pragma unroll
            for (int j = 0; j < 4; j++) acc[mi][ni][j] = 0.f;

    const int nk = K >> 5;
    float4 ar[4], br[2];

#pragma unroll
    for (int i = 0; i < 4; i++) ar[i] = *(const float4*)(aptr[i]);
#pragma unroll
    for (int i = 0; i < 2; i++)
        br[i] = bval[i] ? *(const float4*)(bptr[i]) : make_float4(0.f,0.f,0.f,0.f);
#pragma unroll
    for (int i = 0; i < 4; i++)
        *(uint4*)&As[0][aso[i]] = make_uint4(f2tf32(ar[i].x), f2tf32(ar[i].y), f2tf32(ar[i].z), f2tf32(ar[i].w));
#pragma unroll
    for (int i = 0; i < 2; i++)
        *(uint4*)&Bs[0][bso[i]] = make_uint4(f2tf32(br[i].x), f2tf32(br[i].y), f2tf32(br[i].z), f2tf32(br[i].w));
    __syncthreads();

    for (int kt = 0; kt < nk; kt++) {
        const int cur = kt & 1, nxt = cur ^ 1;
        const bool more = (kt + 1) < nk;
        if (more) {
            const int ko = (kt + 1) * 32;
#pragma unroll
            for (int i = 0; i < 4; i++) ar[i] = *(const float4*)(aptr[i] + ko);
#pragma unroll
            for (int i = 0; i < 2; i++)
                br[i] = bval[i] ? *(const float4*)(bptr[i] + ko) : make_float4(0.f,0.f,0.f,0.f);
        }

#pragma unroll
        for (int ks = 0; ks < 4; ks++) {
            const int x0 = (((ks*2)     ^ s) << 2) + off;
            const int x1 = (((ks*2 + 1) ^ s) << 2) + off;
            unsigned a[2][4];
#pragma unroll
            for (int mi = 0; mi < 2; mi++) {
                int r = (warpM*32 + mi*16 + s) * 32;
                a[mi][0] = As[cur][r + x0];
                a[mi][1] = As[cur][r + 256 + x0];
                a[mi][2] = As[cur][r + x1];
                a[mi][3] = As[cur][r + 256 + x1];
            }
            unsigned b[4][2];
#pragma unroll
            for (int ni = 0; ni < 4; ni++) {
                int rb = (warpN*32 + ni*8 + s) * 32;
                b[ni][0] = Bs[cur][rb + x0];
                b[ni][1] = Bs[cur][rb + x1];
            }
#pragma unroll
            for (int mi = 0; mi < 2; mi++)
#pragma unroll
                for (int ni = 0; ni < 4; ni++)
                    mma_tf32(acc[mi][ni], a[mi], b[ni]);
        }

        if (more) {
#pragma unroll
            for (int i = 0; i < 4; i++)
                *(uint4*)&As[nxt][aso[i]] = make_uint4(f2tf32(ar[i].x), f2tf32(ar[i].y), f2tf32(ar[i].z), f2tf32(ar[i].w));
#pragma unroll
            for (int i = 0; i < 2; i++)
                *(uint4*)&Bs[nxt][bso[i]] = make_uint4(f2tf32(br[i].x), f2tf32(br[i].y), f2tf32(br[i].z), f2tf32(br[i].w));
            __syncthreads();
        }
    }

#pragma unroll
    for (int mi = 0; mi < 2; mi++) {
#pragma unroll
        for (int ni = 0; ni < 4; ni++) {
            int row = m0 + warpM*32 + mi*16 + s;
            int col = n0 + warpN*32 + ni*8 + off*2;
            if (col < N) {
                float v00 = acc[mi][ni][0], v01 = acc[mi][ni][1];
                float v10 = acc[mi][ni][2], v11 = acc[mi][ni][3];
                if (bias) {
                    float b0 = bias[col], b1 = bias[col+1];
                    v00 += b0; v01 += b1; v10 += b0; v11 += b1;
                }
                if (EPI == EPI_ADD) {
                    const float* ap0 = add + (size_t)row * N + col;
                    const float* ap1 = add + (size_t)(row+8) * N + col;
                    v00 += ap0[0]; v01 += ap0[1]; v10 += ap1[0]; v11 += ap1[1];
                } else {
                    v00 = epi_apply_scalar(EPI, v00); v01 = epi_apply_scalar(EPI, v01);
                    v10 = epi_apply_scalar(EPI, v10); v11 = epi_apply_scalar(EPI, v11);
                }
                *(float2*)&C[(size_t)row * N + col]     = make_float2(v00, v01);
                *(float2*)&C[(size_t)(row+8) * N + col] = make_float2(v10, v11);
            }
        }
    }
}

// ============== tf32 tensor-core flash attention =============================
__global__ __launch_bounds__(256) void attn_tc(
    const float* __restrict__ q, const float* __restrict__ k,
    const float* __restrict__ v, const unsigned char* __restrict__ mask,
    float* __restrict__ o)
{
    extern __shared__ unsigned sm_u[];
    unsigned* Ks = sm_u;
    unsigned* Vs = sm_u + 64*68;
    const int tid = threadIdx.x;
    const int lane = tid & 31, w = tid >> 5;
    unsigned* Ps = sm_u + 2*64*68 + w*16*68;
    const int s = lane >> 2, off = lane & 3;

    const int qt = blockIdx.x, h = blockIdx.y, b = blockIdx.z;
    const size_t bL = (size_t)b * LL;
    const int qr = qt * 128 + w * 16;

    unsigned qa[8][4];
    {
        const float* qp = q + (bL + qr) * Dd + h * Ee;
#pragma unroll
        for (int ks = 0; ks < 8; ks++) {
            qa[ks][0] = f2tf32(0.125f * qp[(size_t)(s    ) * Dd + ks*8 + off    ]);
            qa[ks][1] = f2tf32(0.125f * qp[(size_t)(s + 8) * Dd + ks*8 + off    ]);
            qa[ks][2] = f2tf32(0.125f * qp[(size_t)(s    ) * Dd + ks*8 + off + 4]);
            qa[ks][3] = f2tf32(0.125f * qp[(size_t)(s + 8) * Dd + ks*8 + off + 4]);
        }
    }

    float oa[8][4];
#pragma unroll
    for (int et = 0; et < 8; et++)
#pragma unroll
        for (int j = 0; j < 4; j++) oa[et][j] = 0.f;
    float m0v = -INFINITY, m1v = -INFINITY, l0v = 0.f, l1v = 0.f;

    for (int n0k = 0; n0k < LL; n0k += 64) {
        __syncthreads();
#pragma unroll
        for (int i = 0; i < 4; i++) {
            int u = tid + i*256;
            int row = u >> 4, qc = (u & 15) * 4;
            size_t gr = (bL + n0k + row) * Dd + h*Ee + qc;
            float4 kv = *(const float4*)&k[gr];
            *(uint4*)&Ks[row*68 + qc] = make_uint4(f2tf32(kv.x), f2tf32(kv.y), f2tf32(kv.z), f2tf32(kv.w));
            float4 vv = *(const float4*)&v[gr];
            *(uint4*)&Vs[row*68 + qc] = make_uint4(f2tf32(vv.x), f2tf32(vv.y), f2tf32(vv.z), f2tf32(vv.w));
        }
        __syncthreads();

        float sa[8][4];
#pragma unroll
        for (int nt = 0; nt < 8; nt++)
#pragma unroll
            for (int j = 0; j < 4; j++) sa[nt][j] = 0.f;
#pragma unroll
        for (int ks = 0; ks < 8; ks++) {
#pragma unroll
            for (int nt = 0; nt < 8; nt++) {
                unsigned bf[2];
                bf[0] = Ks[(nt*8 + s)*68 + ks*8 + off];
                bf[1] = Ks[(nt*8 + s)*68 + ks*8 + off + 4];
                mma_tf32(sa[nt], qa[ks], bf);
            }
        }

        float rmax0 = -INFINITY, rmax1 = -INFINITY;
#pragma unroll
        for (int nt = 0; nt < 8; nt++) {
            unsigned char mk0 = mask[bL + n0k + nt*8 + off*2];
            unsigned char mk1 = mask[bL + n0k + nt*8 + off*2 + 1];
            if (mk0) { sa[nt][0] = -INFINITY; sa[nt][2] = -INFINITY; }
            if (mk1) { sa[nt][1] = -INFINITY; sa[nt][3] = -INFINITY; }
            rmax0 = fmaxf(rmax0, fmaxf(sa[nt][0], sa[nt][1]));
            rmax1 = fmaxf(rmax1, fmaxf(sa[nt][2], sa[nt][3]));
        }
        rmax0 = fmaxf(rmax0, __shfl_xor_sync(0xffffffffu, rmax0, 1));
        rmax0 = fmaxf(rmax0, __shfl_xor_sync(0xffffffffu, rmax0, 2));
        rmax1 = fmaxf(rmax1, __shfl_xor_sync(0xffffffffu, rmax1, 1));
        rmax1 = fmaxf(rmax1, __shfl_xor_sync(0xffffffffu, rmax1, 2));
        float mn0 = fmaxf(m0v, rmax0), mn1 = fmaxf(m1v, rmax1);
        float c0 = __expf(m0v - mn0), c1 = __expf(m1v - mn1);
        float rs0 = 0.f, rs1 = 0.f;
#pragma unroll
        for (int nt = 0; nt < 8; nt++) {
            float p0 = __expf(sa[nt][0] - mn0);
            float p1 = __expf(sa[nt][1] - mn0);
            float p2 = __expf(sa[nt][2] - mn1);
            float p3 = __expf(sa[nt][3] - mn1);
            rs0 += p0 + p1; rs1 += p2 + p3;
            Ps[ s     *68 + nt*8 + off*2    ] = f2tf32(p0);
            Ps[ s     *68 + nt*8 + off*2 + 1] = f2tf32(p1);
            Ps[(s + 8)*68 + nt*8 + off*2    ] = f2tf32(p2);
            Ps[(s + 8)*68 + nt*8 + off*2 + 1] = f2tf32(p3);
        }
        rs0 += __shfl_xor_sync(0xffffffffu, rs0, 1);
        rs0 += __shfl_xor_sync(0xffffffffu, rs0, 2);
        rs1 += __shfl_xor_sync(0xffffffffu, rs1, 1);
        rs1 += __shfl_xor_sync(0xffffffffu, rs1, 2);
        l0v = l0v * c0 + rs0; l1v = l1v * c1 + rs1;
        m0v = mn0; m1v = mn1;
#pragma unroll
        for (int et = 0; et < 8; et++) {
            oa[et][0] *= c0; oa[et][1] *= c0;
            oa[et][2] *= c1; oa[et][3] *= c1;
        }
        __syncwarp();

#pragma unroll
        for (int ks = 0; ks < 8; ks++) {
            unsigned pa[4];
            pa[0] = Ps[ s     *68 + ks*8 + off    ];
            pa[1] = Ps[(s + 8)*68 + ks*8 + off    ];
            pa[2] = Ps[ s     *68 + ks*8 + off + 4];
            pa[3] = Ps[(s + 8)*68 + ks*8 + off + 4];
#pragma unroll
            for (int et = 0; et < 8; et++) {
                unsigned bf[2];
                bf[0] = Vs[(ks*8 + off    )*68 + et*8 + s];
                bf[1] = Vs[(ks*8 + off + 4)*68 + et*8 + s];
                mma_tf32(oa[et], pa, bf);
            }
        }
    }

    float inv0 = 1.f / l0v, inv1 = 1.f / l1v;
#pragma unroll
    for (int et = 0; et < 8; et++) {
        size_t r0 = (bL + qr + s    ) * Dd + h*Ee + et*8 + off*2;
        size_t r1 = (bL + qr + s + 8) * Dd + h*Ee + et*8 + off*2;
        *(float2*)&o[r0] = make_float2(oa[et][0]*inv0, oa[et][1]*inv0);
        *(float2*)&o[r1] = make_float2(oa[et][2]*inv1, oa[et][3]*inv1);
    }
}

// ---------------- causal depthwise conv (KC=4) + SiLU ------------------------
__global__ void conv_silu_k(const float* __restrict__ xz,
                            const float* __restrict__ cw,
                            const float* __restrict__ cb,
                            float* __restrict__ uact)
{
    int idx = blockIdx.x * 256 + threadIdx.x;
    int r = idx >> 10;
    int j = idx & 1023;
    int t = r % LL;
    float acc = cb[j];
#pragma unroll
    for (int kk = 0; kk < 4; kk++) {
        int tt = t + kk - 3;
        if (tt >= 0)
            acc = fmaf(xz[(size_t)(r + kk - 3) * (2*DI) + j], cw[j*4 + kk], acc);
    }
    uact[idx] = acc / (1.f + expf(-acc));
}

// ---------------- selective scan: 1 warp per (b,d), 2 states/lane ------------
__global__ __launch_bounds__(512) void scan_k(
    const float* __restrict__ delta, const float* __restrict__ uact,
    const float* __restrict__ xdbc, const float* __restrict__ A_log,
    float* __restrict__ y)
{
    __shared__ float sB[16][64];
    __shared__ float sC[16][64];
    __shared__ float sdt[16][16];
    __shared__ float su[16][16];

    int b = blockIdx.y;
    int d0 = blockIdx.x * 16;
    int tid = threadIdx.x;
    int w = tid >> 5, l = tid & 31;
    int d = d0 + w;
    float a0 = -expf(A_log[d*Ss + l]);
    float a1 = -expf(A_log[d*Ss + l + 32]);
    float h0 = 0.f, h1 = 0.f;
    size_t base = (size_t)b * LL;

    for (int t0 = 0; t0 < LL; t0 += 16) {
        __syncthreads();
        for (int i = tid; i < 2048; i += 512) {
            int tt = i >> 7, c = i & 127;
            float val = xdbc[(base + t0 + tt) * 160 + 32 + c];
            if (c < 64) sB[tt][c] = val; else sC[tt][c - 64] = val;
        }
        if (tid < 256) {
            sdt[tid >> 4][tid & 15] = delta[(base + t0 + (tid >> 4)) * DI + d0 + (tid & 15)];
        } else {
            int jj = tid - 256;
            su[jj >> 4][jj & 15] = uact[(base + t0 + (jj >> 4)) * DI + d0 + (jj & 15)];
        }
        __syncthreads();
#pragma unroll 4
        for (int tt = 0; tt < 16; tt++) {
            float dt  = sdt[tt][w];
            float dtu = dt * su[tt][w];
            float dA0 = __expf(dt * a0);
            float dA1 = __expf(dt * a1);
            h0 = fmaf(h0, dA0, dtu * sB[tt][l]);
            h1 = fmaf(h1, dA1, dtu * sB[tt][l + 32]);
            float yv = h0 * sC[tt][l] + h1 * sC[tt][l + 32];
#pragma unroll
            for (int offx = 16; offx > 0; offx >>= 1)
                yv += __shfl_xor_sync(0xffffffffu, yv, offx);
            if (l == 0) y[(base + t0 + tt) * DI + d] = yv;
        }
    }
}

// ---------------- gate: y = (y + uact*D) * silu(z) ---------------------------
__global__ void gate_k(float* __restrict__ y, const float* __restrict__ uact,
                       const float* __restrict__ xz, const float* __restrict__ Dssm)
{
    int idx = blockIdx.x * 256 + threadIdx.x;
    int r = idx >> 10, j = idx & 1023;
    float z  = xz[(size_t)r * (2*DI) + DI + j];
    float yv = y[idx] + uact[idx] * Dssm[j];
    y[idx] = yv * (z / (1.f + expf(-z)));
}

// ---------------- fused residual-sum + LN1 + LN2 -----------------------------
__device__ __forceinline__ float blockSum128(float v, float* sm)
{
#pragma unroll
    for (int offx = 16; offx > 0; offx >>= 1)
        v += __shfl_xor_sync(0xffffffffu, v, offx);
    if ((threadIdx.x & 31) == 0) sm[threadIdx.x >> 5] = v;
    __syncthreads();
    float r = sm[0] + sm[1] + sm[2] + sm[3];
    __syncthreads();
    return r;
}

__global__ __launch_bounds__(128) void combine_ln_k(
    const float* __restrict__ xf, const float* __restrict__ attn,
    const float* __restrict__ mamba,
    const float* __restrict__ g1, const float* __restrict__ b1,
    const float* __restrict__ g2, const float* __restrict__ b2,
    float* __restrict__ h, float* __restrict__ hn)
{
    __shared__ float sm[4];
    int r = blockIdx.x, tid = threadIdx.x;
    size_t base = (size_t)r * Dd;
    float vv[4];
#pragma unroll
    for (int i = 0; i < 4; i++) {
        int c = tid + i*128;
        vv[i] = xf[base+c] + attn[base+c] + mamba[base+c];
    }
    float s = vv[0] + vv[1] + vv[2] + vv[3];
    float mean = blockSum128(s, sm) * (1.f/512.f);
    float sq = 0.f;
#pragma unroll
    for (int i = 0; i < 4; i++) { float dd = vv[i] - mean; sq = fmaf(dd, dd, sq); }
    float var = blockSum128(sq, sm) * (1.f/512.f);
    float inv = rsqrtf(var + 1e-5f);
    float hv[4];
#pragma unroll
    for (int i = 0; i < 4; i++) {
        int c = tid + i*128;
        hv[i] = (vv[i] - mean) * inv * g1[c] + b1[c];
        h[base+c] = hv[i];
    }
    float s2 = hv[0] + hv[1] + hv[2] + hv[3];
    float mean2 = blockSum128(s2, sm) * (1.f/512.f);
    float sq2 = 0.f;
#pragma unroll
    for (int i = 0; i < 4; i++) { float dd = hv[i] - mean2; sq2 = fmaf(dd, dd, sq2); }
    float var2 = blockSum128(sq2, sm) * (1.f/512.f);
    float inv2 = rsqrtf(var2 + 1e-6f);
#pragma unroll
    for (int i = 0; i < 4; i++) {
        int c = tid + i*128;
        hn[base+c] = (hv[i] - mean2) * inv2 * g2[c] + b2[c];
    }
}

// ---------------- launch -----------------------------------------------------
extern "C" void kernel_launch(void* const* d_in, const int* in_sizes, int n_in,
                              void* d_out, int out_size)
{
    const float* x            = (const float*)d_in[0];
    const unsigned char* mask = (const unsigned char*)d_in[1];
    const float* Wq = (const float*)d_in[2];   const float* bq = (const float*)d_in[3];
    const float* Wk = (const float*)d_in[4];   const float* bk = (const float*)d_in[5];
    const float* Wv = (const float*)d_in[6];   const float* bv = (const float*)d_in[7];
    const float* Wo = (const float*)d_in[8];   const float* bo = (const float*)d_in[9];
    const float* in_proj_w = (const float*)d_in[10];
    const float* conv_w    = (const float*)d_in[11];
    const float* conv_b    = (const float*)d_in[12];
    const float* x_proj_w  = (const float*)d_in[13];
    const float* dt_proj_w = (const float*)d_in[14];
    const float* dt_proj_b = (const float*)d_in[15];
    const float* A_log     = (const float*)d_in[16];
    const float* D_ssm     = (const float*)d_in[17];
    const float* out_proj_w= (const float*)d_in[18];
    const float* ln1_g = (const float*)d_in[19]; const float* ln1_b = (const float*)d_in[20];
    const float* ffn_w1= (const float*)d_in[21]; const float* ffn_b1= (const float*)d_in[22];
    const float* ffn_w2= (const float*)d_in[23]; const float* ffn_b2= (const float*)d_in[24];
    const float* ln2_g = (const float*)d_in[25]; const float* ln2_b = (const float*)d_in[26];
    float* out = (float*)d_out;

    float *q,*k,*v,*attnO,*attn_out,*xz,*uact,*xdbc,*delta,*y,*mamba,*h,*hn,*mid;
    cudaGetSymbolAddress((void**)&q,        g_q);
    cudaGetSymbolAddress((void**)&k,        g_k);
    cudaGetSymbolAddress((void**)&v,        g_v);
    cudaGetSymbolAddress((void**)&attnO,    g_attnO);
    cudaGetSymbolAddress((void**)&attn_out, g_attn_out);
    cudaGetSymbolAddress((void**)&xz,       g_xz);
    cudaGetSymbolAddress((void**)&uact,     g_uact);
    cudaGetSymbolAddress((void**)&xdbc,     g_xdbc);
    cudaGetSymbolAddress((void**)&delta,    g_delta);
    cudaGetSymbolAddress((void**)&y,        g_y);
    cudaGetSymbolAddress((void**)&mamba,    g_mamba);
    cudaGetSymbolAddress((void**)&h,        g_h);
    cudaGetSymbolAddress((void**)&hn,       g_hn);
    cudaGetSymbolAddress((void**)&mid,      g_mid);

    static cudaStream_t s_attn = nullptr;
    static cudaEvent_t  e_fork = nullptr, e_join = nullptr;
    if (s_attn == nullptr) {
        cudaStreamCreateWithFlags(&s_attn, cudaStreamNonBlocking);
        cudaEventCreateWithFlags(&e_fork, cudaEventDisableTiming);
        cudaEventCreateWithFlags(&e_join, cudaEventDisableTiming);
    }

    const int MY = Mrows / 128;   // 72
    const int attn_smem = (2*64*68 + 8*16*68) * 4;   // 69632 bytes
    const int gemm_smem = 4*16384;                   // 65536 bytes
    cudaFuncSetAttribute(attn_tc, cudaFuncAttributeMaxDynamicSharedMemorySize, attn_smem);
    cudaFuncSetAttribute(gemm_bf16w<EPI_NONE>, cudaFuncAttributeMaxDynamicSharedMemorySize, gemm_smem);
    cudaFuncSetAttribute(gemm_bf16w<EPI_GELU>, cudaFuncAttributeMaxDynamicSharedMemorySize, gemm_smem);
    cudaFuncSetAttribute(gemm_bf16w<EPI_ADD>,  cudaFuncAttributeMaxDynamicSharedMemorySize, gemm_smem);

    // ---- fork: attention branch on s_attn, mamba branch on stream 0 ----
    cudaEventRecord(e_fork, 0);
    cudaStreamWaitEvent(s_attn, e_fork, 0);

    // attention branch (s_attn)
    gemm_bf16w<EPI_NONE><<<dim3(Dd/128,   MY), 256, gemm_smem, s_attn>>>(x, Dd, Wq, bq, nullptr, q, Mrows, Dd, Dd);
    gemm_bf16w<EPI_NONE><<<dim3(Dd/128,   MY), 256, gemm_smem, s_attn>>>(x, Dd, Wk, bk, nullptr, k, Mrows, Dd, Dd);
    gemm_bf16w<EPI_NONE><<<dim3(Dd/128,   MY), 256, gemm_smem, s_attn>>>(x, Dd, Wv, bv, nullptr, v, Mrows, Dd, Dd);
    attn_tc<<<dim3(LL/128, Hh, Bsz), 256, attn_smem, s_attn>>>(q, k, v, mask, attnO);
    gemm_bf16w<EPI_NONE><<<dim3(Dd/128,   MY), 256, gemm_smem, s_attn>>>(attnO, Dd, Wo, bo, nullptr, attn_out, Mrows, Dd, Dd);
    cudaEventRecord(e_join, s_attn);

    // mamba branch (stream 0)
    gemm_bf16w<EPI_NONE><<<dim3(2*DI/128, MY), 256, gemm_smem>>>(x, Dd, in_proj_w, nullptr, nullptr, xz, Mrows, 2*DI, Dd);
    conv_silu_k<<<Mrows*DI/256, 256>>>(xz, conv_w, conv_b, uact);
    gemm_tf32<EPI_NONE><<<dim3(3,       MY), 256>>>(uact, DI, x_proj_w, nullptr, nullptr, xdbc, Mrows, 160, DI);
    gemm_tf32<EPI_SOFTPLUS><<<dim3(DI/64, MY), 256>>>(xdbc, 160, dt_proj_w, dt_proj_b, nullptr, delta, Mrows, DI, Rr);
    scan_k<<<dim3(DI/16, Bsz), 512>>>(delta, uact, xdbc, A_log, y);
    gate_k<<<Mrows*DI/256, 256>>>(y, uact, xz, D_ssm);
    gemm_bf16w<EPI_NONE><<<dim3(Dd/128,   MY), 256, gemm_smem>>>(y, DI, out_proj_w, nullptr, nullptr, mamba, Mrows, Dd, DI);

    // ---- join ----
    cudaStreamWaitEvent(0, e_join, 0);

    // combine + double layernorm
    combine_ln_k<<<Mrows, 128>>>(x, attn_out, mamba, ln1_g, ln1_b, ln2_g, ln2_b, h, hn);

    // FFN
    gemm_bf16w<EPI_GELU><<<dim3(DFF/128, MY), 256, gemm_smem>>>(hn, Dd, ffn_w1, ffn_b1, nullptr, mid, Mrows, DFF, Dd);
    gemm_bf16w<EPI_ADD><<<dim3(Dd/128,   MY), 256, gemm_smem>>>(mid, DFF, ffn_w2, ffn_b2, h, out, Mrows, Dd, DFF);
}

// round 11
// speedup vs baseline: 1.0469x; 1.0469x over previous
#include <cuda_runtime.h>
#include <cuda_bf16.h>
#include <math.h>

#define Bsz 8
#define Dd 512
#define Hh 8
#define Ee 64
#define DI 1024
#define Ss 64
#define Rr 32
#define DFF 2048
#define LL 1152
#define Mrows (Bsz*LL)   /* 9216 */

// ---------------- scratch (static __device__, no allocation) ----------------
__device__ float g_q[Mrows*Dd];
__device__ float g_k[Mrows*Dd];
__device__ float g_v[Mrows*Dd];
__device__ float g_attnO[Mrows*Dd];
__device__ float g_attn_out[Mrows*Dd];
__device__ float g_xz[Mrows*2*DI];
__device__ float g_uact[Mrows*DI];
__device__ float g_xdbc[Mrows*160];
__device__ float g_delta[Mrows*DI];
__device__ float g_y[Mrows*DI];
__device__ float g_hsum[Mrows*Dd];
__device__ float g_h[Mrows*Dd];
__device__ float g_hn[Mrows*Dd];
__device__ float g_mid[Mrows*DFF];

enum { EPI_NONE = 0, EPI_SOFTPLUS = 1, EPI_GELU = 2, EPI_ADD = 3, EPI_ADD2 = 4 };

__device__ __forceinline__ unsigned f2tf32(float f)
{
    unsigned u;
    asm("cvt.rna.tf32.f32 %0, %1;" : "=r"(u) : "f"(f));
    return u;
}

__device__ __forceinline__ void mma_tf32(float* c, const unsigned* a, const unsigned* b)
{
    asm volatile(
        "mma.sync.aligned.m16n8k8.row.col.f32.tf32.tf32.f32 "
        "{%0,%1,%2,%3},{%4,%5,%6,%7},{%8,%9},{%0,%1,%2,%3};"
        : "+f"(c[0]), "+f"(c[1]), "+f"(c[2]), "+f"(c[3])
        : "r"(a[0]), "r"(a[1]), "r"(a[2]), "r"(a[3]), "r"(b[0]), "r"(b[1]));
}

__device__ __forceinline__ void mma_bf16(float* c, const unsigned* a, const unsigned* b)
{
    asm volatile(
        "mma.sync.aligned.m16n8k16.row.col.f32.bf16.bf16.f32 "
        "{%0,%1,%2,%3},{%4,%5,%6,%7},{%8,%9},{%0,%1,%2,%3};"
        : "+f"(c[0]), "+f"(c[1]), "+f"(c[2]), "+f"(c[3])
        : "r"(a[0]), "r"(a[1]), "r"(a[2]), "r"(a[3]), "r"(b[0]), "r"(b[1]));
}

__device__ __forceinline__ void ldsm4(unsigned* r, unsigned saddr)
{
    asm volatile("ldmatrix.sync.aligned.m8n8.x4.shared.b16 {%0,%1,%2,%3}, [%4];"
        : "=r"(r[0]), "=r"(r[1]), "=r"(r[2]), "=r"(r[3]) : "r"(saddr));
}

__device__ __forceinline__ uint2 pack4(float4 f)
{
    __nv_bfloat162 p0 = __floats2bfloat162_rn(f.x, f.y);
    __nv_bfloat162 p1 = __floats2bfloat162_rn(f.z, f.w);
    uint2 u;
    u.x = *(unsigned*)&p0;
    u.y = *(unsigned*)&p1;
    return u;
}

__device__ __forceinline__ float epi_apply_scalar(int EPI, float v)
{
    if (EPI == EPI_SOFTPLUS) return (v > 20.f) ? v : log1pf(expf(v));
    if (EPI == EPI_GELU)     return 0.5f*v*(1.f + erff(v*0.7071067811865475f));
    return v;
}

// ====== bf16 tensor-core GEMM, 128x64 block tile: C = A(MxK) @ W(NxK)^T ======
template<int EPI>
__global__ __launch_bounds__(256) void gemm_bf16(
    const float* __restrict__ A, int lda,
    const float* __restrict__ W,
    const float* __restrict__ bias,
    const float* __restrict__ add,
    const float* __restrict__ add2,
    float* __restrict__ C, int M, int N, int K)
{
    __shared__ __align__(16) char sm[2*16384 + 2*8192];
    char* AsP = sm;
    char* BsP = sm + 2*16384;
    const unsigned asU = (unsigned)__cvta_generic_to_shared(AsP);
    const unsigned bsU = (unsigned)__cvta_generic_to_shared(BsP);

    const int tid = threadIdx.x;
    const int lane = tid & 31, w = tid >> 5;
    const int warpM = w & 3, warpN = w >> 2;
    const int m0 = blockIdx.y * 128, n0 = blockIdx.x * 64;

    const int arow0 = tid >> 4;
    const int akq   = (tid & 15) * 4;
    const float* Ap = A + (size_t)(m0 + arow0) * lda + akq;
    const int aso0 = arow0*128 + (((akq >> 3) ^ (arow0 & 7)) << 4) + (akq & 7)*2;

    const float* Bp = W + (size_t)(n0 + arow0) * K + akq;
    const int bso0 = aso0;
    bool bnv[4];
#pragma unroll
    for (int i = 0; i < 4; i++) bnv[i] = (n0 + arow0 + 16*i) < N;

    const int lr = (lane & 7) + ((lane >> 3) & 1) * 8;
    const int ko = (lane >> 4);
    int rA[2], mA[2];
#pragma unroll
    for (int mi = 0; mi < 2; mi++) {
        int r = warpM*32 + mi*16 + lr;
        rA[mi] = r * 128; mA[mi] = r & 7;
    }
    int rB[2], mB[2];
#pragma unroll
    for (int nh = 0; nh < 2; nh++) {
        int r = warpN*32 + nh*16 + lr;
        rB[nh] = r * 128; mB[nh] = r & 7;
    }

    float acc[2][4][4];
#pragma unroll
    for (int mi = 0; mi < 2; mi++)
#pragma unroll
        for (int nf = 0; nf < 4; nf++)
#pragma unroll
            for (int j = 0; j < 4; j++) acc[mi][nf][j] = 0.f;

    const int nk = (K + 63) >> 6;
    float4 ar[8], br[4];

    {
        const bool av = akq < K;
#pragma unroll
        for (int i = 0; i < 8; i++)
            ar[i] = av ? *(const float4*)(Ap + (size_t)i*16*lda) : make_float4(0.f,0.f,0.f,0.f);
#pragma unroll
        for (int i = 0; i < 4; i++)
            br[i] = (bnv[i] && av) ? *(const float4*)(Bp + (size_t)i*16*K) : make_float4(0.f,0.f,0.f,0.f);
#pragma unroll
        for (int i = 0; i < 8; i++) *(uint2*)(AsP + aso0 + i*2048) = pack4(ar[i]);
#pragma unroll
        for (int i = 0; i < 4; i++) *(uint2*)(BsP + bso0 + i*2048) = pack4(br[i]);
    }
    __syncthreads();

    for (int kt = 0; kt < nk; kt++) {
        const int cur = kt & 1;
        const bool more = (kt + 1) < nk;
        if (more) {
            const int kof = (kt + 1) << 6;
            const bool av = (akq + kof) < K;
#pragma unroll
            for (int i = 0; i < 8; i++)
                ar[i] = av ? *(const float4*)(Ap + kof + (size_t)i*16*lda) : make_float4(0.f,0.f,0.f,0.f);
#pragma unroll
            for (int i = 0; i < 4; i++)
                br[i] = (bnv[i] && av) ? *(const float4*)(Bp + kof + (size_t)i*16*K) : make_float4(0.f,0.f,0.f,0.f);
        }

        const unsigned aB = asU + cur*16384;
        const unsigned bB = bsU + cur*8192;
#pragma unroll
        for (int ks = 0; ks < 4; ks++) {
            const int kx = 2*ks + ko;
            unsigned afr[2][4], bfr[2][4];
#pragma unroll
            for (int mi = 0; mi < 2; mi++)
                ldsm4(afr[mi], aB + rA[mi] + ((kx ^ mA[mi]) << 4));
#pragma unroll
            for (int nh = 0; nh < 2; nh++)
                ldsm4(bfr[nh], bB + rB[nh] + ((kx ^ mB[nh]) << 4));
#pragma unroll
            for (int mi = 0; mi < 2; mi++) {
                unsigned b0[2] = {bfr[0][0], bfr[0][2]};
                unsigned b1[2] = {bfr[0][1], bfr[0][3]};
                unsigned b2[2] = {bfr[1][0], bfr[1][2]};
                unsigned b3[2] = {bfr[1][1], bfr[1][3]};
                mma_bf16(acc[mi][0], afr[mi], b0);
                mma_bf16(acc[mi][1], afr[mi], b1);
                mma_bf16(acc[mi][2], afr[mi], b2);
                mma_bf16(acc[mi][3], afr[mi], b3);
            }
        }

        if (more) {
            const int nxt = cur ^ 1;
#pragma unroll
            for (int i = 0; i < 8; i++) *(uint2*)(AsP + nxt*16384 + aso0 + i*2048) = pack4(ar[i]);
#pragma unroll
            for (int i = 0; i < 4; i++) *(uint2*)(BsP + nxt*8192  + bso0 + i*2048) = pack4(br[i]);
            __syncthreads();
        }
    }

#pragma unroll
    for (int mi = 0; mi < 2; mi++) {
#pragma unroll
        for (int nf = 0; nf < 4; nf++) {
            int row = m0 + warpM*32 + mi*16 + (lane >> 2);
            int col = n0 + warpN*32 + nf*8 + (lane & 3)*2;
            if (col < N) {
                float v00 = acc[mi][nf][0], v01 = acc[mi][nf][1];
                float v10 = acc[mi][nf][2], v11 = acc[mi][nf][3];
                if (bias) {
                    float b0 = bias[col], b1 = bias[col+1];
                    v00 += b0; v01 += b1; v10 += b0; v11 += b1;
                }
                if (EPI == EPI_ADD || EPI == EPI_ADD2) {
                    const float* ap0 = add + (size_t)row * N + col;
                    const float* ap1 = add + (size_t)(row+8) * N + col;
                    v00 += ap0[0]; v01 += ap0[1]; v10 += ap1[0]; v11 += ap1[1];
                    if (EPI == EPI_ADD2) {
                        const float* bp0 = add2 + (size_t)row * N + col;
                        const float* bp1 = add2 + (size_t)(row+8) * N + col;
                        v00 += bp0[0]; v01 += bp0[1]; v10 += bp1[0]; v11 += bp1[1];
                    }
                } else {
                    v00 = epi_apply_scalar(EPI, v00); v01 = epi_apply_scalar(EPI, v01);
                    v10 = epi_apply_scalar(EPI, v10); v11 = epi_apply_scalar(EPI, v11);
                }
                *(float2*)&C[(size_t)row * N + col]     = make_float2(v00, v01);
                *(float2*)&C[(size_t)(row+8) * N + col] = make_float2(v10, v11);
            }
        }
    }
}

// ================= tf32 tensor-core GEMM (scan-sensitive projections) ========
template<int EPI>
__global__ __launch_bounds__(256) void gemm_tf32(
    const float* __restrict__ A, int lda,
    const float* __restrict__ W,
    const float* __restrict__ bias,
    const float* __restrict__ add,
    float* __restrict__ C, int M, int N, int K)
{
    __shared__ __align__(16) unsigned As[2][128*32];
    __shared__ __align__(16) unsigned Bs[2][64*32];

    const int t = threadIdx.x;
    const int m0 = blockIdx.y * 128, n0 = blockIdx.x * 64;
    const int lane = t & 31, w = t >> 5;
    const int warpM = w & 3, warpN = w >> 2;
    const int s = lane >> 2, off = lane & 3;

    const float* aptr[4]; int aso[4];
#pragma unroll
    for (int i = 0; i < 4; i++) {
        int e = t + i*256;
        int m = e >> 3, g = e & 7;
        aptr[i] = A + (size_t)(m0 + m) * lda + g*4;
        aso[i]  = m*32 + ((g ^ (m & 7)) << 2);
    }
    const float* bptr[2]; int bso[2]; bool bval[2];
#pragma unroll
    for (int i = 0; i < 2; i++) {
        int e = t + i*256;
        int n = e >> 3, g = e & 7;
        bval[i] = (n0 + n) < N;
        bptr[i] = W + (size_t)(n0 + n) * K + g*4;
        bso[i]  = n*32 + ((g ^ (n & 7)) << 2);
    }

    float acc[2][4][4];
#pragma unroll
    for (int mi = 0; mi < 2; mi++)
#pragma unroll
        for (int ni = 0; ni < 4; ni++)
#pragma unroll
            for (int j = 0; j < 4; j++) acc[mi][ni][j] = 0.f;

    const int nk = K >> 5;
    float4 ar[4], br[2];

#pragma unroll
    for (int i = 0; i < 4; i++) ar[i] = *(const float4*)(aptr[i]);
#pragma unroll
    for (int i = 0; i < 2; i++)
        br[i] = bval[i] ? *(const float4*)(bptr[i]) : make_float4(0.f,0.f,0.f,0.f);
#pragma unroll
    for (int i = 0; i < 4; i++)
        *(uint4*)&As[0][aso[i]] = make_uint4(f2tf32(ar[i].x), f2tf32(ar[i].y), f2tf32(ar[i].z), f2tf32(ar[i].w));
#pragma unroll
    for (int i = 0; i < 2; i++)
        *(uint4*)&Bs[0][bso[i]] = make_uint4(f2tf32(br[i].x), f2tf32(br[i].y), f2tf32(br[i].z), f2tf32(br[i].w));
    __syncthreads();

    for (int kt = 0; kt < nk; kt++) {
        const int cur = kt & 1, nxt = cur ^ 1;
        const bool more = (kt + 1) < nk;
        if (more) {
            const int ko = (kt + 1) * 32;
#pragma unroll
            for (int i = 0; i < 4; i++) ar[i] = *(const float4*)(aptr[i] + ko);
#pragma unroll
            for (int i = 0; i < 2; i++)
                br[i] = bval[i] ? *(const float4*)(bptr[i] + ko) : make_float4(0.f,0.f,0.f,0.f);
        }

#pragma unroll
        for (int ks = 0; ks < 4; ks++) {
            const int x0 = (((ks*2)     ^ s) << 2) + off;
            const int x1 = (((ks*2 + 1) ^ s) << 2) + off;
            unsigned a[2][4];
#pragma unroll
            for (int mi = 0; mi < 2; mi++) {
                int r = (warpM*32 + mi*16 + s) * 32;
                a[mi][0] = As[cur][r + x0];
                a[mi][1] = As[cur][r + 256 + x0];
                a[mi][2] = As[cur][r + x1];
                a[mi][3] = As[cur][r + 256 + x1];
            }
            unsigned b[4][2];
#pragma unroll
            for (int ni = 0; ni < 4; ni++) {
                int rb = (warpN*32 + ni*8 + s) * 32;
                b[ni][0] = Bs[cur][rb + x0];
                b[ni][1] = Bs[cur][rb + x1];
            }
#pragma unroll
            for (int mi = 0; mi < 2; mi++)
#pragma unroll
                for (int ni = 0; ni < 4; ni++)
                    mma_tf32(acc[mi][ni], a[mi], b[ni]);
        }

        if (more) {
#pragma unroll
            for (int i = 0; i < 4; i++)
                *(uint4*)&As[nxt][aso[i]] = make_uint4(f2tf32(ar[i].x), f2tf32(ar[i].y), f2tf32(ar[i].z), f2tf32(ar[i].w));
#pragma unroll
            for (int i = 0; i < 2; i++)
                *(uint4*)&Bs[nxt][bso[i]] = make_uint4(f2tf32(br[i].x), f2tf32(br[i].y), f2tf32(br[i].z), f2tf32(br[i].w));
            __syncthreads();
        }
    }

#pragma unroll
    for (int mi = 0; mi < 2; mi++) {
#pragma unroll
        for (int ni = 0; ni < 4; ni++) {
            int row = m0 + warpM*32 + mi*16 + s;
            int col = n0 + warpN*32 + ni*8 + off*2;
            if (col < N) {
                float v00 = acc[mi][ni][0], v01 = acc[mi][ni][1];
                float v10 = acc[mi][ni][2], v11 = acc[mi][ni][3];
                if (bias) {
                    float b0 = bias[col], b1 = bias[col+1];
                    v00 += b0; v01 += b1; v10 += b0; v11 += b1;
                }
                v00 = epi_apply_scalar(EPI, v00); v01 = epi_apply_scalar(EPI, v01);
                v10 = epi_apply_scalar(EPI, v10); v11 = epi_apply_scalar(EPI, v11);
                *(float2*)&C[(size_t)row * N + col]     = make_float2(v00, v01);
                *(float2*)&C[(size_t)(row+8) * N + col] = make_float2(v10, v11);
            }
        }
    }
}

// ============== tf32 tensor-core flash attention =============================
__global__ __launch_bounds__(256) void attn_tc(
    const float* __restrict__ q, const float* __restrict__ k,
    const float* __restrict__ v, const unsigned char* __restrict__ mask,
    float* __restrict__ o)
{
    extern __shared__ unsigned sm_u[];
    unsigned* Ks = sm_u;
    unsigned* Vs = sm_u + 64*68;
    const int tid = threadIdx.x;
    const int lane = tid & 31, w = tid >> 5;
    unsigned* Ps = sm_u + 2*64*68 + w*16*68;
    const int s = lane >> 2, off = lane & 3;

    const int qt = blockIdx.x, h = blockIdx.y, b = blockIdx.z;
    const size_t bL = (size_t)b * LL;
    const int qr = qt * 128 + w * 16;

    unsigned qa[8][4];
    {
        const float* qp = q + (bL + qr) * Dd + h * Ee;
#pragma unroll
        for (int ks = 0; ks < 8; ks++) {
            qa[ks][0] = f2tf32(0.125f * qp[(size_t)(s    ) * Dd + ks*8 + off    ]);
            qa[ks][1] = f2tf32(0.125f * qp[(size_t)(s + 8) * Dd + ks*8 + off    ]);
            qa[ks][2] = f2tf32(0.125f * qp[(size_t)(s    ) * Dd + ks*8 + off + 4]);
            qa[ks][3] = f2tf32(0.125f * qp[(size_t)(s + 8) * Dd + ks*8 + off + 4]);
        }
    }

    float oa[8][4];
#pragma unroll
    for (int et = 0; et < 8; et++)
#pragma unroll
        for (int j = 0; j < 4; j++) oa[et][j] = 0.f;
    float m0v = -INFINITY, m1v = -INFINITY, l0v = 0.f, l1v = 0.f;

    for (int n0k = 0; n0k < LL; n0k += 64) {
        __syncthreads();
#pragma unroll
        for (int i = 0; i < 4; i++) {
            int u = tid + i*256;
            int row = u >> 4, qc = (u & 15) * 4;
            size_t gr = (bL + n0k + row) * Dd + h*Ee + qc;
            float4 kv = *(const float4*)&k[gr];
            *(uint4*)&Ks[row*68 + qc] = make_uint4(f2tf32(kv.x), f2tf32(kv.y), f2tf32(kv.z), f2tf32(kv.w));
            float4 vv = *(const float4*)&v[gr];
            *(uint4*)&Vs[row*68 + qc] = make_uint4(f2tf32(vv.x), f2tf32(vv.y), f2tf32(vv.z), f2tf32(vv.w));
        }
        __syncthreads();

        float sa[8][4];
#pragma unroll
        for (int nt = 0; nt < 8; nt++)
#pragma unroll
            for (int j = 0; j < 4; j++) sa[nt][j] = 0.f;
#pragma unroll
        for (int ks = 0; ks < 8; ks++) {
#pragma unroll
            for (int nt = 0; nt < 8; nt++) {
                unsigned bf[2];
                bf[0] = Ks[(nt*8 + s)*68 + ks*8 + off];
                bf[1] = Ks[(nt*8 + s)*68 + ks*8 + off + 4];
                mma_tf32(sa[nt], qa[ks], bf);
            }
        }

        float rmax0 = -INFINITY, rmax1 = -INFINITY;
#pragma unroll
        for (int nt = 0; nt < 8; nt++) {
            unsigned char mk0 = mask[bL + n0k + nt*8 + off*2];
            unsigned char mk1 = mask[bL + n0k + nt*8 + off*2 + 1];
            if (mk0) { sa[nt][0] = -INFINITY; sa[nt][2] = -INFINITY; }
            if (mk1) { sa[nt][1] = -INFINITY; sa[nt][3] = -INFINITY; }
            rmax0 = fmaxf(rmax0, fmaxf(sa[nt][0], sa[nt][1]));
            rmax1 = fmaxf(rmax1, fmaxf(sa[nt][2], sa[nt][3]));
        }
        rmax0 = fmaxf(rmax0, __shfl_xor_sync(0xffffffffu, rmax0, 1));
        rmax0 = fmaxf(rmax0, __shfl_xor_sync(0xffffffffu, rmax0, 2));
        rmax1 = fmaxf(rmax1, __shfl_xor_sync(0xffffffffu, rmax1, 1));
        rmax1 = fmaxf(rmax1, __shfl_xor_sync(0xffffffffu, rmax1, 2));
        float mn0 = fmaxf(m0v, rmax0), mn1 = fmaxf(m1v, rmax1);
        float c0 = __expf(m0v - mn0), c1 = __expf(m1v - mn1);
        float rs0 = 0.f, rs1 = 0.f;
#pragma unroll
        for (int nt = 0; nt < 8; nt++) {
            float p0 = __expf(sa[nt][0] - mn0);
            float p1 = __expf(sa[nt][1] - mn0);
            float p2 = __expf(sa[nt][2] - mn1);
            float p3 = __expf(sa[nt][3] - mn1);
            rs0 += p0 + p1; rs1 += p2 + p3;
            Ps[ s     *68 + nt*8 + off*2    ] = f2tf32(p0);
            Ps[ s     *68 + nt*8 + off*2 + 1] = f2tf32(p1);
            Ps[(s + 8)*68 + nt*8 + off*2    ] = f2tf32(p2);
            Ps[(s + 8)*68 + nt*8 + off*2 + 1] = f2tf32(p3);
        }
        rs0 += __shfl_xor_sync(0xffffffffu, rs0, 1);
        rs0 += __shfl_xor_sync(0xffffffffu, rs0, 2);
        rs1 += __shfl_xor_sync(0xffffffffu, rs1, 1);
        rs1 += __shfl_xor_sync(0xffffffffu, rs1, 2);
        l0v = l0v * c0 + rs0; l1v = l1v * c1 + rs1;
        m0v = mn0; m1v = mn1;
#pragma unroll
        for (int et = 0; et < 8; et++) {
            oa[et][0] *= c0; oa[et][1] *= c0;
            oa[et][2] *= c1; oa[et][3] *= c1;
        }
        __syncwarp();

#pragma unroll
        for (int ks = 0; ks < 8; ks++) {
            unsigned pa[4];
            pa[0] = Ps[ s     *68 + ks*8 + off    ];
            pa[1] = Ps[(s + 8)*68 + ks*8 + off    ];
            pa[2] = Ps[ s     *68 + ks*8 + off + 4];
            pa[3] = Ps[(s + 8)*68 + ks*8 + off + 4];
#pragma unroll
            for (int et = 0; et < 8; et++) {
                unsigned bf[2];
                bf[0] = Vs[(ks*8 + off    )*68 + et*8 + s];
                bf[1] = Vs[(ks*8 + off + 4)*68 + et*8 + s];
                mma_tf32(oa[et], pa, bf);
            }
        }
    }

    float inv0 = 1.f / l0v, inv1 = 1.f / l1v;
#pragma unroll
    for (int et = 0; et < 8; et++) {
        size_t r0 = (bL + qr + s    ) * Dd + h*Ee + et*8 + off*2;
        size_t r1 = (bL + qr + s + 8) * Dd + h*Ee + et*8 + off*2;
        *(float2*)&o[r0] = make_float2(oa[et][0]*inv0, oa[et][1]*inv0);
        *(float2*)&o[r1] = make_float2(oa[et][2]*inv1, oa[et][3]*inv1);
    }
}

// ---------------- causal depthwise conv (KC=4) + SiLU ------------------------
__global__ void conv_silu_k(const float* __restrict__ xz,
                            const float* __restrict__ cw,
                            const float* __restrict__ cb,
                            float* __restrict__ uact)
{
    int idx = blockIdx.x * 256 + threadIdx.x;
    int r = idx >> 10;
    int j = idx & 1023;
    int t = r % LL;
    float acc = cb[j];
#pragma unroll
    for (int kk = 0; kk < 4; kk++) {
        int tt = t + kk - 3;
        if (tt >= 0)
            acc = fmaf(xz[(size_t)(r + kk - 3) * (2*DI) + j], cw[j*4 + kk], acc);
    }
    uact[idx] = acc / (1.f + expf(-acc));
}

// -------- selective scan + fused gate: 1 warp per (b,d), 2 states/lane -------
// Per-step shfl tree replaced by SMEM partials + batched per-tile reduction.
// Gate (y + u*D) * silu(z) fused into the output write.
__global__ __launch_bounds__(512) void scan_gate_k(
    const float* __restrict__ delta, const float* __restrict__ uact,
    const float* __restrict__ xdbc, const float* __restrict__ A_log,
    const float* __restrict__ xz,   const float* __restrict__ Dssm,
    float* __restrict__ y)
{
    __shared__ float sB[16][64];
    __shared__ float sC[16][64];
    __shared__ float sdt[16][16];
    __shared__ float su[16][16];
    __shared__ float sz[16][16];
    __shared__ float spw[16][16][33];   // [warp][tt][lane] partials (padded)

    int b = blockIdx.y;
    int d0 = blockIdx.x * 16;
    int tid = threadIdx.x;
    int w = tid >> 5, l = tid & 31;
    int d = d0 + w;
    float a0 = -expf(A_log[d*Ss + l]);
    float a1 = -expf(A_log[d*Ss + l + 32]);
    float dD = Dssm[d];
    float h0 = 0.f, h1 = 0.f;
    size_t base = (size_t)b * LL;

    const int rr = l >> 1;          // reduction row for this lane
    const int half = l & 1;         // which 16-lane half to sum

    for (int t0 = 0; t0 < LL; t0 += 16) {
        __syncthreads();
        // stage B/C
        for (int i = tid; i < 2048; i += 512) {
            int tt = i >> 7, c = i & 127;
            float val = xdbc[(base + t0 + tt) * 160 + 32 + c];
            if (c < 64) sB[tt][c] = val; else sC[tt][c - 64] = val;
        }
        // stage dt / u / z  (768 elements)
        for (int i = tid; i < 768; i += 512) {
            int sel = i >> 8;        // 0:dt 1:u 2:z
            int e = i & 255;
            int tt = e >> 4, c = e & 15;
            size_t row = base + t0 + tt;
            if (sel == 0)      sdt[tt][c] = delta[row * DI + d0 + c];
            else if (sel == 1) su[tt][c]  = uact [row * DI + d0 + c];
            else               sz[tt][c]  = xz[row * (2*DI) + DI + d0 + c];
        }
        __syncthreads();

#pragma unroll 4
        for (int tt = 0; tt < 16; tt++) {
            float dt  = sdt[tt][w];
            float dtu = dt * su[tt][w];
            float dA0 = __expf(dt * a0);
            float dA1 = __expf(dt * a1);
            h0 = fmaf(h0, dA0, dtu * sB[tt][l]);
            h1 = fmaf(h1, dA1, dtu * sB[tt][l + 32]);
            spw[w][tt][l] = fmaf(h1, sC[tt][l + 32], h0 * sC[tt][l]);
        }
        __syncwarp();

        // batched reduction: 2 lanes per row, 16 entries each, then pair-combine
        float accv = 0.f;
#pragma unroll
        for (int i = 0; i < 16; i++) accv += spw[w][rr][half*16 + i];
        accv += __shfl_xor_sync(0xffffffffu, accv, 1);
        if (half == 0) {
            float uu = su[rr][w];
            float zz = sz[rr][w];
            float yv = fmaf(uu, dD, accv);
            y[(base + t0 + rr) * DI + d] = yv * (zz / (1.f + __expf(-zz)));
        }
    }
}

// ---------------- double LayerNorm on pre-summed residual --------------------
__device__ __forceinline__ float blockSum128(float v, float* sm)
{
#pragma unroll
    for (int offx = 16; offx > 0; offx >>= 1)
        v += __shfl_xor_sync(0xffffffffu, v, offx);
    if ((threadIdx.x & 31) == 0) sm[threadIdx.x >> 5] = v;
    __syncthreads();
    float r = sm[0] + sm[1] + sm[2] + sm[3];
    __syncthreads();
    return r;
}

__global__ __launch_bounds__(128) void ln2_k(
    const float* __restrict__ hsum,
    const float* __restrict__ g1, const float* __restrict__ b1,
    const float* __restrict__ g2, const float* __restrict__ b2,
    float* __restrict__ h, float* __restrict__ hn)
{
    __shared__ float sm[4];
    int r = blockIdx.x, tid = threadIdx.x;
    size_t base = (size_t)r * Dd;
    float vv[4];
#pragma unroll
    for (int i = 0; i < 4; i++) vv[i] = hsum[base + tid + i*128];
    float s = vv[0] + vv[1] + vv[2] + vv[3];
    float mean = blockSum128(s, sm) * (1.f/512.f);
    float sq = 0.f;
#pragma unroll
    for (int i = 0; i < 4; i++) { float dd = vv[i] - mean; sq = fmaf(dd, dd, sq); }
    float var = blockSum128(sq, sm) * (1.f/512.f);
    float inv = rsqrtf(var + 1e-5f);
    float hv[4];
#pragma unroll
    for (int i = 0; i < 4; i++) {
        int c = tid + i*128;
        hv[i] = (vv[i] - mean) * inv * g1[c] + b1[c];
        h[base+c] = hv[i];
    }
    float s2 = hv[0] + hv[1] + hv[2] + hv[3];
    float mean2 = blockSum128(s2, sm) * (1.f/512.f);
    float sq2 = 0.f;
#pragma unroll
    for (int i = 0; i < 4; i++) { float dd = hv[i] - mean2; sq2 = fmaf(dd, dd, sq2); }
    float var2 = blockSum128(sq2, sm) * (1.f/512.f);
    float inv2 = rsqrtf(var2 + 1e-6f);
#pragma unroll
    for (int i = 0; i < 4; i++) {
        int c = tid + i*128;
        hn[base+c] = (hv[i] - mean2) * inv2 * g2[c] + b2[c];
    }
}

// ---------------- launch -----------------------------------------------------
extern "C" void kernel_launch(void* const* d_in, const int* in_sizes, int n_in,
                              void* d_out, int out_size)
{
    const float* x            = (const float*)d_in[0];
    const unsigned char* mask = (const unsigned char*)d_in[1];
    const float* Wq = (const float*)d_in[2];   const float* bq = (const float*)d_in[3];
    const float* Wk = (const float*)d_in[4];   const float* bk = (const float*)d_in[5];
    const float* Wv = (const float*)d_in[6];   const float* bv = (const float*)d_in[7];
    const float* Wo = (const float*)d_in[8];   const float* bo = (const float*)d_in[9];
    const float* in_proj_w = (const float*)d_in[10];
    const float* conv_w    = (const float*)d_in[11];
    const float* conv_b    = (const float*)d_in[12];
    const float* x_proj_w  = (const float*)d_in[13];
    const float* dt_proj_w = (const float*)d_in[14];
    const float* dt_proj_b = (const float*)d_in[15];
    const float* A_log     = (const float*)d_in[16];
    const float* D_ssm     = (const float*)d_in[17];
    const float* out_proj_w= (const float*)d_in[18];
    const float* ln1_g = (const float*)d_in[19]; const float* ln1_b = (const float*)d_in[20];
    const float* ffn_w1= (const float*)d_in[21]; const float* ffn_b1= (const float*)d_in[22];
    const float* ffn_w2= (const float*)d_in[23]; const float* ffn_b2= (const float*)d_in[24];
    const float* ln2_g = (const float*)d_in[25]; const float* ln2_b = (const float*)d_in[26];
    float* out = (float*)d_out;

    float *q,*k,*v,*attnO,*attn_out,*xz,*uact,*xdbc,*delta,*y,*hsum,*h,*hn,*mid;
    cudaGetSymbolAddress((void**)&q,        g_q);
    cudaGetSymbolAddress((void**)&k,        g_k);
    cudaGetSymbolAddress((void**)&v,        g_v);
    cudaGetSymbolAddress((void**)&attnO,    g_attnO);
    cudaGetSymbolAddress((void**)&attn_out, g_attn_out);
    cudaGetSymbolAddress((void**)&xz,       g_xz);
    cudaGetSymbolAddress((void**)&uact,     g_uact);
    cudaGetSymbolAddress((void**)&xdbc,     g_xdbc);
    cudaGetSymbolAddress((void**)&delta,    g_delta);
    cudaGetSymbolAddress((void**)&y,        g_y);
    cudaGetSymbolAddress((void**)&hsum,     g_hsum);
    cudaGetSymbolAddress((void**)&h,        g_h);
    cudaGetSymbolAddress((void**)&hn,       g_hn);
    cudaGetSymbolAddress((void**)&mid,      g_mid);

    static cudaStream_t s_attn = nullptr;
    static cudaEvent_t  e_fork = nullptr, e_join = nullptr;
    if (s_attn == nullptr) {
        cudaStreamCreateWithFlags(&s_attn, cudaStreamNonBlocking);
        cudaEventCreateWithFlags(&e_fork, cudaEventDisableTiming);
        cudaEventCreateWithFlags(&e_join, cudaEventDisableTiming);
    }

    const int MY = Mrows / 128;   // 72
    const int attn_smem = (2*64*68 + 8*16*68) * 4;   // 69632 bytes
    cudaFuncSetAttribute(attn_tc, cudaFuncAttributeMaxDynamicSharedMemorySize, attn_smem);

    // ---- fork: attention branch on s_attn, mamba branch on stream 0 ----
    cudaEventRecord(e_fork, 0);
    cudaStreamWaitEvent(s_attn, e_fork, 0);

    // attention branch (s_attn)
    gemm_bf16<EPI_NONE><<<dim3(Dd/64,   MY), 256, 0, s_attn>>>(x, Dd, Wq, bq, nullptr, nullptr, q, Mrows, Dd, Dd);
    gemm_bf16<EPI_NONE><<<dim3(Dd/64,   MY), 256, 0, s_attn>>>(x, Dd, Wk, bk, nullptr, nullptr, k, Mrows, Dd, Dd);
    gemm_bf16<EPI_NONE><<<dim3(Dd/64,   MY), 256, 0, s_attn>>>(x, Dd, Wv, bv, nullptr, nullptr, v, Mrows, Dd, Dd);
    attn_tc<<<dim3(LL/128, Hh, Bsz), 256, attn_smem, s_attn>>>(q, k, v, mask, attnO);
    gemm_bf16<EPI_NONE><<<dim3(Dd/64,   MY), 256, 0, s_attn>>>(attnO, Dd, Wo, bo, nullptr, nullptr, attn_out, Mrows, Dd, Dd);
    cudaEventRecord(e_join, s_attn);

    // mamba branch (stream 0)
    gemm_bf16<EPI_NONE><<<dim3(2*DI/64, MY), 256>>>(x, Dd, in_proj_w, nullptr, nullptr, nullptr, xz, Mrows, 2*DI, Dd);
    conv_silu_k<<<Mrows*DI/256, 256>>>(xz, conv_w, conv_b, uact);
    gemm_tf32<EPI_NONE><<<dim3(3,       MY), 256>>>(uact, DI, x_proj_w, nullptr, nullptr, xdbc, Mrows, 160, DI);
    gemm_tf32<EPI_SOFTPLUS><<<dim3(DI/64, MY), 256>>>(xdbc, 160, dt_proj_w, dt_proj_b, nullptr, delta, Mrows, DI, Rr);
    scan_gate_k<<<dim3(DI/16, Bsz), 512>>>(delta, uact, xdbc, A_log, xz, D_ssm, y);

    // ---- join, then out_proj with fused residual adds (hsum = xf + attn + mamba)
    cudaStreamWaitEvent(0, e_join, 0);
    gemm_bf16<EPI_ADD2><<<dim3(Dd/64,   MY), 256>>>(y, DI, out_proj_w, nullptr, x, attn_out, hsum, Mrows, Dd, DI);

    // double layernorm
    ln2_k<<<Mrows, 128>>>(hsum, ln1_g, ln1_b, ln2_g, ln2_b, h, hn);

    // FFN
    gemm_bf16<EPI_GELU><<<dim3(DFF/64, MY), 256>>>(hn, Dd, ffn_w1, ffn_b1, nullptr, nullptr, mid, Mrows, DFF, Dd);
    gemm_bf16<EPI_ADD><<<dim3(Dd/64,   MY), 256>>>(mid, DFF, ffn_w2, ffn_b2, h, nullptr, out, Mrows, Dd, DFF);
}

// round 12
// speedup vs baseline: 1.1019x; 1.0526x over previous
#include <cuda_runtime.h>
#include <cuda_bf16.h>
#include <math.h>

#define Bsz 8
#define Dd 512
#define Hh 8
#define Ee 64
#define DI 1024
#define Ss 64
#define Rr 32
#define DFF 2048
#define LL 1152
#define Mrows (Bsz*LL)   /* 9216 */

// ---------------- scratch (static __device__, no allocation) ----------------
__device__ __nv_bfloat16 g_q[Mrows*Dd];
__device__ __nv_bfloat16 g_k[Mrows*Dd];
__device__ __nv_bfloat16 g_v[Mrows*Dd];
__device__ float g_attnO[Mrows*Dd];
__device__ float g_attn_out[Mrows*Dd];
__device__ float g_xz[Mrows*2*DI];
__device__ float g_uact[Mrows*DI];
__device__ float g_xdbc[Mrows*160];
__device__ float g_delta[Mrows*DI];
__device__ float g_y[Mrows*DI];
__device__ float g_hsum[Mrows*Dd];
__device__ float g_h[Mrows*Dd];
__device__ float g_hn[Mrows*Dd];
__device__ float g_mid[Mrows*DFF];

enum { EPI_NONE = 0, EPI_SOFTPLUS = 1, EPI_GELU = 2, EPI_ADD = 3, EPI_ADD2 = 4 };

__device__ __forceinline__ unsigned f2tf32(float f)
{
    unsigned u;
    asm("cvt.rna.tf32.f32 %0, %1;" : "=r"(u) : "f"(f));
    return u;
}

__device__ __forceinline__ void mma_tf32(float* c, const unsigned* a, const unsigned* b)
{
    asm volatile(
        "mma.sync.aligned.m16n8k8.row.col.f32.tf32.tf32.f32 "
        "{%0,%1,%2,%3},{%4,%5,%6,%7},{%8,%9},{%0,%1,%2,%3};"
        : "+f"(c[0]), "+f"(c[1]), "+f"(c[2]), "+f"(c[3])
        : "r"(a[0]), "r"(a[1]), "r"(a[2]), "r"(a[3]), "r"(b[0]), "r"(b[1]));
}

__device__ __forceinline__ void mma_bf16(float* c, const unsigned* a, const unsigned* b)
{
    asm volatile(
        "mma.sync.aligned.m16n8k16.row.col.f32.bf16.bf16.f32 "
        "{%0,%1,%2,%3},{%4,%5,%6,%7},{%8,%9},{%0,%1,%2,%3};"
        : "+f"(c[0]), "+f"(c[1]), "+f"(c[2]), "+f"(c[3])
        : "r"(a[0]), "r"(a[1]), "r"(a[2]), "r"(a[3]), "r"(b[0]), "r"(b[1]));
}

__device__ __forceinline__ void ldsm4(unsigned* r, unsigned saddr)
{
    asm volatile("ldmatrix.sync.aligned.m8n8.x4.shared.b16 {%0,%1,%2,%3}, [%4];"
        : "=r"(r[0]), "=r"(r[1]), "=r"(r[2]), "=r"(r[3]) : "r"(saddr));
}

__device__ __forceinline__ void ldsm4t(unsigned* r, unsigned saddr)
{
    asm volatile("ldmatrix.sync.aligned.m8n8.x4.trans.shared.b16 {%0,%1,%2,%3}, [%4];"
        : "=r"(r[0]), "=r"(r[1]), "=r"(r[2]), "=r"(r[3]) : "r"(saddr));
}

__device__ __forceinline__ uint2 pack4(float4 f)
{
    __nv_bfloat162 p0 = __floats2bfloat162_rn(f.x, f.y);
    __nv_bfloat162 p1 = __floats2bfloat162_rn(f.z, f.w);
    uint2 u;
    u.x = *(unsigned*)&p0;
    u.y = *(unsigned*)&p1;
    return u;
}

__device__ __forceinline__ unsigned packbf2(float a, float b)
{
    __nv_bfloat162 p = __floats2bfloat162_rn(a, b);
    return *(unsigned*)&p;
}

__device__ __forceinline__ float epi_apply_scalar(int EPI, float v)
{
    if (EPI == EPI_SOFTPLUS) return (v > 20.f) ? v : log1pf(expf(v));
    if (EPI == EPI_GELU)     return 0.5f*v*(1.f + erff(v*0.7071067811865475f));
    return v;
}

// ====== bf16 tensor-core GEMM, 128x64 block tile: C = A(MxK) @ W(NxK)^T ======
// OBF=1: write output as bf16 (N even, col pairs).
template<int EPI, int OBF>
__global__ __launch_bounds__(256) void gemm_bf16(
    const float* __restrict__ A, int lda,
    const float* __restrict__ W,
    const float* __restrict__ bias,
    const float* __restrict__ add,
    const float* __restrict__ add2,
    void* __restrict__ Cv, int M, int N, int K)
{
    __shared__ __align__(16) char sm[2*16384 + 2*8192];
    char* AsP = sm;
    char* BsP = sm + 2*16384;
    const unsigned asU = (unsigned)__cvta_generic_to_shared(AsP);
    const unsigned bsU = (unsigned)__cvta_generic_to_shared(BsP);

    const int tid = threadIdx.x;
    const int lane = tid & 31, w = tid >> 5;
    const int warpM = w & 3, warpN = w >> 2;
    const int m0 = blockIdx.y * 128, n0 = blockIdx.x * 64;

    const int arow0 = tid >> 4;
    const int akq   = (tid & 15) * 4;
    const float* Ap = A + (size_t)(m0 + arow0) * lda + akq;
    const int aso0 = arow0*128 + (((akq >> 3) ^ (arow0 & 7)) << 4) + (akq & 7)*2;

    const float* Bp = W + (size_t)(n0 + arow0) * K + akq;
    const int bso0 = aso0;
    bool bnv[4];
#pragma unroll
    for (int i = 0; i < 4; i++) bnv[i] = (n0 + arow0 + 16*i) < N;

    const int lr = (lane & 7) + ((lane >> 3) & 1) * 8;
    const int ko = (lane >> 4);
    int rA[2], mA[2];
#pragma unroll
    for (int mi = 0; mi < 2; mi++) {
        int r = warpM*32 + mi*16 + lr;
        rA[mi] = r * 128; mA[mi] = r & 7;
    }
    int rB[2], mB[2];
#pragma unroll
    for (int nh = 0; nh < 2; nh++) {
        int r = warpN*32 + nh*16 + lr;
        rB[nh] = r * 128; mB[nh] = r & 7;
    }

    float acc[2][4][4];
#pragma unroll
    for (int mi = 0; mi < 2; mi++)
#pragma unroll
        for (int nf = 0; nf < 4; nf++)
#pragma unroll
            for (int j = 0; j < 4; j++) acc[mi][nf][j] = 0.f;

    const int nk = (K + 63) >> 6;
    float4 ar[8], br[4];

    {
        const bool av = akq < K;
#pragma unroll
        for (int i = 0; i < 8; i++)
            ar[i] = av ? *(const float4*)(Ap + (size_t)i*16*lda) : make_float4(0.f,0.f,0.f,0.f);
#pragma unroll
        for (int i = 0; i < 4; i++)
            br[i] = (bnv[i] && av) ? *(const float4*)(Bp + (size_t)i*16*K) : make_float4(0.f,0.f,0.f,0.f);
#pragma unroll
        for (int i = 0; i < 8; i++) *(uint2*)(AsP + aso0 + i*2048) = pack4(ar[i]);
#pragma unroll
        for (int i = 0; i < 4; i++) *(uint2*)(BsP + bso0 + i*2048) = pack4(br[i]);
    }
    __syncthreads();

    for (int kt = 0; kt < nk; kt++) {
        const int cur = kt & 1;
        const bool more = (kt + 1) < nk;
        if (more) {
            const int kof = (kt + 1) << 6;
            const bool av = (akq + kof) < K;
#pragma unroll
            for (int i = 0; i < 8; i++)
                ar[i] = av ? *(const float4*)(Ap + kof + (size_t)i*16*lda) : make_float4(0.f,0.f,0.f,0.f);
#pragma unroll
            for (int i = 0; i < 4; i++)
                br[i] = (bnv[i] && av) ? *(const float4*)(Bp + kof + (size_t)i*16*K) : make_float4(0.f,0.f,0.f,0.f);
        }

        const unsigned aB = asU + cur*16384;
        const unsigned bB = bsU + cur*8192;
#pragma unroll
        for (int ks = 0; ks < 4; ks++) {
            const int kx = 2*ks + ko;
            unsigned afr[2][4], bfr[2][4];
#pragma unroll
            for (int mi = 0; mi < 2; mi++)
                ldsm4(afr[mi], aB + rA[mi] + ((kx ^ mA[mi]) << 4));
#pragma unroll
            for (int nh = 0; nh < 2; nh++)
                ldsm4(bfr[nh], bB + rB[nh] + ((kx ^ mB[nh]) << 4));
#pragma unroll
            for (int mi = 0; mi < 2; mi++) {
                unsigned b0[2] = {bfr[0][0], bfr[0][2]};
                unsigned b1[2] = {bfr[0][1], bfr[0][3]};
                unsigned b2[2] = {bfr[1][0], bfr[1][2]};
                unsigned b3[2] = {bfr[1][1], bfr[1][3]};
                mma_bf16(acc[mi][0], afr[mi], b0);
                mma_bf16(acc[mi][1], afr[mi], b1);
                mma_bf16(acc[mi][2], afr[mi], b2);
                mma_bf16(acc[mi][3], afr[mi], b3);
            }
        }

        if (more) {
            const int nxt = cur ^ 1;
#pragma unroll
            for (int i = 0; i < 8; i++) *(uint2*)(AsP + nxt*16384 + aso0 + i*2048) = pack4(ar[i]);
#pragma unroll
            for (int i = 0; i < 4; i++) *(uint2*)(BsP + nxt*8192  + bso0 + i*2048) = pack4(br[i]);
            __syncthreads();
        }
    }

#pragma unroll
    for (int mi = 0; mi < 2; mi++) {
#pragma unroll
        for (int nf = 0; nf < 4; nf++) {
            int row = m0 + warpM*32 + mi*16 + (lane >> 2);
            int col = n0 + warpN*32 + nf*8 + (lane & 3)*2;
            if (col < N) {
                float v00 = acc[mi][nf][0], v01 = acc[mi][nf][1];
                float v10 = acc[mi][nf][2], v11 = acc[mi][nf][3];
                if (bias) {
                    float b0 = bias[col], b1 = bias[col+1];
                    v00 += b0; v01 += b1; v10 += b0; v11 += b1;
                }
                if (EPI == EPI_ADD || EPI == EPI_ADD2) {
                    const float* ap0 = add + (size_t)row * N + col;
                    const float* ap1 = add + (size_t)(row+8) * N + col;
                    v00 += ap0[0]; v01 += ap0[1]; v10 += ap1[0]; v11 += ap1[1];
                    if (EPI == EPI_ADD2) {
                        const float* bp0 = add2 + (size_t)row * N + col;
                        const float* bp1 = add2 + (size_t)(row+8) * N + col;
                        v00 += bp0[0]; v01 += bp0[1]; v10 += bp1[0]; v11 += bp1[1];
                    }
                } else {
                    v00 = epi_apply_scalar(EPI, v00); v01 = epi_apply_scalar(EPI, v01);
                    v10 = epi_apply_scalar(EPI, v10); v11 = epi_apply_scalar(EPI, v11);
                }
                if (OBF) {
                    __nv_bfloat16* C16 = (__nv_bfloat16*)Cv;
                    *(unsigned*)&C16[(size_t)row * N + col]     = packbf2(v00, v01);
                    *(unsigned*)&C16[(size_t)(row+8) * N + col] = packbf2(v10, v11);
                } else {
                    float* C = (float*)Cv;
                    *(float2*)&C[(size_t)row * N + col]     = make_float2(v00, v01);
                    *(float2*)&C[(size_t)(row+8) * N + col] = make_float2(v10, v11);
                }
            }
        }
    }
}

// ================= tf32 tensor-core GEMM (scan-sensitive projections) ========
template<int EPI>
__global__ __launch_bounds__(256) void gemm_tf32(
    const float* __restrict__ A, int lda,
    const float* __restrict__ W,
    const float* __restrict__ bias,
    float* __restrict__ C, int M, int N, int K)
{
    __shared__ __align__(16) unsigned As[2][128*32];
    __shared__ __align__(16) unsigned Bs[2][64*32];

    const int t = threadIdx.x;
    const int m0 = blockIdx.y * 128, n0 = blockIdx.x * 64;
    const int lane = t & 31, w = t >> 5;
    const int warpM = w & 3, warpN = w >> 2;
    const int s = lane >> 2, off = lane & 3;

    const float* aptr[4]; int aso[4];
#pragma unroll
    for (int i = 0; i < 4; i++) {
        int e = t + i*256;
        int m = e >> 3, g = e & 7;
        aptr[i] = A + (size_t)(m0 + m) * lda + g*4;
        aso[i]  = m*32 + ((g ^ (m & 7)) << 2);
    }
    const float* bptr[2]; int bso[2]; bool bval[2];
#pragma unroll
    for (int i = 0; i < 2; i++) {
        int e = t + i*256;
        int n = e >> 3, g = e & 7;
        bval[i] = (n0 + n) < N;
        bptr[i] = W + (size_t)(n0 + n) * K + g*4;
        bso[i]  = n*32 + ((g ^ (n & 7)) << 2);
    }

    float acc[2][4][4];
#pragma unroll
    for (int mi = 0; mi < 2; mi++)
#pragma unroll
        for (int ni = 0; ni < 4; ni++)
#pragma unroll
            for (int j = 0; j < 4; j++) acc[mi][ni][j] = 0.f;

    const int nk = K >> 5;
    float4 ar[4], br[2];

#pragma unroll
    for (int i = 0; i < 4; i++) ar[i] = *(const float4*)(aptr[i]);
#pragma unroll
    for (int i = 0; i < 2; i++)
        br[i] = bval[i] ? *(const float4*)(bptr[i]) : make_float4(0.f,0.f,0.f,0.f);
#pragma unroll
    for (int i = 0; i < 4; i++)
        *(uint4*)&As[0][aso[i]] = make_uint4(f2tf32(ar[i].x), f2tf32(ar[i].y), f2tf32(ar[i].z), f2tf32(ar[i].w));
#pragma unroll
    for (int i = 0; i < 2; i++)
        *(uint4*)&Bs[0][bso[i]] = make_uint4(f2tf32(br[i].x), f2tf32(br[i].y), f2tf32(br[i].z), f2tf32(br[i].w));
    __syncthreads();

    for (int kt = 0; kt < nk; kt++) {
        const int cur = kt & 1, nxt = cur ^ 1;
        const bool more = (kt + 1) < nk;
        if (more) {
            const int ko = (kt + 1) * 32;
#pragma unroll
            for (int i = 0; i < 4; i++) ar[i] = *(const float4*)(aptr[i] + ko);
#pragma unroll
            for (int i = 0; i < 2; i++)
                br[i] = bval[i] ? *(const float4*)(bptr[i] + ko) : make_float4(0.f,0.f,0.f,0.f);
        }

#pragma unroll
        for (int ks = 0; ks < 4; ks++) {
            const int x0 = (((ks*2)     ^ s) << 2) + off;
            const int x1 = (((ks*2 + 1) ^ s) << 2) + off;
            unsigned a[2][4];
#pragma unroll
            for (int mi = 0; mi < 2; mi++) {
                int r = (warpM*32 + mi*16 + s) * 32;
                a[mi][0] = As[cur][r + x0];
                a[mi][1] = As[cur][r + 256 + x0];
                a[mi][2] = As[cur][r + x1];
                a[mi][3] = As[cur][r + 256 + x1];
            }
            unsigned b[4][2];
#pragma unroll
            for (int ni = 0; ni < 4; ni++) {
                int rb = (warpN*32 + ni*8 + s) * 32;
                b[ni][0] = Bs[cur][rb + x0];
                b[ni][1] = Bs[cur][rb + x1];
            }
#pragma unroll
            for (int mi = 0; mi < 2; mi++)
#pragma unroll
                for (int ni = 0; ni < 4; ni++)
                    mma_tf32(acc[mi][ni], a[mi], b[ni]);
        }

        if (more) {
#pragma unroll
            for (int i = 0; i < 4; i++)
                *(uint4*)&As[nxt][aso[i]] = make_uint4(f2tf32(ar[i].x), f2tf32(ar[i].y), f2tf32(ar[i].z), f2tf32(ar[i].w));
#pragma unroll
            for (int i = 0; i < 2; i++)
                *(uint4*)&Bs[nxt][bso[i]] = make_uint4(f2tf32(br[i].x), f2tf32(br[i].y), f2tf32(br[i].z), f2tf32(br[i].w));
            __syncthreads();
        }
    }

#pragma unroll
    for (int mi = 0; mi < 2; mi++) {
#pragma unroll
        for (int ni = 0; ni < 4; ni++) {
            int row = m0 + warpM*32 + mi*16 + s;
            int col = n0 + warpN*32 + ni*8 + off*2;
            if (col < N) {
                float v00 = acc[mi][ni][0], v01 = acc[mi][ni][1];
                float v10 = acc[mi][ni][2], v11 = acc[mi][ni][3];
                if (bias) {
                    float b0 = bias[col], b1 = bias[col+1];
                    v00 += b0; v01 += b1; v10 += b0; v11 += b1;
                }
                v00 = epi_apply_scalar(EPI, v00); v01 = epi_apply_scalar(EPI, v01);
                v10 = epi_apply_scalar(EPI, v10); v11 = epi_apply_scalar(EPI, v11);
                *(float2*)&C[(size_t)row * N + col]     = make_float2(v00, v01);
                *(float2*)&C[(size_t)(row+8) * N + col] = make_float2(v10, v11);
            }
        }
    }
}

// ============== bf16 tensor-core flash attention (ldmatrix) ==================
// Block: 128 q rows x (b,h); 8 warps x 16 rows; 64-key tiles.
// SMEM: Q[128][128B] + K[64][128B] + V[64][128B] + per-warp P[16][128B] = 48KB
__global__ __launch_bounds__(256) void attn_bf(
    const __nv_bfloat16* __restrict__ q, const __nv_bfloat16* __restrict__ k,
    const __nv_bfloat16* __restrict__ v, const unsigned char* __restrict__ mask,
    float* __restrict__ o)
{
    extern __shared__ __align__(16) char smA[];
    char* sQ = smA;                  // 16384
    char* sK = smA + 16384;          // 8192
    char* sV = smA + 24576;          // 8192
    const int tid = threadIdx.x;
    const int lane = tid & 31, w = tid >> 5;
    char* sP = smA + 32768 + w*2048; // per-warp 2048
    const unsigned uQ = (unsigned)__cvta_generic_to_shared(sQ);
    const unsigned uK = (unsigned)__cvta_generic_to_shared(sK);
    const unsigned uV = (unsigned)__cvta_generic_to_shared(sV);
    const unsigned uP = (unsigned)__cvta_generic_to_shared(sP);

    const int qt = blockIdx.x, h = blockIdx.y, b = blockIdx.z;
    const size_t bL = (size_t)b * LL;
    const int qr = qt * 128;

    const int lr = (lane & 7) + ((lane >> 3) & 1) * 8;
    const int ko = lane >> 4;
    const int s = lane >> 2, off = lane & 3;

    // stage Q tile (128 rows x 64 bf16, SW128 swizzle)
#pragma unroll
    for (int i = 0; i < 4; i++) {
        int u = tid + i*256;
        int row = u >> 3, g = u & 7;
        uint4 val = *(const uint4*)&q[(bL + qr + row) * Dd + h*Ee + g*8];
        *(uint4*)(sQ + row*128 + ((g ^ (row & 7)) << 4)) = val;
    }
    __syncthreads();

    // Q A-fragments (per warp rows w*16..w*16+15), kept in regs for all tiles
    unsigned qa[4][4];
    {
        int r = w*16 + lr;
        unsigned base = uQ + r*128;
#pragma unroll
        for (int ks = 0; ks < 4; ks++)
            ldsm4(qa[ks], base + (((2*ks + ko) ^ (r & 7)) << 4));
    }

    float oa[8][4];
#pragma unroll
    for (int et = 0; et < 8; et++)
#pragma unroll
        for (int j = 0; j < 4; j++) oa[et][j] = 0.f;
    float m0v = -INFINITY, m1v = -INFINITY, l0v = 0.f, l1v = 0.f;

    for (int n0k = 0; n0k < LL; n0k += 64) {
        __syncthreads();
        // stage K/V tile (each 64 rows x 64 bf16)
#pragma unroll
        for (int i = 0; i < 2; i++) {
            int u = tid + i*256;
            int row = u >> 3, g = u & 7;
            size_t gr = (bL + n0k + row) * Dd + h*Ee + g*8;
            int so = row*128 + ((g ^ (row & 7)) << 4);
            *(uint4*)(sK + so) = *(const uint4*)&k[gr];
            *(uint4*)(sV + so) = *(const uint4*)&v[gr];
        }
        __syncthreads();

        // S = Q K^T  (sa[nt] covers keys nt*8..nt*8+7)
        float sa[8][4];
#pragma unroll
        for (int nt = 0; nt < 8; nt++)
#pragma unroll
            for (int j = 0; j < 4; j++) sa[nt][j] = 0.f;
#pragma unroll
        for (int ks = 0; ks < 4; ks++) {
#pragma unroll
            for (int nb = 0; nb < 4; nb++) {
                unsigned bfr[4];
                int r = nb*16 + lr;
                ldsm4(bfr, uK + r*128 + (((2*ks + ko) ^ (r & 7)) << 4));
                unsigned b0[2] = {bfr[0], bfr[2]};
                unsigned b1[2] = {bfr[1], bfr[3]};
                mma_bf16(sa[nb*2],     qa[ks], b0);
                mma_bf16(sa[nb*2 + 1], qa[ks], b1);
            }
        }

        // scale + mask + online softmax
        float rmax0 = -INFINITY, rmax1 = -INFINITY;
#pragma unroll
        for (int nt = 0; nt < 8; nt++) {
            sa[nt][0] *= 0.125f; sa[nt][1] *= 0.125f;
            sa[nt][2] *= 0.125f; sa[nt][3] *= 0.125f;
            unsigned char mk0 = mask[bL + n0k + nt*8 + off*2];
            unsigned char mk1 = mask[bL + n0k + nt*8 + off*2 + 1];
            if (mk0) { sa[nt][0] = -INFINITY; sa[nt][2] = -INFINITY; }
            if (mk1) { sa[nt][1] = -INFINITY; sa[nt][3] = -INFINITY; }
            rmax0 = fmaxf(rmax0, fmaxf(sa[nt][0], sa[nt][1]));
            rmax1 = fmaxf(rmax1, fmaxf(sa[nt][2], sa[nt][3]));
        }
        rmax0 = fmaxf(rmax0, __shfl_xor_sync(0xffffffffu, rmax0, 1));
        rmax0 = fmaxf(rmax0, __shfl_xor_sync(0xffffffffu, rmax0, 2));
        rmax1 = fmaxf(rmax1, __shfl_xor_sync(0xffffffffu, rmax1, 1));
        rmax1 = fmaxf(rmax1, __shfl_xor_sync(0xffffffffu, rmax1, 2));
        float mn0 = fmaxf(m0v, rmax0), mn1 = fmaxf(m1v, rmax1);
        float c0 = __expf(m0v - mn0), c1 = __expf(m1v - mn1);
        float rs0 = 0.f, rs1 = 0.f;
#pragma unroll
        for (int nt = 0; nt < 8; nt++) {
            float p0 = __expf(sa[nt][0] - mn0);
            float p1 = __expf(sa[nt][1] - mn0);
            float p2 = __expf(sa[nt][2] - mn1);
            float p3 = __expf(sa[nt][3] - mn1);
            rs0 += p0 + p1; rs1 += p2 + p3;
            // P bf16 pairs, SW128 rows (conflict-free: bank = 4*(nt^s)+off)
            *(unsigned*)(sP + s*128       + ((nt ^ (s & 7)) << 4) + off*4) = packbf2(p0, p1);
            *(unsigned*)(sP + (s+8)*128   + ((nt ^ (s & 7)) << 4) + off*4) = packbf2(p2, p3);
        }
        rs0 += __shfl_xor_sync(0xffffffffu, rs0, 1);
        rs0 += __shfl_xor_sync(0xffffffffu, rs0, 2);
        rs1 += __shfl_xor_sync(0xffffffffu, rs1, 1);
        rs1 += __shfl_xor_sync(0xffffffffu, rs1, 2);
        l0v = l0v * c0 + rs0; l1v = l1v * c1 + rs1;
        m0v = mn0; m1v = mn1;
#pragma unroll
        for (int et = 0; et < 8; et++) {
            oa[et][0] *= c0; oa[et][1] *= c0;
            oa[et][2] *= c1; oa[et][3] *= c1;
        }
        __syncwarp();

        // O += P V   (B-frags: ldmatrix.trans on row-major V)
#pragma unroll
        for (int ksp = 0; ksp < 4; ksp++) {
            unsigned pa[4];
            {
                int r = lr;
                ldsm4(pa, uP + r*128 + (((2*ksp + ko) ^ (r & 7)) << 4));
            }
            int key = ksp*16 + lr;
#pragma unroll
            for (int j = 0; j < 4; j++) {
                unsigned vfr[4];
                ldsm4t(vfr, uV + key*128 + (((2*j + ko) ^ (key & 7)) << 4));
                unsigned be0[2] = {vfr[0], vfr[1]};
                unsigned be1[2] = {vfr[2], vfr[3]};
                mma_bf16(oa[j*2],     pa, be0);
                mma_bf16(oa[j*2 + 1], pa, be1);
            }
        }
    }

    float inv0 = 1.f / l0v, inv1 = 1.f / l1v;
#pragma unroll
    for (int et = 0; et < 8; et++) {
        size_t r0 = (bL + qr + w*16 + s    ) * Dd + h*Ee + et*8 + off*2;
        size_t r1 = (bL + qr + w*16 + s + 8) * Dd + h*Ee + et*8 + off*2;
        *(float2*)&o[r0] = make_float2(oa[et][0]*inv0, oa[et][1]*inv0);
        *(float2*)&o[r1] = make_float2(oa[et][2]*inv1, oa[et][3]*inv1);
    }
}

// ---------------- causal depthwise conv (KC=4) + SiLU ------------------------
__global__ void conv_silu_k(const float* __restrict__ xz,
                            const float* __restrict__ cw,
                            const float* __restrict__ cb,
                            float* __restrict__ uact)
{
    int idx = blockIdx.x * 256 + threadIdx.x;
    int r = idx >> 10;
    int j = idx & 1023;
    int t = r % LL;
    float acc = cb[j];
#pragma unroll
    for (int kk = 0; kk < 4; kk++) {
        int tt = t + kk - 3;
        if (tt >= 0)
            acc = fmaf(xz[(size_t)(r + kk - 3) * (2*DI) + j], cw[j*4 + kk], acc);
    }
    uact[idx] = acc / (1.f + expf(-acc));
}

// -------- selective scan + fused gate: 1 warp per (b,d), 2 states/lane -------
__global__ __launch_bounds__(512) void scan_gate_k(
    const float* __restrict__ delta, const float* __restrict__ uact,
    const float* __restrict__ xdbc, const float* __restrict__ A_log,
    const float* __restrict__ xz,   const float* __restrict__ Dssm,
    float* __restrict__ y)
{
    __shared__ float sB[16][64];
    __shared__ float sC[16][64];
    __shared__ float sdt[16][16];
    __shared__ float su[16][16];
    __shared__ float sz[16][16];
    __shared__ float spw[16][16][33];

    int b = blockIdx.y;
    int d0 = blockIdx.x * 16;
    int tid = threadIdx.x;
    int w = tid >> 5, l = tid & 31;
    int d = d0 + w;
    float a0 = -expf(A_log[d*Ss + l]);
    float a1 = -expf(A_log[d*Ss + l + 32]);
    float dD = Dssm[d];
    float h0 = 0.f, h1 = 0.f;
    size_t base = (size_t)b * LL;

    const int rr = l >> 1;
    const int half = l & 1;

    for (int t0 = 0; t0 < LL; t0 += 16) {
        __syncthreads();
        for (int i = tid; i < 2048; i += 512) {
            int tt = i >> 7, c = i & 127;
            float val = xdbc[(base + t0 + tt) * 160 + 32 + c];
            if (c < 64) sB[tt][c] = val; else sC[tt][c - 64] = val;
        }
        for (int i = tid; i < 768; i += 512) {
            int sel = i >> 8;
            int e = i & 255;
            int tt = e >> 4, c = e & 15;
            size_t row = base + t0 + tt;
            if (sel == 0)      sdt[tt][c] = delta[row * DI + d0 + c];
            else if (sel == 1) su[tt][c]  = uact [row * DI + d0 + c];
            else               sz[tt][c]  = xz[row * (2*DI) + DI + d0 + c];
        }
        __syncthreads();

#pragma unroll 4
        for (int tt = 0; tt < 16; tt++) {
            float dt  = sdt[tt][w];
            float dtu = dt * su[tt][w];
            float dA0 = __expf(dt * a0);
            float dA1 = __expf(dt * a1);
            h0 = fmaf(h0, dA0, dtu * sB[tt][l]);
            h1 = fmaf(h1, dA1, dtu * sB[tt][l + 32]);
            spw[w][tt][l] = fmaf(h1, sC[tt][l + 32], h0 * sC[tt][l]);
        }
        __syncwarp();

        float accv = 0.f;
#pragma unroll
        for (int i = 0; i < 16; i++) accv += spw[w][rr][half*16 + i];
        accv += __shfl_xor_sync(0xffffffffu, accv, 1);
        if (half == 0) {
            float uu = su[rr][w];
            float zz = sz[rr][w];
            float yv = fmaf(uu, dD, accv);
            y[(base + t0 + rr) * DI + d] = yv * (zz / (1.f + __expf(-zz)));
        }
    }
}

// ---------------- double LayerNorm on pre-summed residual --------------------
__device__ __forceinline__ float blockSum128(float v, float* sm)
{
#pragma unroll
    for (int offx = 16; offx > 0; offx >>= 1)
        v += __shfl_xor_sync(0xffffffffu, v, offx);
    if ((threadIdx.x & 31) == 0) sm[threadIdx.x >> 5] = v;
    __syncthreads();
    float r = sm[0] + sm[1] + sm[2] + sm[3];
    __syncthreads();
    return r;
}

__global__ __launch_bounds__(128) void ln2_k(
    const float* __restrict__ hsum,
    const float* __restrict__ g1, const float* __restrict__ b1,
    const float* __restrict__ g2, const float* __restrict__ b2,
    float* __restrict__ h, float* __restrict__ hn)
{
    __shared__ float sm[4];
    int r = blockIdx.x, tid = threadIdx.x;
    size_t base = (size_t)r * Dd;
    float vv[4];
#pragma unroll
    for (int i = 0; i < 4; i++) vv[i] = hsum[base + tid + i*128];
    float s = vv[0] + vv[1] + vv[2] + vv[3];
    float mean = blockSum128(s, sm) * (1.f/512.f);
    float sq = 0.f;
#pragma unroll
    for (int i = 0; i < 4; i++) { float dd = vv[i] - mean; sq = fmaf(dd, dd, sq); }
    float var = blockSum128(sq, sm) * (1.f/512.f);
    float inv = rsqrtf(var + 1e-5f);
    float hv[4];
#pragma unroll
    for (int i = 0; i < 4; i++) {
        int c = tid + i*128;
        hv[i] = (vv[i] - mean) * inv * g1[c] + b1[c];
        h[base+c] = hv[i];
    }
    float s2 = hv[0] + hv[1] + hv[2] + hv[3];
    float mean2 = blockSum128(s2, sm) * (1.f/512.f);
    float sq2 = 0.f;
#pragma unroll
    for (int i = 0; i < 4; i++) { float dd = hv[i] - mean2; sq2 = fmaf(dd, dd, sq2); }
    float var2 = blockSum128(sq2, sm) * (1.f/512.f);
    float inv2 = rsqrtf(var2 + 1e-6f);
#pragma unroll
    for (int i = 0; i < 4; i++) {
        int c = tid + i*128;
        hn[base+c] = (hv[i] - mean2) * inv2 * g2[c] + b2[c];
    }
}

// ---------------- launch -----------------------------------------------------
extern "C" void kernel_launch(void* const* d_in, const int* in_sizes, int n_in,
                              void* d_out, int out_size)
{
    const float* x            = (const float*)d_in[0];
    const unsigned char* mask = (const unsigned char*)d_in[1];
    const float* Wq = (const float*)d_in[2];   const float* bq = (const float*)d_in[3];
    const float* Wk = (const float*)d_in[4];   const float* bk = (const float*)d_in[5];
    const float* Wv = (const float*)d_in[6];   const float* bv = (const float*)d_in[7];
    const float* Wo = (const float*)d_in[8];   const float* bo = (const float*)d_in[9];
    const float* in_proj_w = (const float*)d_in[10];
    const float* conv_w    = (const float*)d_in[11];
    const float* conv_b    = (const float*)d_in[12];
    const float* x_proj_w  = (const float*)d_in[13];
    const float* dt_proj_w = (const float*)d_in[14];
    const float* dt_proj_b = (const float*)d_in[15];
    const float* A_log     = (const float*)d_in[16];
    const float* D_ssm     = (const float*)d_in[17];
    const float* out_proj_w= (const float*)d_in[18];
    const float* ln1_g = (const float*)d_in[19]; const float* ln1_b = (const float*)d_in[20];
    const float* ffn_w1= (const float*)d_in[21]; const float* ffn_b1= (const float*)d_in[22];
    const float* ffn_w2= (const float*)d_in[23]; const float* ffn_b2= (const float*)d_in[24];
    const float* ln2_g = (const float*)d_in[25]; const float* ln2_b = (const float*)d_in[26];
    float* out = (float*)d_out;

    __nv_bfloat16 *q, *k, *v;
    float *attnO,*attn_out,*xz,*uact,*xdbc,*delta,*y,*hsum,*h,*hn,*mid;
    cudaGetSymbolAddress((void**)&q,        g_q);
    cudaGetSymbolAddress((void**)&k,        g_k);
    cudaGetSymbolAddress((void**)&v,        g_v);
    cudaGetSymbolAddress((void**)&attnO,    g_attnO);
    cudaGetSymbolAddress((void**)&attn_out, g_attn_out);
    cudaGetSymbolAddress((void**)&xz,       g_xz);
    cudaGetSymbolAddress((void**)&uact,     g_uact);
    cudaGetSymbolAddress((void**)&xdbc,     g_xdbc);
    cudaGetSymbolAddress((void**)&delta,    g_delta);
    cudaGetSymbolAddress((void**)&y,        g_y);
    cudaGetSymbolAddress((void**)&hsum,     g_hsum);
    cudaGetSymbolAddress((void**)&h,        g_h);
    cudaGetSymbolAddress((void**)&hn,       g_hn);
    cudaGetSymbolAddress((void**)&mid,      g_mid);

    static cudaStream_t s_attn = nullptr;
    static cudaEvent_t  e_fork = nullptr, e_join = nullptr;
    if (s_attn == nullptr) {
        cudaStreamCreateWithFlags(&s_attn, cudaStreamNonBlocking);
        cudaEventCreateWithFlags(&e_fork, cudaEventDisableTiming);
        cudaEventCreateWithFlags(&e_join, cudaEventDisableTiming);
    }

    const int MY = Mrows / 128;   // 72
    const int attn_smem = 32768 + 8*2048;   // 49152 bytes
    cudaFuncSetAttribute(attn_bf, cudaFuncAttributeMaxDynamicSharedMemorySize, attn_smem);

    // ---- fork: attention branch on s_attn, mamba branch on stream 0 ----
    cudaEventRecord(e_fork, 0);
    cudaStreamWaitEvent(s_attn, e_fork, 0);

    // attention branch (s_attn) — qkv written directly as bf16
    gemm_bf16<EPI_NONE,1><<<dim3(Dd/64,   MY), 256, 0, s_attn>>>(x, Dd, Wq, bq, nullptr, nullptr, q, Mrows, Dd, Dd);
    gemm_bf16<EPI_NONE,1><<<dim3(Dd/64,   MY), 256, 0, s_attn>>>(x, Dd, Wk, bk, nullptr, nullptr, k, Mrows, Dd, Dd);
    gemm_bf16<EPI_NONE,1><<<dim3(Dd/64,   MY), 256, 0, s_attn>>>(x, Dd, Wv, bv, nullptr, nullptr, v, Mrows, Dd, Dd);
    attn_bf<<<dim3(LL/128, Hh, Bsz), 256, attn_smem, s_attn>>>(q, k, v, mask, attnO);
    gemm_bf16<EPI_NONE,0><<<dim3(Dd/64,   MY), 256, 0, s_attn>>>(attnO, Dd, Wo, bo, nullptr, nullptr, attn_out, Mrows, Dd, Dd);
    cudaEventRecord(e_join, s_attn);

    // mamba branch (stream 0)
    gemm_bf16<EPI_NONE,0><<<dim3(2*DI/64, MY), 256>>>(x, Dd, in_proj_w, nullptr, nullptr, nullptr, xz, Mrows, 2*DI, Dd);
    conv_silu_k<<<Mrows*DI/256, 256>>>(xz, conv_w, conv_b, uact);
    gemm_tf32<EPI_NONE><<<dim3(3,       MY), 256>>>(uact, DI, x_proj_w, nullptr, xdbc, Mrows, 160, DI);
    gemm_tf32<EPI_SOFTPLUS><<<dim3(DI/64, MY), 256>>>(xdbc, 160, dt_proj_w, dt_proj_b, delta, Mrows, DI, Rr);
    scan_gate_k<<<dim3(DI/16, Bsz), 512>>>(delta, uact, xdbc, A_log, xz, D_ssm, y);

    // ---- join, then out_proj with fused residual adds (hsum = xf + attn + mamba)
    cudaStreamWaitEvent(0, e_join, 0);
    gemm_bf16<EPI_ADD2,0><<<dim3(Dd/64,   MY), 256>>>(y, DI, out_proj_w, nullptr, x, attn_out, hsum, Mrows, Dd, DI);

    // double layernorm
    ln2_k<<<Mrows, 128>>>(hsum, ln1_g, ln1_b, ln2_g, ln2_b, h, hn);

    // FFN
    gemm_bf16<EPI_GELU,0><<<dim3(DFF/64, MY), 256>>>(hn, Dd, ffn_w1, ffn_b1, nullptr, nullptr, mid, Mrows, DFF, Dd);
    gemm_bf16<EPI_ADD,0><<<dim3(Dd/64,   MY), 256>>>(mid, DFF, ffn_w2, ffn_b2, h, nullptr, out, Mrows, Dd, DFF);
}

// round 13
// speedup vs baseline: 1.1649x; 1.0571x over previous
#include <cuda_runtime.h>
#include <cuda_bf16.h>
#include <math.h>

#define Bsz 8
#define Dd 512
#define Hh 8
#define Ee 64
#define DI 1024
#define Ss 64
#define Rr 32
#define DFF 2048
#define LL 1152
#define Mrows (Bsz*LL)   /* 9216 */

// ---------------- scratch (static __device__, no allocation) ----------------
__device__ __nv_bfloat16 g_q[Mrows*Dd];
__device__ __nv_bfloat16 g_k[Mrows*Dd];
__device__ __nv_bfloat16 g_v[Mrows*Dd];
__device__ __nv_bfloat16 g_attnO[Mrows*Dd];
__device__ float g_attn_out[Mrows*Dd];
__device__ float g_xz[Mrows*2*DI];
__device__ float g_uact[Mrows*DI];
__device__ float g_xdbc[Mrows*160];
__device__ float g_delta[Mrows*DI];
__device__ __nv_bfloat16 g_y[Mrows*DI];
__device__ float g_hsum[Mrows*Dd];
__device__ float g_h[Mrows*Dd];
__device__ __nv_bfloat16 g_hn[Mrows*Dd];
__device__ __nv_bfloat16 g_mid[Mrows*DFF];

enum { EPI_NONE = 0, EPI_SOFTPLUS = 1, EPI_GELU = 2, EPI_ADD = 3, EPI_ADD2 = 4 };

__device__ __forceinline__ unsigned f2tf32(float f)
{
    unsigned u;
    asm("cvt.rna.tf32.f32 %0, %1;" : "=r"(u) : "f"(f));
    return u;
}

__device__ __forceinline__ void mma_tf32(float* c, const unsigned* a, const unsigned* b)
{
    asm volatile(
        "mma.sync.aligned.m16n8k8.row.col.f32.tf32.tf32.f32 "
        "{%0,%1,%2,%3},{%4,%5,%6,%7},{%8,%9},{%0,%1,%2,%3};"
        : "+f"(c[0]), "+f"(c[1]), "+f"(c[2]), "+f"(c[3])
        : "r"(a[0]), "r"(a[1]), "r"(a[2]), "r"(a[3]), "r"(b[0]), "r"(b[1]));
}

__device__ __forceinline__ void mma_bf16(float* c, const unsigned* a, const unsigned* b)
{
    asm volatile(
        "mma.sync.aligned.m16n8k16.row.col.f32.bf16.bf16.f32 "
        "{%0,%1,%2,%3},{%4,%5,%6,%7},{%8,%9},{%0,%1,%2,%3};"
        : "+f"(c[0]), "+f"(c[1]), "+f"(c[2]), "+f"(c[3])
        : "r"(a[0]), "r"(a[1]), "r"(a[2]), "r"(a[3]), "r"(b[0]), "r"(b[1]));
}

__device__ __forceinline__ void ldsm4(unsigned* r, unsigned saddr)
{
    asm volatile("ldmatrix.sync.aligned.m8n8.x4.shared.b16 {%0,%1,%2,%3}, [%4];"
        : "=r"(r[0]), "=r"(r[1]), "=r"(r[2]), "=r"(r[3]) : "r"(saddr));
}

__device__ __forceinline__ void ldsm4t(unsigned* r, unsigned saddr)
{
    asm volatile("ldmatrix.sync.aligned.m8n8.x4.trans.shared.b16 {%0,%1,%2,%3}, [%4];"
        : "=r"(r[0]), "=r"(r[1]), "=r"(r[2]), "=r"(r[3]) : "r"(saddr));
}

__device__ __forceinline__ uint2 pack4(float4 f)
{
    __nv_bfloat162 p0 = __floats2bfloat162_rn(f.x, f.y);
    __nv_bfloat162 p1 = __floats2bfloat162_rn(f.z, f.w);
    uint2 u;
    u.x = *(unsigned*)&p0;
    u.y = *(unsigned*)&p1;
    return u;
}

__device__ __forceinline__ unsigned packbf2(float a, float b)
{
    __nv_bfloat162 p = __floats2bfloat162_rn(a, b);
    return *(unsigned*)&p;
}

__device__ __forceinline__ float epi_apply_scalar(int EPI, float v)
{
    if (EPI == EPI_SOFTPLUS) return (v > 20.f) ? v : log1pf(expf(v));
    if (EPI == EPI_GELU)     return 0.5f*v*(1.f + erff(v*0.7071067811865475f));
    return v;
}

// ====== bf16 tensor-core GEMM, 128x64 block tile: C = A(MxK) @ W(NxK)^T ======
// OBF=1: write bf16 output. ABF=1: A is already bf16 (K must be mult of 64).
template<int EPI, int OBF, int ABF>
__global__ __launch_bounds__(256) void gemm_bf16(
    const void* __restrict__ Av, int lda,
    const float* __restrict__ W,
    const float* __restrict__ bias,
    const float* __restrict__ add,
    const float* __restrict__ add2,
    void* __restrict__ Cv, int M, int N, int K)
{
    __shared__ __align__(16) char sm[2*16384 + 2*8192];
    char* AsP = sm;
    char* BsP = sm + 2*16384;
    const unsigned asU = (unsigned)__cvta_generic_to_shared(AsP);
    const unsigned bsU = (unsigned)__cvta_generic_to_shared(BsP);

    const int tid = threadIdx.x;
    const int lane = tid & 31, w = tid >> 5;
    const int warpM = w & 3, warpN = w >> 2;
    const int m0 = blockIdx.y * 128, n0 = blockIdx.x * 64;

    // ---- A staging maps ----
    // ABF==0: float4 per thread, 8 iters (rows stride 16)
    const int arow0 = tid >> 4;
    const int akq   = (tid & 15) * 4;
    const float* ApF = (const float*)Av + (size_t)(m0 + arow0) * lda + akq;
    const int aso0 = arow0*128 + (((akq >> 3) ^ (arow0 & 7)) << 4) + (akq & 7)*2;
    // ABF==1: uint4 (8 bf16) per thread, 4 iters (rows stride 32)
    const int hrow0 = tid >> 3;          // 0..31
    const int hg    = tid & 7;           // 0..7
    const __nv_bfloat16* ApH = (const __nv_bfloat16*)Av + (size_t)(m0 + hrow0) * lda + hg*8;
    const int hso0 = hrow0*128 + ((hg ^ (hrow0 & 7)) << 4);

    // ---- B staging ----
    const float* Bp = W + (size_t)(n0 + arow0) * K + akq;
    const int bso0 = aso0;
    bool bnv[4];
#pragma unroll
    for (int i = 0; i < 4; i++) bnv[i] = (n0 + arow0 + 16*i) < N;

    const int lr = (lane & 7) + ((lane >> 3) & 1) * 8;
    const int ko = (lane >> 4);
    int rA[2], mA[2];
#pragma unroll
    for (int mi = 0; mi < 2; mi++) {
        int r = warpM*32 + mi*16 + lr;
        rA[mi] = r * 128; mA[mi] = r & 7;
    }
    int rB[2], mB[2];
#pragma unroll
    for (int nh = 0; nh < 2; nh++) {
        int r = warpN*32 + nh*16 + lr;
        rB[nh] = r * 128; mB[nh] = r & 7;
    }

    float acc[2][4][4];
#pragma unroll
    for (int mi = 0; mi < 2; mi++)
#pragma unroll
        for (int nf = 0; nf < 4; nf++)
#pragma unroll
            for (int j = 0; j < 4; j++) acc[mi][nf][j] = 0.f;

    const int nk = (K + 63) >> 6;
    float4 ar[8], br[4];
    uint4 arh[4];

    {
        const bool av = akq < K;
        if (ABF) {
#pragma unroll
            for (int i = 0; i < 4; i++) arh[i] = *(const uint4*)(ApH + (size_t)i*32*lda);
        } else {
#pragma unroll
            for (int i = 0; i < 8; i++)
                ar[i] = av ? *(const float4*)(ApF + (size_t)i*16*lda) : make_float4(0.f,0.f,0.f,0.f);
        }
#pragma unroll
        for (int i = 0; i < 4; i++)
            br[i] = (bnv[i] && av) ? *(const float4*)(Bp + (size_t)i*16*K) : make_float4(0.f,0.f,0.f,0.f);
        if (ABF) {
#pragma unroll
            for (int i = 0; i < 4; i++) *(uint4*)(AsP + hso0 + i*4096) = arh[i];
        } else {
#pragma unroll
            for (int i = 0; i < 8; i++) *(uint2*)(AsP + aso0 + i*2048) = pack4(ar[i]);
        }
#pragma unroll
        for (int i = 0; i < 4; i++) *(uint2*)(BsP + bso0 + i*2048) = pack4(br[i]);
    }
    __syncthreads();

    for (int kt = 0; kt < nk; kt++) {
        const int cur = kt & 1;
        const bool more = (kt + 1) < nk;
        if (more) {
            const int kof = (kt + 1) << 6;
            const bool av = (akq + kof) < K;
            if (ABF) {
#pragma unroll
                for (int i = 0; i < 4; i++) arh[i] = *(const uint4*)(ApH + kof + (size_t)i*32*lda);
            } else {
#pragma unroll
                for (int i = 0; i < 8; i++)
                    ar[i] = av ? *(const float4*)(ApF + kof + (size_t)i*16*lda) : make_float4(0.f,0.f,0.f,0.f);
            }
#pragma unroll
            for (int i = 0; i < 4; i++)
                br[i] = (bnv[i] && av) ? *(const float4*)(Bp + kof + (size_t)i*16*K) : make_float4(0.f,0.f,0.f,0.f);
        }

        const unsigned aB = asU + cur*16384;
        const unsigned bB = bsU + cur*8192;
#pragma unroll
        for (int ks = 0; ks < 4; ks++) {
            const int kx = 2*ks + ko;
            unsigned afr[2][4], bfr[2][4];
#pragma unroll
            for (int mi = 0; mi < 2; mi++)
                ldsm4(afr[mi], aB + rA[mi] + ((kx ^ mA[mi]) << 4));
#pragma unroll
            for (int nh = 0; nh < 2; nh++)
                ldsm4(bfr[nh], bB + rB[nh] + ((kx ^ mB[nh]) << 4));
#pragma unroll
            for (int mi = 0; mi < 2; mi++) {
                unsigned b0[2] = {bfr[0][0], bfr[0][2]};
                unsigned b1[2] = {bfr[0][1], bfr[0][3]};
                unsigned b2[2] = {bfr[1][0], bfr[1][2]};
                unsigned b3[2] = {bfr[1][1], bfr[1][3]};
                mma_bf16(acc[mi][0], afr[mi], b0);
                mma_bf16(acc[mi][1], afr[mi], b1);
                mma_bf16(acc[mi][2], afr[mi], b2);
                mma_bf16(acc[mi][3], afr[mi], b3);
            }
        }

        if (more) {
            const int nxt = cur ^ 1;
            if (ABF) {
#pragma unroll
                for (int i = 0; i < 4; i++) *(uint4*)(AsP + nxt*16384 + hso0 + i*4096) = arh[i];
            } else {
#pragma unroll
                for (int i = 0; i < 8; i++) *(uint2*)(AsP + nxt*16384 + aso0 + i*2048) = pack4(ar[i]);
            }
#pragma unroll
            for (int i = 0; i < 4; i++) *(uint2*)(BsP + nxt*8192  + bso0 + i*2048) = pack4(br[i]);
            __syncthreads();
        }
    }

#pragma unroll
    for (int mi = 0; mi < 2; mi++) {
#pragma unroll
        for (int nf = 0; nf < 4; nf++) {
            int row = m0 + warpM*32 + mi*16 + (lane >> 2);
            int col = n0 + warpN*32 + nf*8 + (lane & 3)*2;
            if (col < N) {
                float v00 = acc[mi][nf][0], v01 = acc[mi][nf][1];
                float v10 = acc[mi][nf][2], v11 = acc[mi][nf][3];
                if (bias) {
                    float b0 = bias[col], b1 = bias[col+1];
                    v00 += b0; v01 += b1; v10 += b0; v11 += b1;
                }
                if (EPI == EPI_ADD || EPI == EPI_ADD2) {
                    const float* ap0 = add + (size_t)row * N + col;
                    const float* ap1 = add + (size_t)(row+8) * N + col;
                    v00 += ap0[0]; v01 += ap0[1]; v10 += ap1[0]; v11 += ap1[1];
                    if (EPI == EPI_ADD2) {
                        const float* bp0 = add2 + (size_t)row * N + col;
                        const float* bp1 = add2 + (size_t)(row+8) * N + col;
                        v00 += bp0[0]; v01 += bp0[1]; v10 += bp1[0]; v11 += bp1[1];
                    }
                } else {
                    v00 = epi_apply_scalar(EPI, v00); v01 = epi_apply_scalar(EPI, v01);
                    v10 = epi_apply_scalar(EPI, v10); v11 = epi_apply_scalar(EPI, v11);
                }
                if (OBF) {
                    __nv_bfloat16* C16 = (__nv_bfloat16*)Cv;
                    *(unsigned*)&C16[(size_t)row * N + col]     = packbf2(v00, v01);
                    *(unsigned*)&C16[(size_t)(row+8) * N + col] = packbf2(v10, v11);
                } else {
                    float* C = (float*)Cv;
                    *(float2*)&C[(size_t)row * N + col]     = make_float2(v00, v01);
                    *(float2*)&C[(size_t)(row+8) * N + col] = make_float2(v10, v11);
                }
            }
        }
    }
}

// ================= tf32 tensor-core GEMM (scan-sensitive projections) ========
template<int EPI>
__global__ __launch_bounds__(256) void gemm_tf32(
    const float* __restrict__ A, int lda,
    const float* __restrict__ W,
    const float* __restrict__ bias,
    float* __restrict__ C, int M, int N, int K)
{
    __shared__ __align__(16) unsigned As[2][128*32];
    __shared__ __align__(16) unsigned Bs[2][64*32];

    const int t = threadIdx.x;
    const int m0 = blockIdx.y * 128, n0 = blockIdx.x * 64;
    const int lane = t & 31, w = t >> 5;
    const int warpM = w & 3, warpN = w >> 2;
    const int s = lane >> 2, off = lane & 3;

    const float* aptr[4]; int aso[4];
#pragma unroll
    for (int i = 0; i < 4; i++) {
        int e = t + i*256;
        int m = e >> 3, g = e & 7;
        aptr[i] = A + (size_t)(m0 + m) * lda + g*4;
        aso[i]  = m*32 + ((g ^ (m & 7)) << 2);
    }
    const float* bptr[2]; int bso[2]; bool bval[2];
#pragma unroll
    for (int i = 0; i < 2; i++) {
        int e = t + i*256;
        int n = e >> 3, g = e & 7;
        bval[i] = (n0 + n) < N;
        bptr[i] = W + (size_t)(n0 + n) * K + g*4;
        bso[i]  = n*32 + ((g ^ (n & 7)) << 2);
    }

    float acc[2][4][4];
#pragma unroll
    for (int mi = 0; mi < 2; mi++)
#pragma unroll
        for (int ni = 0; ni < 4; ni++)
#pragma unroll
            for (int j = 0; j < 4; j++) acc[mi][ni][j] = 0.f;

    const int nk = K >> 5;
    float4 ar[4], br[2];

#pragma unroll
    for (int i = 0; i < 4; i++) ar[i] = *(const float4*)(aptr[i]);
#pragma unroll
    for (int i = 0; i < 2; i++)
        br[i] = bval[i] ? *(const float4*)(bptr[i]) : make_float4(0.f,0.f,0.f,0.f);
#pragma unroll
    for (int i = 0; i < 4; i++)
        *(uint4*)&As[0][aso[i]] = make_uint4(f2tf32(ar[i].x), f2tf32(ar[i].y), f2tf32(ar[i].z), f2tf32(ar[i].w));
#pragma unroll
    for (int i = 0; i < 2; i++)
        *(uint4*)&Bs[0][bso[i]] = make_uint4(f2tf32(br[i].x), f2tf32(br[i].y), f2tf32(br[i].z), f2tf32(br[i].w));
    __syncthreads();

    for (int kt = 0; kt < nk; kt++) {
        const int cur = kt & 1, nxt = cur ^ 1;
        const bool more = (kt + 1) < nk;
        if (more) {
            const int ko = (kt + 1) * 32;
#pragma unroll
            for (int i = 0; i < 4; i++) ar[i] = *(const float4*)(aptr[i] + ko);
#pragma unroll
            for (int i = 0; i < 2; i++)
                br[i] = bval[i] ? *(const float4*)(bptr[i] + ko) : make_float4(0.f,0.f,0.f,0.f);
        }

#pragma unroll
        for (int ks = 0; ks < 4; ks++) {
            const int x0 = (((ks*2)     ^ s) << 2) + off;
            const int x1 = (((ks*2 + 1) ^ s) << 2) + off;
            unsigned a[2][4];
#pragma unroll
            for (int mi = 0; mi < 2; mi++) {
                int r = (warpM*32 + mi*16 + s) * 32;
                a[mi][0] = As[cur][r + x0];
                a[mi][1] = As[cur][r + 256 + x0];
                a[mi][2] = As[cur][r + x1];
                a[mi][3] = As[cur][r + 256 + x1];
            }
            unsigned b[4][2];
#pragma unroll
            for (int ni = 0; ni < 4; ni++) {
                int rb = (warpN*32 + ni*8 + s) * 32;
                b[ni][0] = Bs[cur][rb + x0];
                b[ni][1] = Bs[cur][rb + x1];
            }
#pragma unroll
            for (int mi = 0; mi < 2; mi++)
#pragma unroll
                for (int ni = 0; ni < 4; ni++)
                    mma_tf32(acc[mi][ni], a[mi], b[ni]);
        }

        if (more) {
#pragma unroll
            for (int i = 0; i < 4; i++)
                *(uint4*)&As[nxt][aso[i]] = make_uint4(f2tf32(ar[i].x), f2tf32(ar[i].y), f2tf32(ar[i].z), f2tf32(ar[i].w));
#pragma unroll
            for (int i = 0; i < 2; i++)
                *(uint4*)&Bs[nxt][bso[i]] = make_uint4(f2tf32(br[i].x), f2tf32(br[i].y), f2tf32(br[i].z), f2tf32(br[i].w));
            __syncthreads();
        }
    }

#pragma unroll
    for (int mi = 0; mi < 2; mi++) {
#pragma unroll
        for (int ni = 0; ni < 4; ni++) {
            int row = m0 + warpM*32 + mi*16 + s;
            int col = n0 + warpN*32 + ni*8 + off*2;
            if (col < N) {
                float v00 = acc[mi][ni][0], v01 = acc[mi][ni][1];
                float v10 = acc[mi][ni][2], v11 = acc[mi][ni][3];
                if (bias) {
                    float b0 = bias[col], b1 = bias[col+1];
                    v00 += b0; v01 += b1; v10 += b0; v11 += b1;
                }
                v00 = epi_apply_scalar(EPI, v00); v01 = epi_apply_scalar(EPI, v01);
                v10 = epi_apply_scalar(EPI, v10); v11 = epi_apply_scalar(EPI, v11);
                *(float2*)&C[(size_t)row * N + col]     = make_float2(v00, v01);
                *(float2*)&C[(size_t)(row+8) * N + col] = make_float2(v10, v11);
            }
        }
    }
}

// ============== bf16 tensor-core flash attention (ldmatrix) ==================
__global__ __launch_bounds__(256, 2) void attn_bf(
    const __nv_bfloat16* __restrict__ q, const __nv_bfloat16* __restrict__ k,
    const __nv_bfloat16* __restrict__ v, const unsigned char* __restrict__ mask,
    __nv_bfloat16* __restrict__ o)
{
    extern __shared__ __align__(16) char smA[];
    char* sQ = smA;                  // 16384
    char* sK = smA + 16384;          // 8192
    char* sV = smA + 24576;          // 8192
    const int tid = threadIdx.x;
    const int lane = tid & 31, w = tid >> 5;
    char* sP = smA + 32768 + w*2048; // per-warp 2048
    const unsigned uQ = (unsigned)__cvta_generic_to_shared(sQ);
    const unsigned uK = (unsigned)__cvta_generic_to_shared(sK);
    const unsigned uV = (unsigned)__cvta_generic_to_shared(sV);
    const unsigned uP = (unsigned)__cvta_generic_to_shared(sP);

    const int qt = blockIdx.x, h = blockIdx.y, b = blockIdx.z;
    const size_t bL = (size_t)b * LL;
    const int qr = qt * 128;

    const int lr = (lane & 7) + ((lane >> 3) & 1) * 8;
    const int ko = lane >> 4;
    const int s = lane >> 2, off = lane & 3;

    // stage Q tile (128 rows x 64 bf16, SW128 swizzle)
#pragma unroll
    for (int i = 0; i < 4; i++) {
        int u = tid + i*256;
        int row = u >> 3, g = u & 7;
        uint4 val = *(const uint4*)&q[(bL + qr + row) * Dd + h*Ee + g*8];
        *(uint4*)(sQ + row*128 + ((g ^ (row & 7)) << 4)) = val;
    }
    __syncthreads();

    unsigned qa[4][4];
    {
        int r = w*16 + lr;
        unsigned base = uQ + r*128;
#pragma unroll
        for (int ks = 0; ks < 4; ks++)
            ldsm4(qa[ks], base + (((2*ks + ko) ^ (r & 7)) << 4));
    }

    float oa[8][4];
#pragma unroll
    for (int et = 0; et < 8; et++)
#pragma unroll
        for (int j = 0; j < 4; j++) oa[et][j] = 0.f;
    float m0v = -INFINITY, m1v = -INFINITY, l0v = 0.f, l1v = 0.f;

    for (int n0k = 0; n0k < LL; n0k += 64) {
        __syncthreads();
#pragma unroll
        for (int i = 0; i < 2; i++) {
            int u = tid + i*256;
            int row = u >> 3, g = u & 7;
            size_t gr = (bL + n0k + row) * Dd + h*Ee + g*8;
            int so = row*128 + ((g ^ (row & 7)) << 4);
            *(uint4*)(sK + so) = *(const uint4*)&k[gr];
            *(uint4*)(sV + so) = *(const uint4*)&v[gr];
        }
        __syncthreads();

        float sa[8][4];
#pragma unroll
        for (int nt = 0; nt < 8; nt++)
#pragma unroll
            for (int j = 0; j < 4; j++) sa[nt][j] = 0.f;
#pragma unroll
        for (int ks = 0; ks < 4; ks++) {
#pragma unroll
            for (int nb = 0; nb < 4; nb++) {
                unsigned bfr[4];
                int r = nb*16 + lr;
                ldsm4(bfr, uK + r*128 + (((2*ks + ko) ^ (r & 7)) << 4));
                unsigned b0[2] = {bfr[0], bfr[2]};
                unsigned b1[2] = {bfr[1], bfr[3]};
                mma_bf16(sa[nb*2],     qa[ks], b0);
                mma_bf16(sa[nb*2 + 1], qa[ks], b1);
            }
        }

        float rmax0 = -INFINITY, rmax1 = -INFINITY;
#pragma unroll
        for (int nt = 0; nt < 8; nt++) {
            sa[nt][0] *= 0.125f; sa[nt][1] *= 0.125f;
            sa[nt][2] *= 0.125f; sa[nt][3] *= 0.125f;
            unsigned char mk0 = mask[bL + n0k + nt*8 + off*2];
            unsigned char mk1 = mask[bL + n0k + nt*8 + off*2 + 1];
            if (mk0) { sa[nt][0] = -INFINITY; sa[nt][2] = -INFINITY; }
            if (mk1) { sa[nt][1] = -INFINITY; sa[nt][3] = -INFINITY; }
            rmax0 = fmaxf(rmax0, fmaxf(sa[nt][0], sa[nt][1]));
            rmax1 = fmaxf(rmax1, fmaxf(sa[nt][2], sa[nt][3]));
        }
        rmax0 = fmaxf(rmax0, __shfl_xor_sync(0xffffffffu, rmax0, 1));
        rmax0 = fmaxf(rmax0, __shfl_xor_sync(0xffffffffu, rmax0, 2));
        rmax1 = fmaxf(rmax1, __shfl_xor_sync(0xffffffffu, rmax1, 1));
        rmax1 = fmaxf(rmax1, __shfl_xor_sync(0xffffffffu, rmax1, 2));
        float mn0 = fmaxf(m0v, rmax0), mn1 = fmaxf(m1v, rmax1);
        float c0 = __expf(m0v - mn0), c1 = __expf(m1v - mn1);
        float rs0 = 0.f, rs1 = 0.f;
#pragma unroll
        for (int nt = 0; nt < 8; nt++) {
            float p0 = __expf(sa[nt][0] - mn0);
            float p1 = __expf(sa[nt][1] - mn0);
            float p2 = __expf(sa[nt][2] - mn1);
            float p3 = __expf(sa[nt][3] - mn1);
            rs0 += p0 + p1; rs1 += p2 + p3;
            *(unsigned*)(sP + s*128       + ((nt ^ (s & 7)) << 4) + off*4) = packbf2(p0, p1);
            *(unsigned*)(sP + (s+8)*128   + ((nt ^ (s & 7)) << 4) + off*4) = packbf2(p2, p3);
        }
        rs0 += __shfl_xor_sync(0xffffffffu, rs0, 1);
        rs0 += __shfl_xor_sync(0xffffffffu, rs0, 2);
        rs1 += __shfl_xor_sync(0xffffffffu, rs1, 1);
        rs1 += __shfl_xor_sync(0xffffffffu, rs1, 2);
        l0v = l0v * c0 + rs0; l1v = l1v * c1 + rs1;
        m0v = mn0; m1v = mn1;
#pragma unroll
        for (int et = 0; et < 8; et++) {
            oa[et][0] *= c0; oa[et][1] *= c0;
            oa[et][2] *= c1; oa[et][3] *= c1;
        }
        __syncwarp();

#pragma unroll
        for (int ksp = 0; ksp < 4; ksp++) {
            unsigned pa[4];
            {
                int r = lr;
                ldsm4(pa, uP + r*128 + (((2*ksp + ko) ^ (r & 7)) << 4));
            }
            int key = ksp*16 + lr;
#pragma unroll
            for (int j = 0; j < 4; j++) {
                unsigned vfr[4];
                ldsm4t(vfr, uV + key*128 + (((2*j + ko) ^ (key & 7)) << 4));
                unsigned be0[2] = {vfr[0], vfr[1]};
                unsigned be1[2] = {vfr[2], vfr[3]};
                mma_bf16(oa[j*2],     pa, be0);
                mma_bf16(oa[j*2 + 1], pa, be1);
            }
        }
    }

    float inv0 = 1.f / l0v, inv1 = 1.f / l1v;
#pragma unroll
    for (int et = 0; et < 8; et++) {
        size_t r0 = (bL + qr + w*16 + s    ) * Dd + h*Ee + et*8 + off*2;
        size_t r1 = (bL + qr + w*16 + s + 8) * Dd + h*Ee + et*8 + off*2;
        *(unsigned*)&o[r0] = packbf2(oa[et][0]*inv0, oa[et][1]*inv0);
        *(unsigned*)&o[r1] = packbf2(oa[et][2]*inv1, oa[et][3]*inv1);
    }
}

// ---------------- causal depthwise conv (KC=4) + SiLU ------------------------
__global__ void conv_silu_k(const float* __restrict__ xz,
                            const float* __restrict__ cw,
                            const float* __restrict__ cb,
                            float* __restrict__ uact)
{
    int idx = blockIdx.x * 256 + threadIdx.x;
    int r = idx >> 10;
    int j = idx & 1023;
    int t = r % LL;
    float acc = cb[j];
#pragma unroll
    for (int kk = 0; kk < 4; kk++) {
        int tt = t + kk - 3;
        if (tt >= 0)
            acc = fmaf(xz[(size_t)(r + kk - 3) * (2*DI) + j], cw[j*4 + kk], acc);
    }
    uact[idx] = acc / (1.f + expf(-acc));
}

// -------- selective scan + fused gate: 1 warp per (b,d), 2 states/lane -------
__global__ __launch_bounds__(512) void scan_gate_k(
    const float* __restrict__ delta, const float* __restrict__ uact,
    const float* __restrict__ xdbc, const float* __restrict__ A_log,
    const float* __restrict__ xz,   const float* __restrict__ Dssm,
    __nv_bfloat16* __restrict__ y)
{
    __shared__ float sB[16][64];
    __shared__ float sC[16][64];
    __shared__ float sdt[16][16];
    __shared__ float su[16][16];
    __shared__ float sz[16][16];
    __shared__ float spw[16][16][33];

    int b = blockIdx.y;
    int d0 = blockIdx.x * 16;
    int tid = threadIdx.x;
    int w = tid >> 5, l = tid & 31;
    int d = d0 + w;
    float a0 = -expf(A_log[d*Ss + l]);
    float a1 = -expf(A_log[d*Ss + l + 32]);
    float dD = Dssm[d];
    float h0 = 0.f, h1 = 0.f;
    size_t base = (size_t)b * LL;

    const int rr = l >> 1;
    const int half = l & 1;

    for (int t0 = 0; t0 < LL; t0 += 16) {
        __syncthreads();
        for (int i = tid; i < 2048; i += 512) {
            int tt = i >> 7, c = i & 127;
            float val = xdbc[(base + t0 + tt) * 160 + 32 + c];
            if (c < 64) sB[tt][c] = val; else sC[tt][c - 64] = val;
        }
        for (int i = tid; i < 768; i += 512) {
            int sel = i >> 8;
            int e = i & 255;
            int tt = e >> 4, c = e & 15;
            size_t row = base + t0 + tt;
            if (sel == 0)      sdt[tt][c] = delta[row * DI + d0 + c];
            else if (sel == 1) su[tt][c]  = uact [row * DI + d0 + c];
            else               sz[tt][c]  = xz[row * (2*DI) + DI + d0 + c];
        }
        __syncthreads();

#pragma unroll 4
        for (int tt = 0; tt < 16; tt++) {
            float dt  = sdt[tt][w];
            float dtu = dt * su[tt][w];
            float dA0 = __expf(dt * a0);
            float dA1 = __expf(dt * a1);
            h0 = fmaf(h0, dA0, dtu * sB[tt][l]);
            h1 = fmaf(h1, dA1, dtu * sB[tt][l + 32]);
            spw[w][tt][l] = fmaf(h1, sC[tt][l + 32], h0 * sC[tt][l]);
        }
        __syncwarp();

        float accv = 0.f;
#pragma unroll
        for (int i = 0; i < 16; i++) accv += spw[w][rr][half*16 + i];
        accv += __shfl_xor_sync(0xffffffffu, accv, 1);
        if (half == 0) {
            float uu = su[rr][w];
            float zz = sz[rr][w];
            float yv = fmaf(uu, dD, accv);
            y[(base + t0 + rr) * DI + d] = __float2bfloat16(yv * (zz / (1.f + __expf(-zz))));
        }
    }
}

// ---------------- double LayerNorm on pre-summed residual --------------------
__device__ __forceinline__ float blockSum128(float v, float* sm)
{
#pragma unroll
    for (int offx = 16; offx > 0; offx >>= 1)
        v += __shfl_xor_sync(0xffffffffu, v, offx);
    if ((threadIdx.x & 31) == 0) sm[threadIdx.x >> 5] = v;
    __syncthreads();
    float r = sm[0] + sm[1] + sm[2] + sm[3];
    __syncthreads();
    return r;
}

__global__ __launch_bounds__(128) void ln2_k(
    const float* __restrict__ hsum,
    const float* __restrict__ g1, const float* __restrict__ b1,
    const float* __restrict__ g2, const float* __restrict__ b2,
    float* __restrict__ h, __nv_bfloat16* __restrict__ hn)
{
    __shared__ float sm[4];
    int r = blockIdx.x, tid = threadIdx.x;
    size_t base = (size_t)r * Dd;
    float vv[4];
#pragma unroll
    for (int i = 0; i < 4; i++) vv[i] = hsum[base + tid + i*128];
    float s = vv[0] + vv[1] + vv[2] + vv[3];
    float mean = blockSum128(s, sm) * (1.f/512.f);
    float sq = 0.f;
#pragma unroll
    for (int i = 0; i < 4; i++) { float dd = vv[i] - mean; sq = fmaf(dd, dd, sq); }
    float var = blockSum128(sq, sm) * (1.f/512.f);
    float inv = rsqrtf(var + 1e-5f);
    float hv[4];
#pragma unroll
    for (int i = 0; i < 4; i++) {
        int c = tid + i*128;
        hv[i] = (vv[i] - mean) * inv * g1[c] + b1[c];
        h[base+c] = hv[i];
    }
    float s2 = hv[0] + hv[1] + hv[2] + hv[3];
    float mean2 = blockSum128(s2, sm) * (1.f/512.f);
    float sq2 = 0.f;
#pragma unroll
    for (int i = 0; i < 4; i++) { float dd = hv[i] - mean2; sq2 = fmaf(dd, dd, sq2); }
    float var2 = blockSum128(sq2, sm) * (1.f/512.f);
    float inv2 = rsqrtf(var2 + 1e-6f);
#pragma unroll
    for (int i = 0; i < 4; i++) {
        int c = tid + i*128;
        hn[base+c] = __float2bfloat16((hv[i] - mean2) * inv2 * g2[c] + b2[c]);
    }
}

// ---------------- launch -----------------------------------------------------
extern "C" void kernel_launch(void* const* d_in, const int* in_sizes, int n_in,
                              void* d_out, int out_size)
{
    const float* x            = (const float*)d_in[0];
    const unsigned char* mask = (const unsigned char*)d_in[1];
    const float* Wq = (const float*)d_in[2];   const float* bq = (const float*)d_in[3];
    const float* Wk = (const float*)d_in[4];   const float* bk = (const float*)d_in[5];
    const float* Wv = (const float*)d_in[6];   const float* bv = (const float*)d_in[7];
    const float* Wo = (const float*)d_in[8];   const float* bo = (const float*)d_in[9];
    const float* in_proj_w = (const float*)d_in[10];
    const float* conv_w    = (const float*)d_in[11];
    const float* conv_b    = (const float*)d_in[12];
    const float* x_proj_w  = (const float*)d_in[13];
    const float* dt_proj_w = (const float*)d_in[14];
    const float* dt_proj_b = (const float*)d_in[15];
    const float* A_log     = (const float*)d_in[16];
    const float* D_ssm     = (const float*)d_in[17];
    const float* out_proj_w= (const float*)d_in[18];
    const float* ln1_g = (const float*)d_in[19]; const float* ln1_b = (const float*)d_in[20];
    const float* ffn_w1= (const float*)d_in[21]; const float* ffn_b1= (const float*)d_in[22];
    const float* ffn_w2= (const float*)d_in[23]; const float* ffn_b2= (const float*)d_in[24];
    const float* ln2_g = (const float*)d_in[25]; const float* ln2_b = (const float*)d_in[26];
    float* out = (float*)d_out;

    __nv_bfloat16 *q, *k, *v, *attnO, *y, *hn, *mid;
    float *attn_out,*xz,*uact,*xdbc,*delta,*hsum,*h;
    cudaGetSymbolAddress((void**)&q,        g_q);
    cudaGetSymbolAddress((void**)&k,        g_k);
    cudaGetSymbolAddress((void**)&v,        g_v);
    cudaGetSymbolAddress((void**)&attnO,    g_attnO);
    cudaGetSymbolAddress((void**)&attn_out, g_attn_out);
    cudaGetSymbolAddress((void**)&xz,       g_xz);
    cudaGetSymbolAddress((void**)&uact,     g_uact);
    cudaGetSymbolAddress((void**)&xdbc,     g_xdbc);
    cudaGetSymbolAddress((void**)&delta,    g_delta);
    cudaGetSymbolAddress((void**)&y,        g_y);
    cudaGetSymbolAddress((void**)&hsum,     g_hsum);
    cudaGetSymbolAddress((void**)&h,        g_h);
    cudaGetSymbolAddress((void**)&hn,       g_hn);
    cudaGetSymbolAddress((void**)&mid,      g_mid);

    static cudaStream_t s_attn = nullptr;
    static cudaEvent_t  e_fork = nullptr, e_join = nullptr;
    if (s_attn == nullptr) {
        cudaStreamCreateWithFlags(&s_attn, cudaStreamNonBlocking);
        cudaEventCreateWithFlags(&e_fork, cudaEventDisableTiming);
        cudaEventCreateWithFlags(&e_join, cudaEventDisableTiming);
    }

    const int MY = Mrows / 128;   // 72
    const int attn_smem = 32768 + 8*2048;   // 49152 bytes
    cudaFuncSetAttribute(attn_bf, cudaFuncAttributeMaxDynamicSharedMemorySize, attn_smem);

    // ---- fork: attention branch on s_attn, mamba branch on stream 0 ----
    cudaEventRecord(e_fork, 0);
    cudaStreamWaitEvent(s_attn, e_fork, 0);

    // attention branch (s_attn)
    gemm_bf16<EPI_NONE,1,0><<<dim3(Dd/64,   MY), 256, 0, s_attn>>>(x, Dd, Wq, bq, nullptr, nullptr, q, Mrows, Dd, Dd);
    gemm_bf16<EPI_NONE,1,0><<<dim3(Dd/64,   MY), 256, 0, s_attn>>>(x, Dd, Wk, bk, nullptr, nullptr, k, Mrows, Dd, Dd);
    gemm_bf16<EPI_NONE,1,0><<<dim3(Dd/64,   MY), 256, 0, s_attn>>>(x, Dd, Wv, bv, nullptr, nullptr, v, Mrows, Dd, Dd);
    attn_bf<<<dim3(LL/128, Hh, Bsz), 256, attn_smem, s_attn>>>(q, k, v, mask, attnO);
    gemm_bf16<EPI_NONE,0,1><<<dim3(Dd/64,   MY), 256, 0, s_attn>>>(attnO, Dd, Wo, bo, nullptr, nullptr, attn_out, Mrows, Dd, Dd);
    cudaEventRecord(e_join, s_attn);

    // mamba branch (stream 0)
    gemm_bf16<EPI_NONE,0,0><<<dim3(2*DI/64, MY), 256>>>(x, Dd, in_proj_w, nullptr, nullptr, nullptr, xz, Mrows, 2*DI, Dd);
    conv_silu_k<<<Mrows*DI/256, 256>>>(xz, conv_w, conv_b, uact);
    gemm_tf32<EPI_NONE><<<dim3(3,       MY), 256>>>(uact, DI, x_proj_w, nullptr, xdbc, Mrows, 160, DI);
    gemm_tf32<EPI_SOFTPLUS><<<dim3(DI/64, MY), 256>>>(xdbc, 160, dt_proj_w, dt_proj_b, delta, Mrows, DI, Rr);
    scan_gate_k<<<dim3(DI/16, Bsz), 512>>>(delta, uact, xdbc, A_log, xz, D_ssm, y);

    // ---- join, then out_proj with fused residual adds (hsum = xf + attn + mamba)
    cudaStreamWaitEvent(0, e_join, 0);
    gemm_bf16<EPI_ADD2,0,1><<<dim3(Dd/64,   MY), 256>>>(y, DI, out_proj_w, nullptr, x, attn_out, hsum, Mrows, Dd, DI);

    // double layernorm
    ln2_k<<<Mrows, 128>>>(hsum, ln1_g, ln1_b, ln2_g, ln2_b, h, hn);

    // FFN
    gemm_bf16<EPI_GELU,1,1><<<dim3(DFF/64, MY), 256>>>(hn, Dd, ffn_w1, ffn_b1, nullptr, nullptr, mid, Mrows, DFF, Dd);
    gemm_bf16<EPI_ADD,0,1><<<dim3(Dd/64,   MY), 256>>>(mid, DFF, ffn_w2, ffn_b2, h, nullptr, out, Mrows, Dd, DFF);
}

// round 15
// speedup vs baseline: 1.1936x; 1.0247x over previous
#include <cuda_runtime.h>
#include <cuda_bf16.h>
#include <math.h>

#define Bsz 8
#define Dd 512
#define Hh 8
#define Ee 64
#define DI 1024
#define Ss 64
#define Rr 32
#define DFF 2048
#define LL 1152
#define Mrows (Bsz*LL)   /* 9216 */

// ---------------- scratch (static __device__, no allocation) ----------------
__device__ __nv_bfloat16 g_xbf[Mrows*Dd];
__device__ __nv_bfloat16 g_wq[Dd*Dd];
__device__ __nv_bfloat16 g_wk[Dd*Dd];
__device__ __nv_bfloat16 g_wv[Dd*Dd];
__device__ __nv_bfloat16 g_wo[Dd*Dd];
__device__ __nv_bfloat16 g_win[2*DI*Dd];
__device__ __nv_bfloat16 g_wout[Dd*DI];
__device__ __nv_bfloat16 g_wf1[DFF*Dd];
__device__ __nv_bfloat16 g_wf2[Dd*DFF];
__device__ __nv_bfloat16 g_q[Mrows*Dd];
__device__ __nv_bfloat16 g_k[Mrows*Dd];
__device__ __nv_bfloat16 g_v[Mrows*Dd];
__device__ __nv_bfloat16 g_attnO[Mrows*Dd];
__device__ float g_attn_out[Mrows*Dd];
__device__ float g_xz[Mrows*2*DI];
__device__ float g_uact[Mrows*DI];
__device__ float g_xdbc[Mrows*160];
__device__ float g_delta[Mrows*DI];
__device__ __nv_bfloat16 g_y[Mrows*DI];
__device__ float g_hsum[Mrows*Dd];
__device__ float g_h[Mrows*Dd];
__device__ __nv_bfloat16 g_hn[Mrows*Dd];
__device__ __nv_bfloat16 g_mid[Mrows*DFF];

enum { EPI_NONE = 0, EPI_SOFTPLUS = 1, EPI_GELU = 2, EPI_ADD = 3, EPI_ADD2 = 4 };

__device__ __forceinline__ unsigned f2tf32(float f)
{
    unsigned u;
    asm("cvt.rna.tf32.f32 %0, %1;" : "=r"(u) : "f"(f));
    return u;
}

__device__ __forceinline__ void mma_tf32(float* c, const unsigned* a, const unsigned* b)
{
    asm volatile(
        "mma.sync.aligned.m16n8k8.row.col.f32.tf32.tf32.f32 "
        "{%0,%1,%2,%3},{%4,%5,%6,%7},{%8,%9},{%0,%1,%2,%3};"
        : "+f"(c[0]), "+f"(c[1]), "+f"(c[2]), "+f"(c[3])
        : "r"(a[0]), "r"(a[1]), "r"(a[2]), "r"(a[3]), "r"(b[0]), "r"(b[1]));
}

__device__ __forceinline__ void mma_bf16(float* c, const unsigned* a, const unsigned* b)
{
    asm volatile(
        "mma.sync.aligned.m16n8k16.row.col.f32.bf16.bf16.f32 "
        "{%0,%1,%2,%3},{%4,%5,%6,%7},{%8,%9},{%0,%1,%2,%3};"
        : "+f"(c[0]), "+f"(c[1]), "+f"(c[2]), "+f"(c[3])
        : "r"(a[0]), "r"(a[1]), "r"(a[2]), "r"(a[3]), "r"(b[0]), "r"(b[1]));
}

__device__ __forceinline__ void ldsm4(unsigned* r, unsigned saddr)
{
    asm volatile("ldmatrix.sync.aligned.m8n8.x4.shared.b16 {%0,%1,%2,%3}, [%4];"
        : "=r"(r[0]), "=r"(r[1]), "=r"(r[2]), "=r"(r[3]) : "r"(saddr));
}

__device__ __forceinline__ void ldsm4t(unsigned* r, unsigned saddr)
{
    asm volatile("ldmatrix.sync.aligned.m8n8.x4.trans.shared.b16 {%0,%1,%2,%3}, [%4];"
        : "=r"(r[0]), "=r"(r[1]), "=r"(r[2]), "=r"(r[3]) : "r"(saddr));
}

__device__ __forceinline__ void cpa16(unsigned d, const void* s)
{
    asm volatile("cp.async.cg.shared.global [%0], [%1], 16;" :: "r"(d), "l"(s));
}
__device__ __forceinline__ void cpa_commit()
{
    asm volatile("cp.async.commit_group;");
}
template<int NN> __device__ __forceinline__ void cpa_wait()
{
    asm volatile("cp.async.wait_group %0;" :: "n"(NN));
}

__device__ __forceinline__ uint2 pack4(float4 f)
{
    __nv_bfloat162 p0 = __floats2bfloat162_rn(f.x, f.y);
    __nv_bfloat162 p1 = __floats2bfloat162_rn(f.z, f.w);
    uint2 u;
    u.x = *(unsigned*)&p0;
    u.y = *(unsigned*)&p1;
    return u;
}

__device__ __forceinline__ unsigned packbf2(float a, float b)
{
    __nv_bfloat162 p = __floats2bfloat162_rn(a, b);
    return *(unsigned*)&p;
}

__device__ __forceinline__ float epi_apply_scalar(int EPI, float v)
{
    if (EPI == EPI_SOFTPLUS) return (v > 20.f) ? v : log1pf(expf(v));
    if (EPI == EPI_GELU)     return 0.5f*v*(1.f + erff(v*0.7071067811865475f));
    return v;
}

// ---------------- fp32 -> bf16 conversion (rn, identical to staging cvt) -----
__global__ void cvt_bf_k(const float* __restrict__ s, __nv_bfloat16* __restrict__ d, int n)
{
    int i = (blockIdx.x * 256 + threadIdx.x) * 4;
    if (i < n) {
        float4 v = *(const float4*)(s + i);
        *(uint2*)(d + i) = pack4(v);
    }
}

// ====== all-bf16 GEMM with cp.async staging: C = A(MxK) @ W(NxK)^T ===========
// A, W bf16. N % 64 == 0, K % 64 == 0. 128x64 tile, 8 warps (4Mx2N).
template<int EPI, int OBF>
__global__ __launch_bounds__(256, 2) void gemm_bb(
    const __nv_bfloat16* __restrict__ A, int lda,
    const __nv_bfloat16* __restrict__ W,
    const float* __restrict__ bias,
    const float* __restrict__ add,
    const float* __restrict__ add2,
    void* __restrict__ Cv, int M, int N, int K)
{
    __shared__ __align__(16) char sm[2*16384 + 2*8192];
    char* AsP = sm;
    char* BsP = sm + 2*16384;
    const unsigned asU = (unsigned)__cvta_generic_to_shared(AsP);
    const unsigned bsU = (unsigned)__cvta_generic_to_shared(BsP);

    const int tid = threadIdx.x;
    const int lane = tid & 31, w = tid >> 5;
    const int warpM = w & 3, warpN = w >> 2;
    const int m0 = blockIdx.y * 128, n0 = blockIdx.x * 64;

    // A staging: row = tid>>1 (0..127), 4 contiguous 16B segs from (tid&1)*4
    const int arow = tid >> 1, ag0 = (tid & 1) * 4;
    const __nv_bfloat16* Ap = A + (size_t)(m0 + arow) * lda + ag0*8;
    unsigned adst[4];
#pragma unroll
    for (int i = 0; i < 4; i++)
        adst[i] = asU + arow*128 + (((ag0 + i) ^ (arow & 7)) << 4);

    // B staging: row = tid>>2 (0..63), 2 segs from (tid&3)*2
    const int brow = tid >> 2, bg0 = (tid & 3) * 2;
    const __nv_bfloat16* Bp = W + (size_t)(n0 + brow) * K + bg0*8;
    unsigned bdst[2];
#pragma unroll
    for (int i = 0; i < 2; i++)
        bdst[i] = bsU + brow*128 + (((bg0 + i) ^ (brow & 7)) << 4);

    // ldmatrix lane geometry
    const int lr = (lane & 7) + ((lane >> 3) & 1) * 8;
    const int ko = (lane >> 4);
    int rA[2], mA[2];
#pragma unroll
    for (int mi = 0; mi < 2; mi++) {
        int r = warpM*32 + mi*16 + lr;
        rA[mi] = r * 128; mA[mi] = r & 7;
    }
    int rB[2], mB[2];
#pragma unroll
    for (int nh = 0; nh < 2; nh++) {
        int r = warpN*32 + nh*16 + lr;
        rB[nh] = r * 128; mB[nh] = r & 7;
    }

    float acc[2][4][4];
#pragma unroll
    for (int mi = 0; mi < 2; mi++)
#pragma unroll
        for (int nf = 0; nf < 4; nf++)
#pragma unroll
            for (int j = 0; j < 4; j++) acc[mi][nf][j] = 0.f;

    const int nk = K >> 6;

    // prologue: async-copy tile 0 into buffer 0
#pragma unroll
    for (int i = 0; i < 4; i++) cpa16(adst[i], Ap + i*8);
#pragma unroll
    for (int i = 0; i < 2; i++) cpa16(bdst[i], Bp + i*8);
    cpa_commit();

    for (int kt = 0; kt < nk; kt++) {
        const int cur = kt & 1;
        const bool more = (kt + 1) < nk;
        if (more) {
            const int nxt = cur ^ 1;
            const int kof = (kt + 1) << 6;
#pragma unroll
            for (int i = 0; i < 4; i++) cpa16(adst[i] + nxt*16384, Ap + kof + i*8);
#pragma unroll
            for (int i = 0; i < 2; i++) cpa16(bdst[i] + nxt*8192,  Bp + kof + i*8);
            cpa_commit();
            cpa_wait<1>();
        } else {
            cpa_wait<0>();
        }
        __syncthreads();

        const unsigned aB = asU + cur*16384;
        const unsigned bB = bsU + cur*8192;
#pragma unroll
        for (int ks = 0; ks < 4; ks++) {
            const int kx = 2*ks + ko;
            unsigned afr[2][4], bfr[2][4];
#pragma unroll
            for (int mi = 0; mi < 2; mi++)
                ldsm4(afr[mi], aB + rA[mi] + ((kx ^ mA[mi]) << 4));
#pragma unroll
            for (int nh = 0; nh < 2; nh++)
                ldsm4(bfr[nh], bB + rB[nh] + ((kx ^ mB[nh]) << 4));
#pragma unroll
            for (int mi = 0; mi < 2; mi++) {
                unsigned b0[2] = {bfr[0][0], bfr[0][2]};
                unsigned b1[2] = {bfr[0][1], bfr[0][3]};
                unsigned b2[2] = {bfr[1][0], bfr[1][2]};
                unsigned b3[2] = {bfr[1][1], bfr[1][3]};
                mma_bf16(acc[mi][0], afr[mi], b0);
                mma_bf16(acc[mi][1], afr[mi], b1);
                mma_bf16(acc[mi][2], afr[mi], b2);
                mma_bf16(acc[mi][3], afr[mi], b3);
            }
        }
        __syncthreads();
    }

    // epilogue
#pragma unroll
    for (int mi = 0; mi < 2; mi++) {
#pragma unroll
        for (int nf = 0; nf < 4; nf++) {
            int row = m0 + warpM*32 + mi*16 + (lane >> 2);
            int col = n0 + warpN*32 + nf*8 + (lane & 3)*2;
            float v00 = acc[mi][nf][0], v01 = acc[mi][nf][1];
            float v10 = acc[mi][nf][2], v11 = acc[mi][nf][3];
            if (bias) {
                float b0 = bias[col], b1 = bias[col+1];
                v00 += b0; v01 += b1; v10 += b0; v11 += b1;
            }
            if (EPI == EPI_ADD || EPI == EPI_ADD2) {
                const float* ap0 = add + (size_t)row * N + col;
                const float* ap1 = add + (size_t)(row+8) * N + col;
                v00 += ap0[0]; v01 += ap0[1]; v10 += ap1[0]; v11 += ap1[1];
                if (EPI == EPI_ADD2) {
                    const float* bp0 = add2 + (size_t)row * N + col;
                    const float* bp1 = add2 + (size_t)(row+8) * N + col;
                    v00 += bp0[0]; v01 += bp0[1]; v10 += bp1[0]; v11 += bp1[1];
                }
            } else {
                v00 = epi_apply_scalar(EPI, v00); v01 = epi_apply_scalar(EPI, v01);
                v10 = epi_apply_scalar(EPI, v10); v11 = epi_apply_scalar(EPI, v11);
            }
            if (OBF) {
                __nv_bfloat16* C16 = (__nv_bfloat16*)Cv;
                *(unsigned*)&C16[(size_t)row * N + col]     = packbf2(v00, v01);
                *(unsigned*)&C16[(size_t)(row+8) * N + col] = packbf2(v10, v11);
            } else {
                float* C = (float*)Cv;
                *(float2*)&C[(size_t)row * N + col]     = make_float2(v00, v01);
                *(float2*)&C[(size_t)(row+8) * N + col] = make_float2(v10, v11);
            }
        }
    }
}

// ================= tf32 tensor-core GEMM (scan-sensitive projections) ========
template<int EPI>
__global__ __launch_bounds__(256) void gemm_tf32(
    const float* __restrict__ A, int lda,
    const float* __restrict__ W,
    const float* __restrict__ bias,
    float* __restrict__ C, int M, int N, int K)
{
    __shared__ __align__(16) unsigned As[2][128*32];
    __shared__ __align__(16) unsigned Bs[2][64*32];

    const int t = threadIdx.x;
    const int m0 = blockIdx.y * 128, n0 = blockIdx.x * 64;
    const int lane = t & 31, w = t >> 5;
    const int warpM = w & 3, warpN = w >> 2;
    const int s = lane >> 2, off = lane & 3;

    const float* aptr[4]; int aso[4];
#pragma unroll
    for (int i = 0; i < 4; i++) {
        int e = t + i*256;
        int m = e >> 3, g = e & 7;
        aptr[i] = A + (size_t)(m0 + m) * lda + g*4;
        aso[i]  = m*32 + ((g ^ (m & 7)) << 2);
    }
    const float* bptr[2]; int bso[2]; bool bval[2];
#pragma unroll
    for (int i = 0; i < 2; i++) {
        int e = t + i*256;
        int n = e >> 3, g = e & 7;
        bval[i] = (n0 + n) < N;
        bptr[i] = W + (size_t)(n0 + n) * K + g*4;
        bso[i]  = n*32 + ((g ^ (n & 7)) << 2);
    }

    float acc[2][4][4];
#pragma unroll
    for (int mi = 0; mi < 2; mi++)
#pragma unroll
        for (int ni = 0; ni < 4; ni++)
#pragma unroll
            for (int j = 0; j < 4; j++) acc[mi][ni][j] = 0.f;

    const int nk = K >> 5;
    float4 ar[4], br[2];

#pragma unroll
    for (int i = 0; i < 4; i++) ar[i] = *(const float4*)(aptr[i]);
#pragma unroll
    for (int i = 0; i < 2; i++)
        br[i] = bval[i] ? *(const float4*)(bptr[i]) : make_float4(0.f,0.f,0.f,0.f);
#pragma unroll
    for (int i = 0; i < 4; i++)
        *(uint4*)&As[0][aso[i]] = make_uint4(f2tf32(ar[i].x), f2tf32(ar[i].y), f2tf32(ar[i].z), f2tf32(ar[i].w));
#pragma unroll
    for (int i = 0; i < 2; i++)
        *(uint4*)&Bs[0][bso[i]] = make_uint4(f2tf32(br[i].x), f2tf32(br[i].y), f2tf32(br[i].z), f2tf32(br[i].w));
    __syncthreads();

    for (int kt = 0; kt < nk; kt++) {
        const int cur = kt & 1, nxt = cur ^ 1;
        const bool more = (kt + 1) < nk;
        if (more) {
            const int ko = (kt + 1) * 32;
#pragma unroll
            for (int i = 0; i < 4; i++) ar[i] = *(const float4*)(aptr[i] + ko);
#pragma unroll
            for (int i = 0; i < 2; i++)
                br[i] = bval[i] ? *(const float4*)(bptr[i] + ko) : make_float4(0.f,0.f,0.f,0.f);
        }

#pragma unroll
        for (int ks = 0; ks < 4; ks++) {
            const int x0 = (((ks*2)     ^ s) << 2) + off;
            const int x1 = (((ks*2 + 1) ^ s) << 2) + off;
            unsigned a[2][4];
#pragma unroll
            for (int mi = 0; mi < 2; mi++) {
                int r = (warpM*32 + mi*16 + s) * 32;
                a[mi][0] = As[cur][r + x0];
                a[mi][1] = As[cur][r + 256 + x0];
                a[mi][2] = As[cur][r + x1];
                a[mi][3] = As[cur][r + 256 + x1];
            }
            unsigned b[4][2];
#pragma unroll
            for (int ni = 0; ni < 4; ni++) {
                int rb = (warpN*32 + ni*8 + s) * 32;
                b[ni][0] = Bs[cur][rb + x0];
                b[ni][1] = Bs[cur][rb + x1];
            }
#pragma unroll
            for (int mi = 0; mi < 2; mi++)
#pragma unroll
                for (int ni = 0; ni < 4; ni++)
                    mma_tf32(acc[mi][ni], a[mi], b[ni]);
        }

        if (more) {
#pragma unroll
            for (int i = 0; i < 4; i++)
                *(uint4*)&As[nxt][aso[i]] = make_uint4(f2tf32(ar[i].x), f2tf32(ar[i].y), f2tf32(ar[i].z), f2tf32(ar[i].w));
#pragma unroll
            for (int i = 0; i < 2; i++)
                *(uint4*)&Bs[nxt][bso[i]] = make_uint4(f2tf32(br[i].x), f2tf32(br[i].y), f2tf32(br[i].z), f2tf32(br[i].w));
            __syncthreads();
        }
    }

#pragma unroll
    for (int mi = 0; mi < 2; mi++) {
#pragma unroll
        for (int ni = 0; ni < 4; ni++) {
            int row = m0 + warpM*32 + mi*16 + s;
            int col = n0 + warpN*32 + ni*8 + off*2;
            if (col < N) {
                float v00 = acc[mi][ni][0], v01 = acc[mi][ni][1];
                float v10 = acc[mi][ni][2], v11 = acc[mi][ni][3];
                if (bias) {
                    float b0 = bias[col], b1 = bias[col+1];
                    v00 += b0; v01 += b1; v10 += b0; v11 += b1;
                }
                v00 = epi_apply_scalar(EPI, v00); v01 = epi_apply_scalar(EPI, v01);
                v10 = epi_apply_scalar(EPI, v10); v11 = epi_apply_scalar(EPI, v11);
                *(float2*)&C[(size_t)row * N + col]     = make_float2(v00, v01);
                *(float2*)&C[(size_t)(row+8) * N + col] = make_float2(v10, v11);
            }
        }
    }
}

// ============== bf16 tensor-core flash attention (ldmatrix) ==================
__global__ __launch_bounds__(256, 2) void attn_bf(
    const __nv_bfloat16* __restrict__ q, const __nv_bfloat16* __restrict__ k,
    const __nv_bfloat16* __restrict__ v, const unsigned char* __restrict__ mask,
    __nv_bfloat16* __restrict__ o)
{
    extern __shared__ __align__(16) char smA[];
    char* sQ = smA;                  // 16384
    char* sK = smA + 16384;          // 8192
    char* sV = smA + 24576;          // 8192
    const int tid = threadIdx.x;
    const int lane = tid & 31, w = tid >> 5;
    char* sP = smA + 32768 + w*2048; // per-warp 2048
    const unsigned uQ = (unsigned)__cvta_generic_to_shared(sQ);
    const unsigned uK = (unsigned)__cvta_generic_to_shared(sK);
    const unsigned uV = (unsigned)__cvta_generic_to_shared(sV);
    const unsigned uP = (unsigned)__cvta_generic_to_shared(sP);

    const int qt = blockIdx.x, h = blockIdx.y, b = blockIdx.z;
    const size_t bL = (size_t)b * LL;
    const int qr = qt * 128;

    const int lr = (lane & 7) + ((lane >> 3) & 1) * 8;
    const int ko = lane >> 4;
    const int s = lane >> 2, off = lane & 3;

#pragma unroll
    for (int i = 0; i < 4; i++) {
        int u = tid + i*256;
        int row = u >> 3, g = u & 7;
        uint4 val = *(const uint4*)&q[(bL + qr + row) * Dd + h*Ee + g*8];
        *(uint4*)(sQ + row*128 + ((g ^ (row & 7)) << 4)) = val;
    }
    __syncthreads();

    unsigned qa[4][4];
    {
        int r = w*16 + lr;
        unsigned base = uQ + r*128;
#pragma unroll
        for (int ks = 0; ks < 4; ks++)
            ldsm4(qa[ks], base + (((2*ks + ko) ^ (r & 7)) << 4));
    }

    float oa[8][4];
#pragma unroll
    for (int et = 0; et < 8; et++)
#pragma unroll
        for (int j = 0; j < 4; j++) oa[et][j] = 0.f;
    float m0v = -INFINITY, m1v = -INFINITY, l0v = 0.f, l1v = 0.f;

    for (int n0k = 0; n0k < LL; n0k += 64) {
        __syncthreads();
#pragma unroll
        for (int i = 0; i < 2; i++) {
            int u = tid + i*256;
            int row = u >> 3, g = u & 7;
            size_t gr = (bL + n0k + row) * Dd + h*Ee + g*8;
            int so = row*128 + ((g ^ (row & 7)) << 4);
            *(uint4*)(sK + so) = *(const uint4*)&k[gr];
            *(uint4*)(sV + so) = *(const uint4*)&v[gr];
        }
        __syncthreads();

        float sa[8][4];
#pragma unroll
        for (int nt = 0; nt < 8; nt++)
#pragma unroll
            for (int j = 0; j < 4; j++) sa[nt][j] = 0.f;
#pragma unroll
        for (int ks = 0; ks < 4; ks++) {
#pragma unroll
            for (int nb = 0; nb < 4; nb++) {
                unsigned bfr[4];
                int r = nb*16 + lr;
                ldsm4(bfr, uK + r*128 + (((2*ks + ko) ^ (r & 7)) << 4));
                unsigned b0[2] = {bfr[0], bfr[2]};
                unsigned b1[2] = {bfr[1], bfr[3]};
                mma_bf16(sa[nb*2],     qa[ks], b0);
                mma_bf16(sa[nb*2 + 1], qa[ks], b1);
            }
        }

        float rmax0 = -INFINITY, rmax1 = -INFINITY;
#pragma unroll
        for (int nt = 0; nt < 8; nt++) {
            sa[nt][0] *= 0.125f; sa[nt][1] *= 0.125f;
            sa[nt][2] *= 0.125f; sa[nt][3] *= 0.125f;
            unsigned char mk0 = mask[bL + n0k + nt*8 + off*2];
            unsigned char mk1 = mask[bL + n0k + nt*8 + off*2 + 1];
            if (mk0) { sa[nt][0] = -INFINITY; sa[nt][2] = -INFINITY; }
            if (mk1) { sa[nt][1] = -INFINITY; sa[nt][3] = -INFINITY; }
            rmax0 = fmaxf(rmax0, fmaxf(sa[nt][0], sa[nt][1]));
            rmax1 = fmaxf(rmax1, fmaxf(sa[nt][2], sa[nt][3]));
        }
        rmax0 = fmaxf(rmax0, __shfl_xor_sync(0xffffffffu, rmax0, 1));
        rmax0 = fmaxf(rmax0, __shfl_xor_sync(0xffffffffu, rmax0, 2));
        rmax1 = fmaxf(rmax1, __shfl_xor_sync(0xffffffffu, rmax1, 1));
        rmax1 = fmaxf(rmax1, __shfl_xor_sync(0xffffffffu, rmax1, 2));
        float mn0 = fmaxf(m0v, rmax0), mn1 = fmaxf(m1v, rmax1);
        float c0 = __expf(m0v - mn0), c1 = __expf(m1v - mn1);
        float rs0 = 0.f, rs1 = 0.f;
#pragma unroll
        for (int nt = 0; nt < 8; nt++) {
            float p0 = __expf(sa[nt][0] - mn0);
            float p1 = __expf(sa[nt][1] - mn0);
            float p2 = __expf(sa[nt][2] - mn1);
            float p3 = __expf(sa[nt][3] - mn1);
            rs0 += p0 + p1; rs1 += p2 + p3;
            *(unsigned*)(sP + s*128       + ((nt ^ (s & 7)) << 4) + off*4) = packbf2(p0, p1);
            *(unsigned*)(sP + (s+8)*128   + ((nt ^ (s & 7)) << 4) + off*4) = packbf2(p2, p3);
        }
        rs0 += __shfl_xor_sync(0xffffffffu, rs0, 1);
        rs0 += __shfl_xor_sync(0xffffffffu, rs0, 2);
        rs1 += __shfl_xor_sync(0xffffffffu, rs1, 1);
        rs1 += __shfl_xor_sync(0xffffffffu, rs1, 2);
        l0v = l0v * c0 + rs0; l1v = l1v * c1 + rs1;
        m0v = mn0; m1v = mn1;
#pragma unroll
        for (int et = 0; et < 8; et++) {
            oa[et][0] *= c0; oa[et][1] *= c0;
            oa[et][2] *= c1; oa[et][3] *= c1;
        }
        __syncwarp();

#pragma unroll
        for (int ksp = 0; ksp < 4; ksp++) {
            unsigned pa[4];
            {
                int r = lr;
                ldsm4(pa, uP + r*128 + (((2*ksp + ko) ^ (r & 7)) << 4));
            }
            int key = ksp*16 + lr;
#pragma unroll
            for (int j = 0; j < 4; j++) {
                unsigned vfr[4];
                ldsm4t(vfr, uV + key*128 + (((2*j + ko) ^ (key & 7)) << 4));
                unsigned be0[2] = {vfr[0], vfr[1]};
                unsigned be1[2] = {vfr[2], vfr[3]};
                mma_bf16(oa[j*2],     pa, be0);
                mma_bf16(oa[j*2 + 1], pa, be1);
            }
        }
    }

    float inv0 = 1.f / l0v, inv1 = 1.f / l1v;
#pragma unroll
    for (int et = 0; et < 8; et++) {
        size_t r0 = (bL + qr + w*16 + s    ) * Dd + h*Ee + et*8 + off*2;
        size_t r1 = (bL + qr + w*16 + s + 8) * Dd + h*Ee + et*8 + off*2;
        *(unsigned*)&o[r0] = packbf2(oa[et][0]*inv0, oa[et][1]*inv0);
        *(unsigned*)&o[r1] = packbf2(oa[et][2]*inv1, oa[et][3]*inv1);
    }
}

// ---------------- causal depthwise conv (KC=4) + SiLU ------------------------
__global__ void conv_silu_k(const float* __restrict__ xz,
                            const float* __restrict__ cw,
                            const float* __restrict__ cb,
                            float* __restrict__ uact)
{
    int idx = blockIdx.x * 256 + threadIdx.x;
    int r = idx >> 10;
    int j = idx & 1023;
    int t = r % LL;
    float acc = cb[j];
#pragma unroll
    for (int kk = 0; kk < 4; kk++) {
        int tt = t + kk - 3;
        if (tt >= 0)
            acc = fmaf(xz[(size_t)(r + kk - 3) * (2*DI) + j], cw[j*4 + kk], acc);
    }
    uact[idx] = acc / (1.f + expf(-acc));
}

// -------- selective scan + fused gate: 1 warp per (b,d), 2 states/lane -------
__global__ __launch_bounds__(512) void scan_gate_k(
    const float* __restrict__ delta, const float* __restrict__ uact,
    const float* __restrict__ xdbc, const float* __restrict__ A_log,
    const float* __restrict__ xz,   const float* __restrict__ Dssm,
    __nv_bfloat16* __restrict__ y)
{
    __shared__ float sB[16][64];
    __shared__ float sC[16][64];
    __shared__ float sdt[16][16];
    __shared__ float su[16][16];
    __shared__ float sz[16][16];
    __shared__ float spw[16][16][33];

    int b = blockIdx.y;
    int d0 = blockIdx.x * 16;
    int tid = threadIdx.x;
    int w = tid >> 5, l = tid & 31;
    int d = d0 + w;
    float a0 = -expf(A_log[d*Ss + l]);
    float a1 = -expf(A_log[d*Ss + l + 32]);
    float dD = Dssm[d];
    float h0 = 0.f, h1 = 0.f;
    size_t base = (size_t)b * LL;

    const int rr = l >> 1;
    const int half = l & 1;

    for (int t0 = 0; t0 < LL; t0 += 16) {
        __syncthreads();
        for (int i = tid; i < 2048; i += 512) {
            int tt = i >> 7, c = i & 127;
            float val = xdbc[(base + t0 + tt) * 160 + 32 + c];
            if (c < 64) sB[tt][c] = val; else sC[tt][c - 64] = val;
        }
        for (int i = tid; i < 768; i += 512) {
            int sel = i >> 8;
            int e = i & 255;
            int tt = e >> 4, c = e & 15;
            size_t row = base + t0 + tt;
            if (sel == 0)      sdt[tt][c] = delta[row * DI + d0 + c];
            else if (sel == 1) su[tt][c]  = uact [row * DI + d0 + c];
            else               sz[tt][c]  = xz[row * (2*DI) + DI + d0 + c];
        }
        __syncthreads();

#pragma unroll 4
        for (int tt = 0; tt < 16; tt++) {
            float dt  = sdt[tt][w];
            float dtu = dt * su[tt][w];
            float dA0 = __expf(dt * a0);
            float dA1 = __expf(dt * a1);
            h0 = fmaf(h0, dA0, dtu * sB[tt][l]);
            h1 = fmaf(h1, dA1, dtu * sB[tt][l + 32]);
            spw[w][tt][l] = fmaf(h1, sC[tt][l + 32], h0 * sC[tt][l]);
        }
        __syncwarp();

        float accv = 0.f;
#pragma unroll
        for (int i = 0; i < 16; i++) accv += spw[w][rr][half*16 + i];
        accv += __shfl_xor_sync(0xffffffffu, accv, 1);
        if (half == 0) {
            float uu = su[rr][w];
            float zz = sz[rr][w];
            float yv = fmaf(uu, dD, accv);
            y[(base + t0 + rr) * DI + d] = __float2bfloat16(yv * (zz / (1.f + __expf(-zz))));
        }
    }
}

// ---------------- double LayerNorm on pre-summed residual --------------------
__device__ __forceinline__ float blockSum128(float v, float* sm)
{
#pragma unroll
    for (int offx = 16; offx > 0; offx >>= 1)
        v += __shfl_xor_sync(0xffffffffu, v, offx);
    if ((threadIdx.x & 31) == 0) sm[threadIdx.x >> 5] = v;
    __syncthreads();
    float r = sm[0] + sm[1] + sm[2] + sm[3];
    __syncthreads();
    return r;
}

__global__ __launch_bounds__(128) void ln2_k(
    const float* __restrict__ hsum,
    const float* __restrict__ g1, const float* __restrict__ b1,
    const float* __restrict__ g2, const float* __restrict__ b2,
    float* __restrict__ h, __nv_bfloat16* __restrict__ hn)
{
    __shared__ float sm[4];
    int r = blockIdx.x, tid = threadIdx.x;
    size_t base = (size_t)r * Dd;
    float vv[4];
#pragma unroll
    for (int i = 0; i < 4; i++) vv[i] = hsum[base + tid + i*128];
    float s = vv[0] + vv[1] + vv[2] + vv[3];
    float mean = blockSum128(s, sm) * (1.f/512.f);
    float sq = 0.f;
#pragma unroll
    for (int i = 0; i < 4; i++) { float dd = vv[i] - mean; sq = fmaf(dd, dd, sq); }
    float var = blockSum128(sq, sm) * (1.f/512.f);
    float inv = rsqrtf(var + 1e-5f);
    float hv[4];
#pragma unroll
    for (int i = 0; i < 4; i++) {
        int c = tid + i*128;
        hv[i] = (vv[i] - mean) * inv * g1[c] + b1[c];
        h[base+c] = hv[i];
    }
    float s2 = hv[0] + hv[1] + hv[2] + hv[3];
    float mean2 = blockSum128(s2, sm) * (1.f/512.f);
    float sq2 = 0.f;
#pragma unroll
    for (int i = 0; i < 4; i++) { float dd = hv[i] - mean2; sq2 = fmaf(dd, dd, sq2); }
    float var2 = blockSum128(sq2, sm) * (1.f/512.f);
    float inv2 = rsqrtf(var2 + 1e-6f);
#pragma unroll
    for (int i = 0; i < 4; i++) {
        int c = tid + i*128;
        hn[base+c] = __float2bfloat16((hv[i] - mean2) * inv2 * g2[c] + b2[c]);
    }
}

// ---------------- launch -----------------------------------------------------
extern "C" void kernel_launch(void* const* d_in, const int* in_sizes, int n_in,
                              void* d_out, int out_size)
{
    const float* x            = (const float*)d_in[0];
    const unsigned char* mask = (const unsigned char*)d_in[1];
    const float* Wq = (const float*)d_in[2];   const float* bq = (const float*)d_in[3];
    const float* Wk = (const float*)d_in[4];   const float* bk = (const float*)d_in[5];
    const float* Wv = (const float*)d_in[6];   const float* bv = (const float*)d_in[7];
    const float* Wo = (const float*)d_in[8];   const float* bo = (const float*)d_in[9];
    const float* in_proj_w = (const float*)d_in[10];
    const float* conv_w    = (const float*)d_in[11];
    const float* conv_b    = (const float*)d_in[12];
    const float* x_proj_w  = (const float*)d_in[13];
    const float* dt_proj_w = (const float*)d_in[14];
    const float* dt_proj_b = (const float*)d_in[15];
    const float* A_log     = (const float*)d_in[16];
    const float* D_ssm     = (const float*)d_in[17];
    const float* out_proj_w= (const float*)d_in[18];
    const float* ln1_g = (const float*)d_in[19]; const float* ln1_b = (const float*)d_in[20];
    const float* ffn_w1= (const float*)d_in[21]; const float* ffn_b1= (const float*)d_in[22];
    const float* ffn_w2= (const float*)d_in[23]; const float* ffn_b2= (const float*)d_in[24];
    const float* ln2_g = (const float*)d_in[25]; const float* ln2_b = (const float*)d_in[26];
    float* out = (float*)d_out;

    __nv_bfloat16 *xbf,*wqb,*wkb,*wvb,*wob,*winb,*woutb,*wf1b,*wf2b;
    __nv_bfloat16 *q, *k, *v, *attnO, *y, *hn, *mid;
    float *attn_out,*xz,*uact,*xdbc,*delta,*hsum,*h;
    cudaGetSymbolAddress((void**)&xbf,   g_xbf);
    cudaGetSymbolAddress((void**)&wqb,   g_wq);
    cudaGetSymbolAddress((void**)&wkb,   g_wk);
    cudaGetSymbolAddress((void**)&wvb,   g_wv);
    cudaGetSymbolAddress((void**)&wob,   g_wo);
    cudaGetSymbolAddress((void**)&winb,  g_win);
    cudaGetSymbolAddress((void**)&woutb, g_wout);
    cudaGetSymbolAddress((void**)&wf1b,  g_wf1);
    cudaGetSymbolAddress((void**)&wf2b,  g_wf2);
    cudaGetSymbolAddress((void**)&q,        g_q);
    cudaGetSymbolAddress((void**)&k,        g_k);
    cudaGetSymbolAddress((void**)&v,        g_v);
    cudaGetSymbolAddress((void**)&attnO,    g_attnO);
    cudaGetSymbolAddress((void**)&attn_out, g_attn_out);
    cudaGetSymbolAddress((void**)&xz,       g_xz);
    cudaGetSymbolAddress((void**)&uact,     g_uact);
    cudaGetSymbolAddress((void**)&xdbc,     g_xdbc);
    cudaGetSymbolAddress((void**)&delta,    g_delta);
    cudaGetSymbolAddress((void**)&y,        g_y);
    cudaGetSymbolAddress((void**)&hsum,     g_hsum);
    cudaGetSymbolAddress((void**)&h,        g_h);
    cudaGetSymbolAddress((void**)&hn,       g_hn);
    cudaGetSymbolAddress((void**)&mid,      g_mid);

    static cudaStream_t s_attn = nullptr;
    static cudaEvent_t  e_fork = nullptr, e_join = nullptr;
    if (s_attn == nullptr) {
        cudaStreamCreateWithFlags(&s_attn, cudaStreamNonBlocking);
        cudaEventCreateWithFlags(&e_fork, cudaEventDisableTiming);
        cudaEventCreateWithFlags(&e_join, cudaEventDisableTiming);
    }

    const int MY = Mrows / 128;   // 72
    const int attn_smem = 32768 + 8*2048;   // 49152 bytes
    cudaFuncSetAttribute(attn_bf, cudaFuncAttributeMaxDynamicSharedMemorySize, attn_smem);

    #define CVT(src, dst, n) cvt_bf_k<<<((n)/4 + 255)/256, 256, 0, 0>>>(src, dst, n)
    #define CVT_S(src, dst, n) cvt_bf_k<<<((n)/4 + 255)/256, 256, 0, s_attn>>>(src, dst, n)

    // ---- x -> bf16 (needed by both branches), then fork ----
    CVT(x, xbf, Mrows*Dd);
    cudaEventRecord(e_fork, 0);
    cudaStreamWaitEvent(s_attn, e_fork, 0);

    // attention branch (s_attn): convert its weights, then run
    CVT_S(Wq, wqb, Dd*Dd);
    CVT_S(Wk, wkb, Dd*Dd);
    CVT_S(Wv, wvb, Dd*Dd);
    CVT_S(Wo, wob, Dd*Dd);
    gemm_bb<EPI_NONE,1><<<dim3(Dd/64,   MY), 256, 0, s_attn>>>(xbf, Dd, wqb, bq, nullptr, nullptr, q, Mrows, Dd, Dd);
    gemm_bb<EPI_NONE,1><<<dim3(Dd/64,   MY), 256, 0, s_attn>>>(xbf, Dd, wkb, bk, nullptr, nullptr, k, Mrows, Dd, Dd);
    gemm_bb<EPI_NONE,1><<<dim3(Dd/64,   MY), 256, 0, s_attn>>>(xbf, Dd, wvb, bv, nullptr, nullptr, v, Mrows, Dd, Dd);
    attn_bf<<<dim3(LL/128, Hh, Bsz), 256, attn_smem, s_attn>>>(q, k, v, mask, attnO);
    gemm_bb<EPI_NONE,0><<<dim3(Dd/64,   MY), 256, 0, s_attn>>>(attnO, Dd, wob, bo, nullptr, nullptr, attn_out, Mrows, Dd, Dd);
    cudaEventRecord(e_join, s_attn);

    // mamba branch (stream 0): convert its weights, then run
    CVT(in_proj_w, winb, 2*DI*Dd);
    CVT(out_proj_w, woutb, Dd*DI);
    CVT(ffn_w1, wf1b, DFF*Dd);
    CVT(ffn_w2, wf2b, Dd*DFF);
    gemm_bb<EPI_NONE,0><<<dim3(2*DI/64, MY), 256>>>(xbf, Dd, winb, nullptr, nullptr, nullptr, xz, Mrows, 2*DI, Dd);
    conv_silu_k<<<Mrows*DI/256, 256>>>(xz, conv_w, conv_b, uact);
    gemm_tf32<EPI_NONE><<<dim3(3,       MY), 256>>>(uact, DI, x_proj_w, nullptr, xdbc, Mrows, 160, DI);
    gemm_tf32<EPI_SOFTPLUS><<<dim3(DI/64, MY), 256>>>(xdbc, 160, dt_proj_w, dt_proj_b, delta, Mrows, DI, Rr);
    scan_gate_k<<<dim3(DI/16, Bsz), 512>>>(delta, uact, xdbc, A_log, xz, D_ssm, y);

    // ---- join, then out_proj with fused residual adds ----
    cudaStreamWaitEvent(0, e_join, 0);
    gemm_bb<EPI_ADD2,0><<<dim3(Dd/64,   MY), 256>>>(y, DI, woutb, nullptr, x, attn_out, hsum, Mrows, Dd, DI);

    // double layernorm
    ln2_k<<<Mrows, 128>>>(hsum, ln1_g, ln1_b, ln2_g, ln2_b, h, hn);

    // FFN
    gemm_bb<EPI_GELU,1><<<dim3(DFF/64, MY), 256>>>(hn, Dd, wf1b, ffn_b1, nullptr, nullptr, mid, Mrows, DFF, Dd);
    gemm_bb<EPI_ADD,0><<<dim3(Dd/64,   MY), 256>>>(mid, DFF, wf2b, ffn_b2, h, nullptr, out, Mrows, Dd, DFF);

    #undef CVT
    #undef CVT_S
}

// round 16
// speedup vs baseline: 1.3114x; 1.0987x over previous
#include <cuda_runtime.h>
#include <cuda_bf16.h>
#include <math.h>

#define Bsz 8
#define Dd 512
#define Hh 8
#define Ee 64
#define DI 1024
#define Ss 64
#define Rr 32
#define DFF 2048
#define LL 1152
#define Mrows (Bsz*LL)   /* 9216 */
#define QKVN 1536

// ---------------- scratch (static __device__, no allocation) ----------------
__device__ __nv_bfloat16 g_xbf[Mrows*Dd];
__device__ __nv_bfloat16 g_wqkv[QKVN*Dd];
__device__ float         g_bqkv[QKVN];
__device__ __nv_bfloat16 g_wo[Dd*Dd];
__device__ __nv_bfloat16 g_win[2*DI*Dd];
__device__ __nv_bfloat16 g_wout[Dd*DI];
__device__ __nv_bfloat16 g_wf1[DFF*Dd];
__device__ __nv_bfloat16 g_wf2[Dd*DFF];
__device__ __nv_bfloat16 g_qkv[Mrows*QKVN];
__device__ __nv_bfloat16 g_attnO[Mrows*Dd];
__device__ float g_attn_out[Mrows*Dd];
__device__ float g_xz[Mrows*2*DI];
__device__ float g_uact[Mrows*DI];
__device__ float g_xdbc[Mrows*160];
__device__ float g_delta[Mrows*DI];
__device__ __nv_bfloat16 g_y[Mrows*DI];
__device__ float g_hsum[Mrows*Dd];
__device__ float g_h[Mrows*Dd];
__device__ __nv_bfloat16 g_hn[Mrows*Dd];
__device__ __nv_bfloat16 g_mid[Mrows*DFF];

enum { EPI_NONE = 0, EPI_SOFTPLUS = 1, EPI_GELU = 2, EPI_ADD = 3, EPI_ADD2 = 4 };

__device__ __forceinline__ unsigned f2tf32(float f)
{
    unsigned u;
    asm("cvt.rna.tf32.f32 %0, %1;" : "=r"(u) : "f"(f));
    return u;
}

__device__ __forceinline__ void mma_tf32(float* c, const unsigned* a, const unsigned* b)
{
    asm volatile(
        "mma.sync.aligned.m16n8k8.row.col.f32.tf32.tf32.f32 "
        "{%0,%1,%2,%3},{%4,%5,%6,%7},{%8,%9},{%0,%1,%2,%3};"
        : "+f"(c[0]), "+f"(c[1]), "+f"(c[2]), "+f"(c[3])
        : "r"(a[0]), "r"(a[1]), "r"(a[2]), "r"(a[3]), "r"(b[0]), "r"(b[1]));
}

__device__ __forceinline__ void mma_bf16(float* c, const unsigned* a, const unsigned* b)
{
    asm volatile(
        "mma.sync.aligned.m16n8k16.row.col.f32.bf16.bf16.f32 "
        "{%0,%1,%2,%3},{%4,%5,%6,%7},{%8,%9},{%0,%1,%2,%3};"
        : "+f"(c[0]), "+f"(c[1]), "+f"(c[2]), "+f"(c[3])
        : "r"(a[0]), "r"(a[1]), "r"(a[2]), "r"(a[3]), "r"(b[0]), "r"(b[1]));
}

__device__ __forceinline__ void ldsm4(unsigned* r, unsigned saddr)
{
    asm volatile("ldmatrix.sync.aligned.m8n8.x4.shared.b16 {%0,%1,%2,%3}, [%4];"
        : "=r"(r[0]), "=r"(r[1]), "=r"(r[2]), "=r"(r[3]) : "r"(saddr));
}

__device__ __forceinline__ void ldsm4t(unsigned* r, unsigned saddr)
{
    asm volatile("ldmatrix.sync.aligned.m8n8.x4.trans.shared.b16 {%0,%1,%2,%3}, [%4];"
        : "=r"(r[0]), "=r"(r[1]), "=r"(r[2]), "=r"(r[3]) : "r"(saddr));
}

__device__ __forceinline__ void cpa16(unsigned d, const void* s)
{
    asm volatile("cp.async.cg.shared.global [%0], [%1], 16;" :: "r"(d), "l"(s));
}
__device__ __forceinline__ void cpa_commit()
{
    asm volatile("cp.async.commit_group;");
}
template<int NN> __device__ __forceinline__ void cpa_wait()
{
    asm volatile("cp.async.wait_group %0;" :: "n"(NN));
}

__device__ __forceinline__ uint2 pack4(float4 f)
{
    __nv_bfloat162 p0 = __floats2bfloat162_rn(f.x, f.y);
    __nv_bfloat162 p1 = __floats2bfloat162_rn(f.z, f.w);
    uint2 u;
    u.x = *(unsigned*)&p0;
    u.y = *(unsigned*)&p1;
    return u;
}

__device__ __forceinline__ unsigned packbf2(float a, float b)
{
    __nv_bfloat162 p = __floats2bfloat162_rn(a, b);
    return *(unsigned*)&p;
}

__device__ __forceinline__ float epi_apply_scalar(int EPI, float v)
{
    if (EPI == EPI_SOFTPLUS) return (v > 20.f) ? v : log1pf(expf(v));
    if (EPI == EPI_GELU)     return 0.5f*v*(1.f + erff(v*0.7071067811865475f));
    return v;
}

// ---------------- fp32 -> bf16 conversion (rn, identical to staging cvt) -----
__global__ void cvt_bf_k(const float* __restrict__ s, __nv_bfloat16* __restrict__ d, int n)
{
    int i = (blockIdx.x * 256 + threadIdx.x) * 4;
    if (i < n) {
        float4 v = *(const float4*)(s + i);
        *(uint2*)(d + i) = pack4(v);
    }
}

__global__ void concat_bias_k(const float* __restrict__ a, const float* __restrict__ b,
                              const float* __restrict__ c, float* __restrict__ d)
{
    int i = blockIdx.x * 256 + threadIdx.x;
    if (i < QKVN)
        d[i] = (i < Dd) ? a[i] : (i < 2*Dd) ? b[i - Dd] : c[i - 2*Dd];
}

// ====== all-bf16 GEMM with cp.async staging: C = A(MxK) @ W(NxK)^T ===========
template<int EPI, int OBF>
__global__ __launch_bounds__(256, 2) void gemm_bb(
    const __nv_bfloat16* __restrict__ A, int lda,
    const __nv_bfloat16* __restrict__ W,
    const float* __restrict__ bias,
    const float* __restrict__ add,
    const float* __restrict__ add2,
    void* __restrict__ Cv, int M, int N, int K)
{
    __shared__ __align__(16) char sm[2*16384 + 2*8192];
    char* AsP = sm;
    char* BsP = sm + 2*16384;
    const unsigned asU = (unsigned)__cvta_generic_to_shared(AsP);
    const unsigned bsU = (unsigned)__cvta_generic_to_shared(BsP);

    const int tid = threadIdx.x;
    const int lane = tid & 31, w = tid >> 5;
    const int warpM = w & 3, warpN = w >> 2;
    const int m0 = blockIdx.y * 128, n0 = blockIdx.x * 64;

    const int arow = tid >> 1, ag0 = (tid & 1) * 4;
    const __nv_bfloat16* Ap = A + (size_t)(m0 + arow) * lda + ag0*8;
    unsigned adst[4];
#pragma unroll
    for (int i = 0; i < 4; i++)
        adst[i] = asU + arow*128 + (((ag0 + i) ^ (arow & 7)) << 4);

    const int brow = tid >> 2, bg0 = (tid & 3) * 2;
    const __nv_bfloat16* Bp = W + (size_t)(n0 + brow) * K + bg0*8;
    unsigned bdst[2];
#pragma unroll
    for (int i = 0; i < 2; i++)
        bdst[i] = bsU + brow*128 + (((bg0 + i) ^ (brow & 7)) << 4);

    const int lr = (lane & 7) + ((lane >> 3) & 1) * 8;
    const int ko = (lane >> 4);
    int rA[2], mA[2];
#pragma unroll
    for (int mi = 0; mi < 2; mi++) {
        int r = warpM*32 + mi*16 + lr;
        rA[mi] = r * 128; mA[mi] = r & 7;
    }
    int rB[2], mB[2];
#pragma unroll
    for (int nh = 0; nh < 2; nh++) {
        int r = warpN*32 + nh*16 + lr;
        rB[nh] = r * 128; mB[nh] = r & 7;
    }

    float acc[2][4][4];
#pragma unroll
    for (int mi = 0; mi < 2; mi++)
#pragma unroll
        for (int nf = 0; nf < 4; nf++)
#pragma unroll
            for (int j = 0; j < 4; j++) acc[mi][nf][j] = 0.f;

    const int nk = K >> 6;

#pragma unroll
    for (int i = 0; i < 4; i++) cpa16(adst[i], Ap + i*8);
#pragma unroll
    for (int i = 0; i < 2; i++) cpa16(bdst[i], Bp + i*8);
    cpa_commit();

    for (int kt = 0; kt < nk; kt++) {
        const int cur = kt & 1;
        const bool more = (kt + 1) < nk;
        if (more) {
            const int nxt = cur ^ 1;
            const int kof = (kt + 1) << 6;
#pragma unroll
            for (int i = 0; i < 4; i++) cpa16(adst[i] + nxt*16384, Ap + kof + i*8);
#pragma unroll
            for (int i = 0; i < 2; i++) cpa16(bdst[i] + nxt*8192,  Bp + kof + i*8);
            cpa_commit();
            cpa_wait<1>();
        } else {
            cpa_wait<0>();
        }
        __syncthreads();

        const unsigned aB = asU + cur*16384;
        const unsigned bB = bsU + cur*8192;
#pragma unroll
        for (int ks = 0; ks < 4; ks++) {
            const int kx = 2*ks + ko;
            unsigned afr[2][4], bfr[2][4];
#pragma unroll
            for (int mi = 0; mi < 2; mi++)
                ldsm4(afr[mi], aB + rA[mi] + ((kx ^ mA[mi]) << 4));
#pragma unroll
            for (int nh = 0; nh < 2; nh++)
                ldsm4(bfr[nh], bB + rB[nh] + ((kx ^ mB[nh]) << 4));
#pragma unroll
            for (int mi = 0; mi < 2; mi++) {
                unsigned b0[2] = {bfr[0][0], bfr[0][2]};
                unsigned b1[2] = {bfr[0][1], bfr[0][3]};
                unsigned b2[2] = {bfr[1][0], bfr[1][2]};
                unsigned b3[2] = {bfr[1][1], bfr[1][3]};
                mma_bf16(acc[mi][0], afr[mi], b0);
                mma_bf16(acc[mi][1], afr[mi], b1);
                mma_bf16(acc[mi][2], afr[mi], b2);
                mma_bf16(acc[mi][3], afr[mi], b3);
            }
        }
        __syncthreads();
    }

#pragma unroll
    for (int mi = 0; mi < 2; mi++) {
#pragma unroll
        for (int nf = 0; nf < 4; nf++) {
            int row = m0 + warpM*32 + mi*16 + (lane >> 2);
            int col = n0 + warpN*32 + nf*8 + (lane & 3)*2;
            float v00 = acc[mi][nf][0], v01 = acc[mi][nf][1];
            float v10 = acc[mi][nf][2], v11 = acc[mi][nf][3];
            if (bias) {
                float b0 = bias[col], b1 = bias[col+1];
                v00 += b0; v01 += b1; v10 += b0; v11 += b1;
            }
            if (EPI == EPI_ADD || EPI == EPI_ADD2) {
                const float* ap0 = add + (size_t)row * N + col;
                const float* ap1 = add + (size_t)(row+8) * N + col;
                v00 += ap0[0]; v01 += ap0[1]; v10 += ap1[0]; v11 += ap1[1];
                if (EPI == EPI_ADD2) {
                    const float* bp0 = add2 + (size_t)row * N + col;
                    const float* bp1 = add2 + (size_t)(row+8) * N + col;
                    v00 += bp0[0]; v01 += bp0[1]; v10 += bp1[0]; v11 += bp1[1];
                }
            } else {
                v00 = epi_apply_scalar(EPI, v00); v01 = epi_apply_scalar(EPI, v01);
                v10 = epi_apply_scalar(EPI, v10); v11 = epi_apply_scalar(EPI, v11);
            }
            if (OBF) {
                __nv_bfloat16* C16 = (__nv_bfloat16*)Cv;
                *(unsigned*)&C16[(size_t)row * N + col]     = packbf2(v00, v01);
                *(unsigned*)&C16[(size_t)(row+8) * N + col] = packbf2(v10, v11);
            } else {
                float* C = (float*)Cv;
                *(float2*)&C[(size_t)row * N + col]     = make_float2(v00, v01);
                *(float2*)&C[(size_t)(row+8) * N + col] = make_float2(v10, v11);
            }
        }
    }
}

// ================= tf32 tensor-core GEMM (scan-sensitive projections) ========
template<int EPI>
__global__ __launch_bounds__(256) void gemm_tf32(
    const float* __restrict__ A, int lda,
    const float* __restrict__ W,
    const float* __restrict__ bias,
    float* __restrict__ C, int M, int N, int K)
{
    __shared__ __align__(16) unsigned As[2][128*32];
    __shared__ __align__(16) unsigned Bs[2][64*32];

    const int t = threadIdx.x;
    const int m0 = blockIdx.y * 128, n0 = blockIdx.x * 64;
    const int lane = t & 31, w = t >> 5;
    const int warpM = w & 3, warpN = w >> 2;
    const int s = lane >> 2, off = lane & 3;

    const float* aptr[4]; int aso[4];
#pragma unroll
    for (int i = 0; i < 4; i++) {
        int e = t + i*256;
        int m = e >> 3, g = e & 7;
        aptr[i] = A + (size_t)(m0 + m) * lda + g*4;
        aso[i]  = m*32 + ((g ^ (m & 7)) << 2);
    }
    const float* bptr[2]; int bso[2]; bool bval[2];
#pragma unroll
    for (int i = 0; i < 2; i++) {
        int e = t + i*256;
        int n = e >> 3, g = e & 7;
        bval[i] = (n0 + n) < N;
        bptr[i] = W + (size_t)(n0 + n) * K + g*4;
        bso[i]  = n*32 + ((g ^ (n & 7)) << 2);
    }

    float acc[2][4][4];
#pragma unroll
    for (int mi = 0; mi < 2; mi++)
#pragma unroll
        for (int ni = 0; ni < 4; ni++)
#pragma unroll
            for (int j = 0; j < 4; j++) acc[mi][ni][j] = 0.f;

    const int nk = K >> 5;
    float4 ar[4], br[2];

#pragma unroll
    for (int i = 0; i < 4; i++) ar[i] = *(const float4*)(aptr[i]);
#pragma unroll
    for (int i = 0; i < 2; i++)
        br[i] = bval[i] ? *(const float4*)(bptr[i]) : make_float4(0.f,0.f,0.f,0.f);
#pragma unroll
    for (int i = 0; i < 4; i++)
        *(uint4*)&As[0][aso[i]] = make_uint4(f2tf32(ar[i].x), f2tf32(ar[i].y), f2tf32(ar[i].z), f2tf32(ar[i].w));
#pragma unroll
    for (int i = 0; i < 2; i++)
        *(uint4*)&Bs[0][bso[i]] = make_uint4(f2tf32(br[i].x), f2tf32(br[i].y), f2tf32(br[i].z), f2tf32(br[i].w));
    __syncthreads();

    for (int kt = 0; kt < nk; kt++) {
        const int cur = kt & 1, nxt = cur ^ 1;
        const bool more = (kt + 1) < nk;
        if (more) {
            const int ko = (kt + 1) * 32;
#pragma unroll
            for (int i = 0; i < 4; i++) ar[i] = *(const float4*)(aptr[i] + ko);
#pragma unroll
            for (int i = 0; i < 2; i++)
                br[i] = bval[i] ? *(const float4*)(bptr[i] + ko) : make_float4(0.f,0.f,0.f,0.f);
        }

#pragma unroll
        for (int ks = 0; ks < 4; ks++) {
            const int x0 = (((ks*2)     ^ s) << 2) + off;
            const int x1 = (((ks*2 + 1) ^ s) << 2) + off;
            unsigned a[2][4];
#pragma unroll
            for (int mi = 0; mi < 2; mi++) {
                int r = (warpM*32 + mi*16 + s) * 32;
                a[mi][0] = As[cur][r + x0];
                a[mi][1] = As[cur][r + 256 + x0];
                a[mi][2] = As[cur][r + x1];
                a[mi][3] = As[cur][r + 256 + x1];
            }
            unsigned b[4][2];
#pragma unroll
            for (int ni = 0; ni < 4; ni++) {
                int rb = (warpN*32 + ni*8 + s) * 32;
                b[ni][0] = Bs[cur][rb + x0];
                b[ni][1] = Bs[cur][rb + x1];
            }
#pragma unroll
            for (int mi = 0; mi < 2; mi++)
#pragma unroll
                for (int ni = 0; ni < 4; ni++)
                    mma_tf32(acc[mi][ni], a[mi], b[ni]);
        }

        if (more) {
#pragma unroll
            for (int i = 0; i < 4; i++)
                *(uint4*)&As[nxt][aso[i]] = make_uint4(f2tf32(ar[i].x), f2tf32(ar[i].y), f2tf32(ar[i].z), f2tf32(ar[i].w));
#pragma unroll
            for (int i = 0; i < 2; i++)
                *(uint4*)&Bs[nxt][bso[i]] = make_uint4(f2tf32(br[i].x), f2tf32(br[i].y), f2tf32(br[i].z), f2tf32(br[i].w));
            __syncthreads();
        }
    }

#pragma unroll
    for (int mi = 0; mi < 2; mi++) {
#pragma unroll
        for (int ni = 0; ni < 4; ni++) {
            int row = m0 + warpM*32 + mi*16 + s;
            int col = n0 + warpN*32 + ni*8 + off*2;
            if (col < N) {
                float v00 = acc[mi][ni][0], v01 = acc[mi][ni][1];
                float v10 = acc[mi][ni][2], v11 = acc[mi][ni][3];
                if (bias) {
                    float b0 = bias[col], b1 = bias[col+1];
                    v00 += b0; v01 += b1; v10 += b0; v11 += b1;
                }
                v00 = epi_apply_scalar(EPI, v00); v01 = epi_apply_scalar(EPI, v01);
                v10 = epi_apply_scalar(EPI, v10); v11 = epi_apply_scalar(EPI, v11);
                *(float2*)&C[(size_t)row * N + col]     = make_float2(v00, v01);
                *(float2*)&C[(size_t)(row+8) * N + col] = make_float2(v10, v11);
            }
        }
    }
}

// ============== bf16 tensor-core flash attention (fused QKV input) ===========
__global__ __launch_bounds__(256, 2) void attn_bf(
    const __nv_bfloat16* __restrict__ qkv, const unsigned char* __restrict__ mask,
    __nv_bfloat16* __restrict__ o)
{
    extern __shared__ __align__(16) char smA[];
    char* sQ = smA;                  // 16384
    char* sK = smA + 16384;          // 8192
    char* sV = smA + 24576;          // 8192
    const int tid = threadIdx.x;
    const int lane = tid & 31, w = tid >> 5;
    char* sP = smA + 32768 + w*2048; // per-warp 2048
    const unsigned uQ = (unsigned)__cvta_generic_to_shared(sQ);
    const unsigned uK = (unsigned)__cvta_generic_to_shared(sK);
    const unsigned uV = (unsigned)__cvta_generic_to_shared(sV);
    const unsigned uP = (unsigned)__cvta_generic_to_shared(sP);

    const int qt = blockIdx.x, h = blockIdx.y, b = blockIdx.z;
    const size_t bL = (size_t)b * LL;
    const int qr = qt * 128;

    const int lr = (lane & 7) + ((lane >> 3) & 1) * 8;
    const int ko = lane >> 4;
    const int s = lane >> 2, off = lane & 3;

    const __nv_bfloat16* qp = qkv + h*Ee;
    const __nv_bfloat16* kp = qkv + Dd + h*Ee;
    const __nv_bfloat16* vp = qkv + 2*Dd + h*Ee;

#pragma unroll
    for (int i = 0; i < 4; i++) {
        int u = tid + i*256;
        int row = u >> 3, g = u & 7;
        uint4 val = *(const uint4*)&qp[(bL + qr + row) * QKVN + g*8];
        *(uint4*)(sQ + row*128 + ((g ^ (row & 7)) << 4)) = val;
    }
    __syncthreads();

    unsigned qa[4][4];
    {
        int r = w*16 + lr;
        unsigned base = uQ + r*128;
#pragma unroll
        for (int ks = 0; ks < 4; ks++)
            ldsm4(qa[ks], base + (((2*ks + ko) ^ (r & 7)) << 4));
    }

    float oa[8][4];
#pragma unroll
    for (int et = 0; et < 8; et++)
#pragma unroll
        for (int j = 0; j < 4; j++) oa[et][j] = 0.f;
    float m0v = -INFINITY, m1v = -INFINITY, l0v = 0.f, l1v = 0.f;

    for (int n0k = 0; n0k < LL; n0k += 64) {
        __syncthreads();
#pragma unroll
        for (int i = 0; i < 2; i++) {
            int u = tid + i*256;
            int row = u >> 3, g = u & 7;
            size_t gr = (bL + n0k + row) * QKVN + g*8;
            int so = row*128 + ((g ^ (row & 7)) << 4);
            *(uint4*)(sK + so) = *(const uint4*)&kp[gr];
            *(uint4*)(sV + so) = *(const uint4*)&vp[gr];
        }
        __syncthreads();

        float sa[8][4];
#pragma unroll
        for (int nt = 0; nt < 8; nt++)
#pragma unroll
            for (int j = 0; j < 4; j++) sa[nt][j] = 0.f;
#pragma unroll
        for (int ks = 0; ks < 4; ks++) {
#pragma unroll
            for (int nb = 0; nb < 4; nb++) {
                unsigned bfr[4];
                int r = nb*16 + lr;
                ldsm4(bfr, uK + r*128 + (((2*ks + ko) ^ (r & 7)) << 4));
                unsigned b0[2] = {bfr[0], bfr[2]};
                unsigned b1[2] = {bfr[1], bfr[3]};
                mma_bf16(sa[nb*2],     qa[ks], b0);
                mma_bf16(sa[nb*2 + 1], qa[ks], b1);
            }
        }

        float rmax0 = -INFINITY, rmax1 = -INFINITY;
#pragma unroll
        for (int nt = 0; nt < 8; nt++) {
            sa[nt][0] *= 0.125f; sa[nt][1] *= 0.125f;
            sa[nt][2] *= 0.125f; sa[nt][3] *= 0.125f;
            unsigned char mk0 = mask[bL + n0k + nt*8 + off*2];
            unsigned char mk1 = mask[bL + n0k + nt*8 + off*2 + 1];
            if (mk0) { sa[nt][0] = -INFINITY; sa[nt][2] = -INFINITY; }
            if (mk1) { sa[nt][1] = -INFINITY; sa[nt][3] = -INFINITY; }
            rmax0 = fmaxf(rmax0, fmaxf(sa[nt][0], sa[nt][1]));
            rmax1 = fmaxf(rmax1, fmaxf(sa[nt][2], sa[nt][3]));
        }
        rmax0 = fmaxf(rmax0, __shfl_xor_sync(0xffffffffu, rmax0, 1));
        rmax0 = fmaxf(rmax0, __shfl_xor_sync(0xffffffffu, rmax0, 2));
        rmax1 = fmaxf(rmax1, __shfl_xor_sync(0xffffffffu, rmax1, 1));
        rmax1 = fmaxf(rmax1, __shfl_xor_sync(0xffffffffu, rmax1, 2));
        float mn0 = fmaxf(m0v, rmax0), mn1 = fmaxf(m1v, rmax1);
        float c0 = __expf(m0v - mn0), c1 = __expf(m1v - mn1);
        float rs0 = 0.f, rs1 = 0.f;
#pragma unroll
        for (int nt = 0; nt < 8; nt++) {
            float p0 = __expf(sa[nt][0] - mn0);
            float p1 = __expf(sa[nt][1] - mn0);
            float p2 = __expf(sa[nt][2] - mn1);
            float p3 = __expf(sa[nt][3] - mn1);
            rs0 += p0 + p1; rs1 += p2 + p3;
            *(unsigned*)(sP + s*128       + ((nt ^ (s & 7)) << 4) + off*4) = packbf2(p0, p1);
            *(unsigned*)(sP + (s+8)*128   + ((nt ^ (s & 7)) << 4) + off*4) = packbf2(p2, p3);
        }
        rs0 += __shfl_xor_sync(0xffffffffu, rs0, 1);
        rs0 += __shfl_xor_sync(0xffffffffu, rs0, 2);
        rs1 += __shfl_xor_sync(0xffffffffu, rs1, 1);
        rs1 += __shfl_xor_sync(0xffffffffu, rs1, 2);
        l0v = l0v * c0 + rs0; l1v = l1v * c1 + rs1;
        m0v = mn0; m1v = mn1;
#pragma unroll
        for (int et = 0; et < 8; et++) {
            oa[et][0] *= c0; oa[et][1] *= c0;
            oa[et][2] *= c1; oa[et][3] *= c1;
        }
        __syncwarp();

#pragma unroll
        for (int ksp = 0; ksp < 4; ksp++) {
            unsigned pa[4];
            {
                int r = lr;
                ldsm4(pa, uP + r*128 + (((2*ksp + ko) ^ (r & 7)) << 4));
            }
            int key = ksp*16 + lr;
#pragma unroll
            for (int j = 0; j < 4; j++) {
                unsigned vfr[4];
                ldsm4t(vfr, uV + key*128 + (((2*j + ko) ^ (key & 7)) << 4));
                unsigned be0[2] = {vfr[0], vfr[1]};
                unsigned be1[2] = {vfr[2], vfr[3]};
                mma_bf16(oa[j*2],     pa, be0);
                mma_bf16(oa[j*2 + 1], pa, be1);
            }
        }
    }

    float inv0 = 1.f / l0v, inv1 = 1.f / l1v;
#pragma unroll
    for (int et = 0; et < 8; et++) {
        size_t r0 = (bL + qr + w*16 + s    ) * Dd + h*Ee + et*8 + off*2;
        size_t r1 = (bL + qr + w*16 + s + 8) * Dd + h*Ee + et*8 + off*2;
        *(unsigned*)&o[r0] = packbf2(oa[et][0]*inv0, oa[et][1]*inv0);
        *(unsigned*)&o[r1] = packbf2(oa[et][2]*inv1, oa[et][3]*inv1);
    }
}

// ---------------- causal depthwise conv (KC=4) + SiLU ------------------------
__global__ void conv_silu_k(const float* __restrict__ xz,
                            const float* __restrict__ cw,
                            const float* __restrict__ cb,
                            float* __restrict__ uact)
{
    int idx = blockIdx.x * 256 + threadIdx.x;
    int r = idx >> 10;
    int j = idx & 1023;
    int t = r % LL;
    float acc = cb[j];
#pragma unroll
    for (int kk = 0; kk < 4; kk++) {
        int tt = t + kk - 3;
        if (tt >= 0)
            acc = fmaf(xz[(size_t)(r + kk - 3) * (2*DI) + j], cw[j*4 + kk], acc);
    }
    uact[idx] = acc / (1.f + expf(-acc));
}

// -------- selective scan + fused gate, 3-stage cp.async staging --------------
// dyn smem layout (floats): stg[3] x {B 1024 | C 1024 | dt 256 | u 256 | z 256}
// then spw[16][16][33]. Total 16896 floats = 67584 B.
#define STG_F 2816
__global__ __launch_bounds__(512) void scan_gate_k(
    const float* __restrict__ delta, const float* __restrict__ uact,
    const float* __restrict__ xdbc, const float* __restrict__ A_log,
    const float* __restrict__ xz,   const float* __restrict__ Dssm,
    __nv_bfloat16* __restrict__ y)
{
    extern __shared__ __align__(16) float smS[];
    float* spw = smS + 3*STG_F;   // [16][16][33]
    const unsigned stgU = (unsigned)__cvta_generic_to_shared(smS);

    int b = blockIdx.y;
    int d0 = blockIdx.x * 16;
    int tid = threadIdx.x;
    int w = tid >> 5, l = tid & 31;
    int d = d0 + w;
    float a0 = -expf(A_log[d*Ss + l]);
    float a1 = -expf(A_log[d*Ss + l + 32]);
    float dD = Dssm[d];
    float h0 = 0.f, h1 = 0.f;
    size_t base = (size_t)b * LL;

    const int rr = l >> 1;
    const int half = l & 1;

    // staging maps (per thread): one 16B B/C transfer, plus dt/u/z for tid<192
    const int btt = tid >> 5, bc = (tid & 31) * 4;           // B/C: tt, col
    const unsigned bcDst = stgU + ((btt*128 + bc) << 2);     // B at +0, C at +4096B handled by col
    const int s3 = tid >> 6, e3 = (tid & 63) * 4;            // dt/u/z sel, elem
    const int stt = e3 >> 4, sc = e3 & 15;
    const unsigned sDst = stgU + ((2048 + s3*256 + stt*16 + sc) << 2);

    const int nt = LL / 16;   // 72

    // prologue: stage tile 0 into stage buffer 0
    {
        cpa16(bcDst, &xdbc[(base + btt) * 160 + 32 + bc]);
        if (tid < 192) {
            const float* src = (s3 == 0) ? &delta[(base + stt) * DI + d0 + sc]
                             : (s3 == 1) ? &uact [(base + stt) * DI + d0 + sc]
                                         : &xz[(base + stt) * (2*DI) + DI + d0 + sc];
            cpa16(sDst, src);
        }
        cpa_commit();
    }

    for (int t = 0; t < nt; t++) {
        const int cur = t % 3;
        if (t + 1 < nt) {
            const int nxt = (t + 1) % 3;
            const int t0n = (t + 1) * 16;
            cpa16(bcDst + nxt*STG_F*4, &xdbc[(base + t0n + btt) * 160 + 32 + bc]);
            if (tid < 192) {
                const float* src = (s3 == 0) ? &delta[(base + t0n + stt) * DI + d0 + sc]
                                 : (s3 == 1) ? &uact [(base + t0n + stt) * DI + d0 + sc]
                                             : &xz[(base + t0n + stt) * (2*DI) + DI + d0 + sc];
                cpa16(sDst + nxt*STG_F*4, src);
            }
            cpa_commit();
            cpa_wait<1>();
        } else {
            cpa_wait<0>();
        }
        __syncthreads();

        const float* sBC = smS + cur*STG_F;        // [16][128]: B cols 0-63, C cols 64-127
        const float* sdt = smS + cur*STG_F + 2048; // [16][16]
        const float* su  = sdt + 256;
        const float* sz  = su + 256;
        const int t0 = t * 16;

#pragma unroll 4
        for (int tt = 0; tt < 16; tt++) {
            float dt  = sdt[tt*16 + w];
            float dtu = dt * su[tt*16 + w];
            float dA0 = __expf(dt * a0);
            float dA1 = __expf(dt * a1);
            h0 = fmaf(h0, dA0, dtu * sBC[tt*128 + l]);
            h1 = fmaf(h1, dA1, dtu * sBC[tt*128 + l + 32]);
            spw[(w*16 + tt)*33 + l] = fmaf(h1, sBC[tt*128 + 64 + l + 32], h0 * sBC[tt*128 + 64 + l]);
        }
        __syncwarp();

        float accv = 0.f;
#pragma unroll
        for (int i = 0; i < 16; i++) accv += spw[(w*16 + rr)*33 + half*16 + i];
        accv += __shfl_xor_sync(0xffffffffu, accv, 1);
        if (half == 0) {
            float uu = su[rr*16 + w];
            float zz = sz[rr*16 + w];
            float yv = fmaf(uu, dD, accv);
            y[(base + t0 + rr) * DI + d] = __float2bfloat16(yv * (zz / (1.f + __expf(-zz))));
        }
    }
}

// ---------------- double LayerNorm on pre-summed residual --------------------
__device__ __forceinline__ float blockSum128(float v, float* sm)
{
#pragma unroll
    for (int offx = 16; offx > 0; offx >>= 1)
        v += __shfl_xor_sync(0xffffffffu, v, offx);
    if ((threadIdx.x & 31) == 0) sm[threadIdx.x >> 5] = v;
    __syncthreads();
    float r = sm[0] + sm[1] + sm[2] + sm[3];
    __syncthreads();
    return r;
}

__global__ __launch_bounds__(128) void ln2_k(
    const float* __restrict__ hsum,
    const float* __restrict__ g1, const float* __restrict__ b1,
    const float* __restrict__ g2, const float* __restrict__ b2,
    float* __restrict__ h, __nv_bfloat16* __restrict__ hn)
{
    __shared__ float sm[4];
    int r = blockIdx.x, tid = threadIdx.x;
    size_t base = (size_t)r * Dd;
    float vv[4];
#pragma unroll
    for (int i = 0; i < 4; i++) vv[i] = hsum[base + tid + i*128];
    float s = vv[0] + vv[1] + vv[2] + vv[3];
    float mean = blockSum128(s, sm) * (1.f/512.f);
    float sq = 0.f;
#pragma unroll
    for (int i = 0; i < 4; i++) { float dd = vv[i] - mean; sq = fmaf(dd, dd, sq); }
    float var = blockSum128(sq, sm) * (1.f/512.f);
    float inv = rsqrtf(var + 1e-5f);
    float hv[4];
#pragma unroll
    for (int i = 0; i < 4; i++) {
        int c = tid + i*128;
        hv[i] = (vv[i] - mean) * inv * g1[c] + b1[c];
        h[base+c] = hv[i];
    }
    float s2 = hv[0] + hv[1] + hv[2] + hv[3];
    float mean2 = blockSum128(s2, sm) * (1.f/512.f);
    float sq2 = 0.f;
#pragma unroll
    for (int i = 0; i < 4; i++) { float dd = hv[i] - mean2; sq2 = fmaf(dd, dd, sq2); }
    float var2 = blockSum128(sq2, sm) * (1.f/512.f);
    float inv2 = rsqrtf(var2 + 1e-6f);
#pragma unroll
    for (int i = 0; i < 4; i++) {
        int c = tid + i*128;
        hn[base+c] = __float2bfloat16((hv[i] - mean2) * inv2 * g2[c] + b2[c]);
    }
}

// ---------------- launch -----------------------------------------------------
extern "C" void kernel_launch(void* const* d_in, const int* in_sizes, int n_in,
                              void* d_out, int out_size)
{
    const float* x            = (const float*)d_in[0];
    const unsigned char* mask = (const unsigned char*)d_in[1];
    const float* Wq = (const float*)d_in[2];   const float* bq = (const float*)d_in[3];
    const float* Wk = (const float*)d_in[4];   const float* bk = (const float*)d_in[5];
    const float* Wv = (const float*)d_in[6];   const float* bv = (const float*)d_in[7];
    const float* Wo = (const float*)d_in[8];   const float* bo = (const float*)d_in[9];
    const float* in_proj_w = (const float*)d_in[10];
    const float* conv_w    = (const float*)d_in[11];
    const float* conv_b    = (const float*)d_in[12];
    const float* x_proj_w  = (const float*)d_in[13];
    const float* dt_proj_w = (const float*)d_in[14];
    const float* dt_proj_b = (const float*)d_in[15];
    const float* A_log     = (const float*)d_in[16];
    const float* D_ssm     = (const float*)d_in[17];
    const float* out_proj_w= (const float*)d_in[18];
    const float* ln1_g = (const float*)d_in[19]; const float* ln1_b = (const float*)d_in[20];
    const float* ffn_w1= (const float*)d_in[21]; const float* ffn_b1= (const float*)d_in[22];
    const float* ffn_w2= (const float*)d_in[23]; const float* ffn_b2= (const float*)d_in[24];
    const float* ln2_g = (const float*)d_in[25]; const float* ln2_b = (const float*)d_in[26];
    float* out = (float*)d_out;

    __nv_bfloat16 *xbf,*wqkvb,*wob,*winb,*woutb,*wf1b,*wf2b;
    float *bqkv;
    __nv_bfloat16 *qkv, *attnO, *y, *hn, *mid;
    float *attn_out,*xz,*uact,*xdbc,*delta,*hsum,*h;
    cudaGetSymbolAddress((void**)&xbf,   g_xbf);
    cudaGetSymbolAddress((void**)&wqkvb, g_wqkv);
    cudaGetSymbolAddress((void**)&bqkv,  g_bqkv);
    cudaGetSymbolAddress((void**)&wob,   g_wo);
    cudaGetSymbolAddress((void**)&winb,  g_win);
    cudaGetSymbolAddress((void**)&woutb, g_wout);
    cudaGetSymbolAddress((void**)&wf1b,  g_wf1);
    cudaGetSymbolAddress((void**)&wf2b,  g_wf2);
    cudaGetSymbolAddress((void**)&qkv,      g_qkv);
    cudaGetSymbolAddress((void**)&attnO,    g_attnO);
    cudaGetSymbolAddress((void**)&attn_out, g_attn_out);
    cudaGetSymbolAddress((void**)&xz,       g_xz);
    cudaGetSymbolAddress((void**)&uact,     g_uact);
    cudaGetSymbolAddress((void**)&xdbc,     g_xdbc);
    cudaGetSymbolAddress((void**)&delta,    g_delta);
    cudaGetSymbolAddress((void**)&y,        g_y);
    cudaGetSymbolAddress((void**)&hsum,     g_hsum);
    cudaGetSymbolAddress((void**)&h,        g_h);
    cudaGetSymbolAddress((void**)&hn,       g_hn);
    cudaGetSymbolAddress((void**)&mid,      g_mid);

    static cudaStream_t s_attn = nullptr;
    static cudaEvent_t  e_fork = nullptr, e_join = nullptr;
    if (s_attn == nullptr) {
        cudaStreamCreateWithFlags(&s_attn, cudaStreamNonBlocking);
        cudaEventCreateWithFlags(&e_fork, cudaEventDisableTiming);
        cudaEventCreateWithFlags(&e_join, cudaEventDisableTiming);
    }

    const int MY = Mrows / 128;   // 72
    const int attn_smem = 32768 + 8*2048;   // 49152 bytes
    const int scan_smem = (3*STG_F + 16*16*33) * 4;   // 67584 bytes
    cudaFuncSetAttribute(attn_bf, cudaFuncAttributeMaxDynamicSharedMemorySize, attn_smem);
    cudaFuncSetAttribute(scan_gate_k, cudaFuncAttributeMaxDynamicSharedMemorySize, scan_smem);

    #define CVT(src, dst, n) cvt_bf_k<<<((n)/4 + 255)/256, 256, 0, 0>>>(src, dst, n)
    #define CVT_S(src, dst, n) cvt_bf_k<<<((n)/4 + 255)/256, 256, 0, s_attn>>>(src, dst, n)

    // ---- x -> bf16 (needed by both branches), then fork ----
    CVT(x, xbf, Mrows*Dd);
    cudaEventRecord(e_fork, 0);
    cudaStreamWaitEvent(s_attn, e_fork, 0);

    // attention branch (s_attn)
    CVT_S(Wq, wqkvb,            Dd*Dd);
    CVT_S(Wk, wqkvb + Dd*Dd,    Dd*Dd);
    CVT_S(Wv, wqkvb + 2*Dd*Dd,  Dd*Dd);
    CVT_S(Wo, wob, Dd*Dd);
    concat_bias_k<<<(QKVN + 255)/256, 256, 0, s_attn>>>(bq, bk, bv, bqkv);
    gemm_bb<EPI_NONE,1><<<dim3(QKVN/64, MY), 256, 0, s_attn>>>(xbf, Dd, wqkvb, bqkv, nullptr, nullptr, qkv, Mrows, QKVN, Dd);
    attn_bf<<<dim3(LL/128, Hh, Bsz), 256, attn_smem, s_attn>>>(qkv, mask, attnO);
    gemm_bb<EPI_NONE,0><<<dim3(Dd/64,   MY), 256, 0, s_attn>>>(attnO, Dd, wob, bo, nullptr, nullptr, attn_out, Mrows, Dd, Dd);
    cudaEventRecord(e_join, s_attn);

    // mamba branch (stream 0)
    CVT(in_proj_w, winb, 2*DI*Dd);
    CVT(out_proj_w, woutb, Dd*DI);
    CVT(ffn_w1, wf1b, DFF*Dd);
    CVT(ffn_w2, wf2b, Dd*DFF);
    gemm_bb<EPI_NONE,0><<<dim3(2*DI/64, MY), 256>>>(xbf, Dd, winb, nullptr, nullptr, nullptr, xz, Mrows, 2*DI, Dd);
    conv_silu_k<<<Mrows*DI/256, 256>>>(xz, conv_w, conv_b, uact);
    gemm_tf32<EPI_NONE><<<dim3(3,       MY), 256>>>(uact, DI, x_proj_w, nullptr, xdbc, Mrows, 160, DI);
    gemm_tf32<EPI_SOFTPLUS><<<dim3(DI/64, MY), 256>>>(xdbc, 160, dt_proj_w, dt_proj_b, delta, Mrows, DI, Rr);
    scan_gate_k<<<dim3(DI/16, Bsz), 512, scan_smem>>>(delta, uact, xdbc, A_log, xz, D_ssm, y);

    // ---- join, then out_proj with fused residual adds ----
    cudaStreamWaitEvent(0, e_join, 0);
    gemm_bb<EPI_ADD2,0><<<dim3(Dd/64,   MY), 256>>>(y, DI, woutb, nullptr, x, attn_out, hsum, Mrows, Dd, DI);

    // double layernorm
    ln2_k<<<Mrows, 128>>>(hsum, ln1_g, ln1_b, ln2_g, ln2_b, h, hn);

    // FFN
    gemm_bb<EPI_GELU,1><<<dim3(DFF/64, MY), 256>>>(hn, Dd, wf1b, ffn_b1, nullptr, nullptr, mid, Mrows, DFF, Dd);
    gemm_bb<EPI_ADD,0><<<dim3(Dd/64,   MY), 256>>>(mid, DFF, wf2b, ffn_b2, h, nullptr, out, Mrows, Dd, DFF);

    #undef CVT
    #undef CVT_S
}